// round 10
// baseline (speedup 1.0000x reference)
#include <cuda_runtime.h>
#include <cuda_bf16.h>
#include <math.h>
#include <stdint.h>

// Problem constants
#define BB   2
#define LS   2048
#define DM   1024
#define DIN  2048
#define DST  16
#define RDT  64
#define ML   (BB*LS)      // 4096 rows
#define DFF  (4*DM)       // 4096

// ---------------- scratch (device globals) -----------------------------------
// xz unified: [ML][8192], cols [dir*4096 .. +2047]=xi, [+2048..+4095]=z
__device__ __align__(256) float g_xz  [(size_t)ML * 8192];
__device__ __align__(256) float g_xc  [2u * ML * DIN];
__device__ __align__(256) float g_xdbl[2u * ML * 96];     // cols 64..95: B/C interleaved
__device__ __align__(256) float g_dtu [2u * (size_t)ML * DIN * 2];  // (dt, u) pairs
__device__ __align__(256) float g_y   [2u * ML * DIN];    // scan out (tf32-rounded)
__device__ __align__(256) float g_ydir[2u * ML * DM];
__device__ __align__(256) float g_xsum[(size_t)ML * DM];
__device__ __align__(256) float g_ln  [(size_t)ML * DM];  // tf32-rounded
__device__ __align__(256) float g_f1  [(size_t)ML * DFF]; // tf32-rounded
__device__ __align__(256) float g_xcv [(size_t)ML * DM];  // x tf32-rounded
__device__ __align__(256) float g_inwcv [2u * 2 * DIN * DM];
__device__ __align__(256) float g_outwcv[2u * DM * DIN];
__device__ __align__(256) float g_w1cv[(size_t)DFF * DM];
__device__ __align__(256) float g_w2cv[(size_t)DM * DFF];

// ---------------- helpers ------------------------------------------------------
__device__ __forceinline__ float siluf(float v) { return v / (1.f + __expf(-v)); }
__device__ __forceinline__ float softplusf(float v) {
    return (v > 20.f) ? v : log1pf(__expf(v));
}
__device__ __forceinline__ float rna_tf32(float f) {
    uint32_t u;
    asm("cvt.rna.tf32.f32 %0, %1;" : "=r"(u) : "f"(f));
    return __uint_as_float(u);
}

#define MMAT32(d, a, b0, b1) \
    asm volatile("mma.sync.aligned.m16n8k8.row.col.f32.tf32.tf32.f32 " \
        "{%0,%1,%2,%3}, {%4,%5,%6,%7}, {%8,%9}, {%0,%1,%2,%3};" \
        : "+f"((d)[0]), "+f"((d)[1]), "+f"((d)[2]), "+f"((d)[3]) \
        : "r"((a)[0]), "r"((a)[1]), "r"((a)[2]), "r"((a)[3]), "r"(b0), "r"(b1))

#define CPA16(sa, ga) \
    asm volatile("cp.async.cg.shared.global [%0], [%1], 16;" :: "r"(sa), "l"(ga))
#define CPA_COMMIT() asm volatile("cp.async.commit_group;" ::: "memory")
#define CPA_WAIT1()  asm volatile("cp.async.wait_group 1;" ::: "memory")

// ---------------- tf32 tensor-core GEMM: C[M,N] = A[M,K] * B[N,K]^T ------------
// Inputs pre-rounded to tf32 (RNA). 128x128 tiles, KC=32 floats, 3-stage cp.async.
// 8 warps (2Mx4N), warp tile 64x32, mma m16n8k8.
#define KCF     32
#define ROWF    36                      // padded row length in floats (144B)
#define ARR_F   (128 * ROWF * 4)        // 18432 B
#define STAGE_F (2 * ARR_F)             // 36864 B (A + B)
#define NSTG    3
#define DSMEM3  (NSTG * STAGE_F)        // 110592 B

__global__ __launch_bounds__(256, 2)
void t32_gemm(const float* __restrict__ A, int lda,
              const float* __restrict__ Bw, int ldb,
              const float* __restrict__ bias,
              const float* __restrict__ addsrc,
              float* __restrict__ Cf,
              int ldc, int K, int act, int rndC,
              size_t zsA, size_t zsB, size_t zsC)
{
    extern __shared__ char sm[];
    const int tid  = threadIdx.x;
    const int lane = tid & 31;
    const int wid  = tid >> 5;
    const int wm   = wid >> 2;          // 0..1
    const int wn   = wid & 3;           // 0..3
    const int rowBase = blockIdx.y * 128;
    const int colBase = blockIdx.x * 128;
    const size_t zA = (size_t)blockIdx.z * zsA;
    const size_t zB = (size_t)blockIdx.z * zsB;
    const size_t zC = (size_t)blockIdx.z * zsC;
    const uint32_t smb = (uint32_t)__cvta_generic_to_shared(sm);

    // loader: thread t -> one combined row (A: 0..127, B: 128..255), 8 x 16B chunks
    const int isB  = tid >> 7;              // 0:A 1:B
    const int lrow = tid & 127;
    const size_t gRow = isB ? (zB + (size_t)(colBase + lrow) * ldb)
                            : (zA + (size_t)(rowBase + lrow) * lda);
    const float* gBase = isB ? Bw : A;
    const uint32_t sRow = (uint32_t)(isB ? ARR_F : 0) + (uint32_t)lrow * (ROWF * 4);

    // fragment addressing
    const int gid  = lane >> 2;             // 0..7
    const int ctid = lane & 3;              // 0..3
    uint32_t aOff[4], bOff[4];
    #pragma unroll
    for (int i = 0; i < 4; i++)
        aOff[i] = (uint32_t)((wm * 64 + i * 16 + gid) * ROWF + ctid) * 4;
    #pragma unroll
    for (int j = 0; j < 4; j++)
        bOff[j] = (uint32_t)ARR_F + (uint32_t)((wn * 32 + j * 8 + gid) * ROWF + ctid) * 4;

    float acc[16][4];
    #pragma unroll
    for (int i = 0; i < 16; i++)
        #pragma unroll
        for (int j = 0; j < 4; j++) acc[i][j] = 0.f;

    const int nk = K / KCF;

    auto issue = [&](int stg, int kt) {
        const uint32_t sb = smb + (uint32_t)stg * STAGE_F + sRow;
        const float* gp = gBase + gRow + (size_t)kt * KCF;
        #pragma unroll
        for (int c = 0; c < 8; c++)
            CPA16(sb + (uint32_t)c * 16, gp + c * 4);
    };

    issue(0, 0); CPA_COMMIT();
    issue(1, 1); CPA_COMMIT();

    int stg = 0;
    for (int kt = 0; kt < nk; kt++) {
        CPA_WAIT1();
        __syncthreads();
        if (kt + 2 < nk) issue((stg + 2) % NSTG, kt + 2);
        CPA_COMMIT();

        const uint32_t base = smb + (uint32_t)stg * STAGE_F;
        #pragma unroll
        for (int ks = 0; ks < 4; ks++) {
            const uint32_t kadd = (uint32_t)ks * 32;   // 8 floats
            uint32_t aF[4][4], bF[4][2];
            #pragma unroll
            for (int i = 0; i < 4; i++) {
                const uint32_t a0 = base + aOff[i] + kadd;
                aF[i][0] = *(const uint32_t*)(sm + (a0 - smb));
                aF[i][1] = *(const uint32_t*)(sm + (a0 - smb) + 8 * ROWF * 4);
                aF[i][2] = *(const uint32_t*)(sm + (a0 - smb) + 16);
                aF[i][3] = *(const uint32_t*)(sm + (a0 - smb) + 8 * ROWF * 4 + 16);
            }
            #pragma unroll
            for (int j = 0; j < 4; j++) {
                const uint32_t b0 = base + bOff[j] + kadd;
                bF[j][0] = *(const uint32_t*)(sm + (b0 - smb));
                bF[j][1] = *(const uint32_t*)(sm + (b0 - smb) + 16);
            }
            #pragma unroll
            for (int i = 0; i < 4; i++)
                #pragma unroll
                for (int j = 0; j < 4; j++)
                    MMAT32(acc[i*4+j], aF[i], bF[j][0], bF[j][1]);
        }
        stg = (stg + 1) % NSTG;
    }

    // epilogue (C layout identical to m16n8k16)
    const int erow  = wm * 64 + (lane >> 2);
    const int ecol0 = wn * 32 + (lane & 3) * 2;
    #pragma unroll
    for (int i = 0; i < 4; i++) {
        int r0 = rowBase + erow + i * 16;
        int r1 = r0 + 8;
        #pragma unroll
        for (int nt = 0; nt < 4; nt++) {
            int c = colBase + ecol0 + nt * 8;
            float v0 = acc[i*4+nt][0], v1 = acc[i*4+nt][1];
            float v2 = acc[i*4+nt][2], v3 = acc[i*4+nt][3];
            if (bias) {
                float b0 = __ldg(&bias[c]), b1 = __ldg(&bias[c+1]);
                v0 += b0; v1 += b1; v2 += b0; v3 += b1;
            }
            if (act == 1) { v0 = siluf(v0); v1 = siluf(v1); v2 = siluf(v2); v3 = siluf(v3); }
            else if (act == 2) { v0 = softplusf(v0); v1 = softplusf(v1); v2 = softplusf(v2); v3 = softplusf(v3); }
            if (addsrc) {
                v0 += addsrc[(size_t)r0 * ldc + c];
                v1 += addsrc[(size_t)r0 * ldc + c + 1];
                v2 += addsrc[(size_t)r1 * ldc + c];
                v3 += addsrc[(size_t)r1 * ldc + c + 1];
            }
            if (rndC) {
                v0 = rna_tf32(v0); v1 = rna_tf32(v1);
                v2 = rna_tf32(v2); v3 = rna_tf32(v3);
            }
            *(float2*)&Cf[zC + (size_t)r0 * ldc + c] = make_float2(v0, v1);
            *(float2*)&Cf[zC + (size_t)r1 * ldc + c] = make_float2(v2, v3);
        }
    }
}

// ---------------- fp32 -> tf32(RNA) fp32 convert ---------------------------------
__global__ void cvt_kernel(const float* __restrict__ in,
                           float* __restrict__ out, int n4)
{
    int i = blockIdx.x * blockDim.x + threadIdx.x;
    if (i >= n4) return;
    float4 v = ((const float4*)in)[i];
    v.x = rna_tf32(v.x); v.y = rna_tf32(v.y);
    v.z = rna_tf32(v.z); v.w = rna_tf32(v.w);
    ((float4*)out)[i] = v;
}

// ---------------- xdbl GEMM: [2][ML][96], B/C interleaved in cols 64..95 --------
__global__ __launch_bounds__(128)
void xdbl_gemm(const float* __restrict__ xcA,
               const float* __restrict__ xw0,
               const float* __restrict__ xw1,
               float* __restrict__ out)
{
    __shared__ float As[16][36];
    __shared__ float Bs[16][100];
    const int dir = blockIdx.z;
    const float* A = xcA + (size_t)dir * ML * DIN + (size_t)blockIdx.x * 32 * DIN;
    const float* B = dir ? xw1 : xw0;
    float* C = out + (size_t)dir * ML * 96 + (size_t)blockIdx.x * 32 * 96;

    const int tid = threadIdx.x;
    const int tx = tid & 15, ty = tid >> 4;
    float acc[4][6];
    #pragma unroll
    for (int i = 0; i < 4; i++)
        #pragma unroll
        for (int j = 0; j < 6; j++) acc[i][j] = 0.f;

    const int ar = tid >> 2, akc = (tid & 3) * 4;

    for (int k0 = 0; k0 < DIN; k0 += 16) {
        {
            float4 v = *(const float4*)(A + (size_t)ar * DIN + k0 + akc);
            As[akc+0][ar] = v.x; As[akc+1][ar] = v.y;
            As[akc+2][ar] = v.z; As[akc+3][ar] = v.w;
        }
        #pragma unroll
        for (int j = 0; j < 3; j++) {
            int i = tid + j * 128;
            int n = i >> 2, kc = (i & 3) * 4;
            float4 v = *(const float4*)(B + (size_t)n * DIN + k0 + kc);
            Bs[kc+0][n] = v.x; Bs[kc+1][n] = v.y;
            Bs[kc+2][n] = v.z; Bs[kc+3][n] = v.w;
        }
        __syncthreads();
        #pragma unroll
        for (int kk = 0; kk < 16; kk++) {
            float4 a4 = *(const float4*)&As[kk][ty*4];
            float ar4[4] = {a4.x, a4.y, a4.z, a4.w};
            float2 b0 = *(const float2*)&Bs[kk][tx*6];
            float2 b1 = *(const float2*)&Bs[kk][tx*6+2];
            float2 b2 = *(const float2*)&Bs[kk][tx*6+4];
            float br[6] = {b0.x, b0.y, b1.x, b1.y, b2.x, b2.y};
            #pragma unroll
            for (int i = 0; i < 4; i++)
                #pragma unroll
                for (int j = 0; j < 6; j++)
                    acc[i][j] = fmaf(ar4[i], br[j], acc[i][j]);
        }
        __syncthreads();
    }
    #pragma unroll
    for (int i = 0; i < 4; i++)
        #pragma unroll
        for (int j = 0; j < 6; j++) {
            int c = tx*6 + j;
            int cw = (c < 64) ? c : ((c < 80) ? (64 + 2*(c - 64)) : (65 + 2*(c - 80)));
            C[(size_t)(ty*4+i) * 96 + cw] = acc[i][j];
        }
}

// ---------------- dt GEMM -> (dt, u) float2 pairs --------------------------------
__global__ __launch_bounds__(256)
void dt_gemm(const float* __restrict__ xdblA,
             const float* __restrict__ xcA,
             const float* __restrict__ w0, const float* __restrict__ w1,
             const float* __restrict__ b0, const float* __restrict__ b1,
             float* __restrict__ out)          // [2][ML][DIN][2]
{
    __shared__ float As[16][132];
    __shared__ float Bs[16][132];

    const int dir = blockIdx.z;
    const float* A = xdblA + (size_t)dir * ML * 96;
    const float* xcD = xcA + (size_t)dir * ML * DIN;
    const float* Bw = dir ? w1 : w0;
    const float* bias = dir ? b1 : b0;
    float* C = out + (size_t)dir * ML * DIN * 2;

    const int tid = threadIdx.x;
    const int tx = tid & 15;
    const int ty = tid >> 4;
    const int rowBase = blockIdx.y * 128;
    const int colBase = blockIdx.x * 128;

    const int lm = tid >> 1;
    const int lk = (tid & 1) * 8;

    const float* aPtr = A + (size_t)(rowBase + lm) * 96 + lk;
    const float* bPtr = Bw + (size_t)(colBase + lm) * RDT + lk;

    float acc[8][8];
    #pragma unroll
    for (int i = 0; i < 8; i++)
        #pragma unroll
        for (int j = 0; j < 8; j++) acc[i][j] = 0.f;

    for (int k0 = 0; k0 < RDT; k0 += 16) {
        float4 a0 = *(const float4*)(aPtr + k0);
        float4 a1 = *(const float4*)(aPtr + k0 + 4);
        float4 b0v = *(const float4*)(bPtr + k0);
        float4 b1v = *(const float4*)(bPtr + k0 + 4);

        As[lk+0][lm] = a0.x; As[lk+1][lm] = a0.y; As[lk+2][lm] = a0.z; As[lk+3][lm] = a0.w;
        As[lk+4][lm] = a1.x; As[lk+5][lm] = a1.y; As[lk+6][lm] = a1.z; As[lk+7][lm] = a1.w;
        Bs[lk+0][lm] = b0v.x; Bs[lk+1][lm] = b0v.y; Bs[lk+2][lm] = b0v.z; Bs[lk+3][lm] = b0v.w;
        Bs[lk+4][lm] = b1v.x; Bs[lk+5][lm] = b1v.y; Bs[lk+6][lm] = b1v.z; Bs[lk+7][lm] = b1v.w;
        __syncthreads();

        #pragma unroll
        for (int kk = 0; kk < 16; kk++) {
            float4 ra0 = *(const float4*)&As[kk][ty * 4];
            float4 ra1 = *(const float4*)&As[kk][64 + ty * 4];
            float4 rb0 = *(const float4*)&Bs[kk][tx * 4];
            float4 rb1 = *(const float4*)&Bs[kk][64 + tx * 4];
            float ar[8] = {ra0.x, ra0.y, ra0.z, ra0.w, ra1.x, ra1.y, ra1.z, ra1.w};
            float br[8] = {rb0.x, rb0.y, rb0.z, rb0.w, rb1.x, rb1.y, rb1.z, rb1.w};
            #pragma unroll
            for (int i = 0; i < 8; i++)
                #pragma unroll
                for (int j = 0; j < 8; j++)
                    acc[i][j] = fmaf(ar[i], br[j], acc[i][j]);
        }
        __syncthreads();
    }

    #pragma unroll
    for (int i = 0; i < 8; i++) {
        int r = rowBase + ((i < 4) ? (ty * 4 + i) : (64 + ty * 4 + i - 4));
        #pragma unroll
        for (int j = 0; j < 8; j++) {
            int c = colBase + ((j < 4) ? (tx * 4 + j) : (64 + tx * 4 + j - 4));
            float dtv = softplusf(acc[i][j] + bias[c]);
            float uv  = xcD[(size_t)r * DIN + c];
            *(float2*)&C[((size_t)r * DIN + c) * 2] = make_float2(dtv, uv);
        }
    }
}

// ---------------- depthwise causal conv (k=4, dir-dependent taps) ---------------
__global__ void conv_kernel(const float* __restrict__ xz,
                            const float* __restrict__ cw0, const float* __restrict__ cw1,
                            const float* __restrict__ cb0, const float* __restrict__ cb1,
                            float* __restrict__ xc)
{
    int idx = blockIdx.x * blockDim.x + threadIdx.x;
    if (idx >= 2 * ML * DIN) return;
    int dir = idx >= ML * DIN;
    int li = dir ? (idx - ML * DIN) : idx;
    int c = li & (DIN - 1);
    int r = li / DIN;
    int l = r & (LS - 1);
    int b = r >> 11;
    const float* cw = dir ? cw1 : cw0;
    const float* cb = dir ? cb1 : cb0;
    float acc = cb[c];
    float w0 = cw[c*4+0], w1 = cw[c*4+1], w2 = cw[c*4+2], w3 = cw[c*4+3];
    size_t colOff = (size_t)dir * 4096 + c;
    if (!dir) {
        #pragma unroll
        for (int k = 0; k < 4; k++) {
            int lp = l - 3 + k;
            if (lp >= 0) {
                float w = (k==0)?w0:(k==1)?w1:(k==2)?w2:w3;
                acc += xz[(size_t)(b * LS + lp) * 8192 + colOff] * w;
            }
        }
    } else {
        #pragma unroll
        for (int k = 0; k < 4; k++) {
            int lp = l + 3 - k;
            if (lp < LS) {
                float w = (k==0)?w0:(k==1)?w1:(k==2)?w2:w3;
                acc += xz[(size_t)(b * LS + lp) * 8192 + colOff] * w;
            }
        }
    }
    xc[(size_t)dir * ML * DIN + (size_t)r * DIN + c] = siluf(acc);
}

// ---------------- selective scan: (dir,b,16d) blocks, coalesced fp32 y out -------
__global__ __launch_bounds__(256)
void scan_kernel(const float* __restrict__ dtu,   // [2][ML][DIN][2]
                 const float* __restrict__ xdbl,  // [2][ML][96] (B/C paired)
                 const float* __restrict__ xz,    // [ML][8192]
                 const float* __restrict__ A0, const float* __restrict__ A1,
                 const float* __restrict__ D0, const float* __restrict__ D1,
                 float* __restrict__ yout)        // [2][ML][DIN], tf32-rounded
{
    __shared__ float sy[32][16];

    const int tid  = threadIdx.x;
    const int wid  = tid >> 5;
    const int lane = tid & 31;
    const int half = lane >> 4;
    const int s    = lane & 15;

    const int dg  = blockIdx.x & 127;
    const int b   = (blockIdx.x >> 7) & 1;
    const int dir = blockIdx.x >> 8;
    const int dloc = wid * 2 + half;
    const int d    = dg * 16 + dloc;

    const float* Alog = dir ? A1 : A0;
    const float Av = -__expf(Alog[d * DST + s]);
    const float Dd = (dir ? D1 : D0)[d];
    float h = 0.f;
    const bool w0lane = (s == 0);

    const size_t base = (size_t)b * LS;
    const int l0 = dir ? (LS - 1) : 0;
    const int step = dir ? -1 : 1;

    const float* pDtu = dtu + ((size_t)dir * ML * DIN + (base + l0) * DIN + d) * 2;
    const float* pBC  = xdbl + (size_t)dir * ML * 96 + (base + l0) * 96 + RDT + 2 * s;
    const float* pZ   = xz + (base + l0) * 8192 + (size_t)dir * 4096 + 2048 + d;
    const ptrdiff_t sDtu = (ptrdiff_t)step * DIN * 2;
    const ptrdiff_t sBC  = (ptrdiff_t)step * 96;
    const ptrdiff_t sZ   = (ptrdiff_t)step * 8192;
    const size_t yBase = (size_t)dir * ML * DIN + base * DIN;

    float2 du = *(const float2*)pDtu;
    float2 bc = *(const float2*)pBC;
    float zv  = w0lane ? *pZ : 0.f;

    for (int it = 0; it < LS; it++) {
        const bool more = (it + 1 < LS);
        float2 dun = more ? *(const float2*)(pDtu + sDtu) : du;
        float2 bcn = more ? *(const float2*)(pBC + sBC)   : bc;
        float zn   = (w0lane && more) ? *(pZ + sZ) : zv;

        h = h * __expf(du.x * Av) + du.x * du.y * bc.x;
        float y = h * bc.y;
        y += __shfl_xor_sync(0xffffffffu, y, 8);
        y += __shfl_xor_sync(0xffffffffu, y, 4);
        y += __shfl_xor_sync(0xffffffffu, y, 2);
        y += __shfl_xor_sync(0xffffffffu, y, 1);
        if (w0lane) {
            float yv = (y + du.y * Dd) * siluf(zv);
            sy[it & 31][dloc] = rna_tf32(yv);
        }
        if ((it & 31) == 31) {
            __syncthreads();
            const int row = tid >> 3;        // 0..31
            const int cp  = tid & 7;         // 0..7
            const int itr = (it - 31) + row;
            const int gl  = l0 + step * itr;
            const size_t go = yBase + (size_t)gl * DIN + dg * 16 + 2 * cp;
            *(float2*)(yout + go) = *(const float2*)&sy[row][2 * cp];
            __syncthreads();
        }
        pDtu += sDtu; pBC += sBC; pZ += sZ;
        du = dun; bc = bcn; zv = zn;
    }
}

// ---------------- fused residual + layernorm -> xsum + tf32-rounded ln -----------
__global__ void resln_kernel(const float* __restrict__ x,
                             const float* __restrict__ y0,
                             const float* __restrict__ y1,
                             const float* __restrict__ g,
                             const float* __restrict__ bta,
                             float* __restrict__ xsum,
                             float* __restrict__ lnout)
{
    int row = blockIdx.x;
    size_t off4 = (size_t)row * (DM / 4) + threadIdx.x;
    float4 xv = ((const float4*)x)[off4];
    float4 a = ((const float4*)y0)[off4];
    float4 b = ((const float4*)y1)[off4];
    float4 v;
    v.x = xv.x + 0.5f * (a.x + b.x);
    v.y = xv.y + 0.5f * (a.y + b.y);
    v.z = xv.z + 0.5f * (a.z + b.z);
    v.w = xv.w + 0.5f * (a.w + b.w);
    ((float4*)xsum)[off4] = v;

    float s  = v.x + v.y + v.z + v.w;
    float sq = v.x*v.x + v.y*v.y + v.z*v.z + v.w*v.w;
    #pragma unroll
    for (int o = 16; o >= 1; o >>= 1) {
        s  += __shfl_xor_sync(0xffffffffu, s, o);
        sq += __shfl_xor_sync(0xffffffffu, sq, o);
    }
    __shared__ float ss[8], ssq[8];
    int warp = threadIdx.x >> 5, lane = threadIdx.x & 31;
    if (lane == 0) { ss[warp] = s; ssq[warp] = sq; }
    __syncthreads();
    __shared__ float sh_mean, sh_inv;
    if (threadIdx.x == 0) {
        float ts = 0.f, tq = 0.f;
        #pragma unroll
        for (int w = 0; w < 8; w++) { ts += ss[w]; tq += ssq[w]; }
        float mean = ts / DM;
        float var = tq / DM - mean * mean;
        sh_mean = mean;
        sh_inv = rsqrtf(var + 1e-5f);
    }
    __syncthreads();
    float mean = sh_mean, inv = sh_inv;
    float4 gv = ((const float4*)g)[threadIdx.x];
    float4 bv = ((const float4*)bta)[threadIdx.x];
    float4 o;
    o.x = rna_tf32((v.x - mean) * inv * gv.x + bv.x);
    o.y = rna_tf32((v.y - mean) * inv * gv.y + bv.y);
    o.z = rna_tf32((v.z - mean) * inv * gv.z + bv.z);
    o.w = rna_tf32((v.w - mean) * inv * gv.w + bv.w);
    ((float4*)lnout)[off4] = o;
}

// ---------------- host orchestration ----------------------------------------------
extern "C" void kernel_launch(void* const* d_in, const int* in_sizes, int n_in,
                              void* d_out, int out_size)
{
    (void)in_sizes; (void)n_in; (void)out_size;

    const float* x = (const float*)d_in[0];
    const float* in_w[2]   = { (const float*)d_in[1],  (const float*)d_in[10] };
    const float* conv_w[2] = { (const float*)d_in[2],  (const float*)d_in[11] };
    const float* conv_b[2] = { (const float*)d_in[3],  (const float*)d_in[12] };
    const float* x_w[2]    = { (const float*)d_in[4],  (const float*)d_in[13] };
    const float* dt_w[2]   = { (const float*)d_in[5],  (const float*)d_in[14] };
    const float* dt_b[2]   = { (const float*)d_in[6],  (const float*)d_in[15] };
    const float* A_log[2]  = { (const float*)d_in[7],  (const float*)d_in[16] };
    const float* Dp[2]     = { (const float*)d_in[8],  (const float*)d_in[17] };
    const float* out_w[2]  = { (const float*)d_in[9],  (const float*)d_in[18] };
    const float* ff_ln_g = (const float*)d_in[19];
    const float* ff_ln_b = (const float*)d_in[20];
    const float* ff_w1   = (const float*)d_in[21];
    const float* ff_b1   = (const float*)d_in[22];
    const float* ff_w2   = (const float*)d_in[23];
    const float* ff_b2   = (const float*)d_in[24];

    float *xz, *xc, *xdbl, *dtu, *yb, *ydir, *xsum, *lnb, *f1;
    float *xcv, *inwcv, *outwcv, *w1cv, *w2cv;
    cudaGetSymbolAddress((void**)&xz,   g_xz);
    cudaGetSymbolAddress((void**)&xc,   g_xc);
    cudaGetSymbolAddress((void**)&xdbl, g_xdbl);
    cudaGetSymbolAddress((void**)&dtu,  g_dtu);
    cudaGetSymbolAddress((void**)&yb,   g_y);
    cudaGetSymbolAddress((void**)&ydir, g_ydir);
    cudaGetSymbolAddress((void**)&xsum, g_xsum);
    cudaGetSymbolAddress((void**)&lnb,  g_ln);
    cudaGetSymbolAddress((void**)&f1,   g_f1);
    cudaGetSymbolAddress((void**)&xcv,  g_xcv);
    cudaGetSymbolAddress((void**)&inwcv,  g_inwcv);
    cudaGetSymbolAddress((void**)&outwcv, g_outwcv);
    cudaGetSymbolAddress((void**)&w1cv, g_w1cv);
    cudaGetSymbolAddress((void**)&w2cv, g_w2cv);

    cudaFuncSetAttribute(t32_gemm, cudaFuncAttributeMaxDynamicSharedMemorySize, DSMEM3);

    const size_t szXC   = (size_t)ML * DIN;
    const size_t szYDIR = (size_t)ML * DM;
    const size_t szINW  = (size_t)2 * DIN * DM;
    const size_t szOUTW = (size_t)DM * DIN;

    dim3 blk(256);

    // idx 0-2: converts needed for in-proj
    cvt_kernel<<<(ML*DM/4 + 255)/256, blk>>>(x, xcv, ML*DM/4);
    cvt_kernel<<<((int)szINW/4 + 255)/256, blk>>>(in_w[0], inwcv,         (int)szINW/4);
    cvt_kernel<<<((int)szINW/4 + 255)/256, blk>>>(in_w[1], inwcv + szINW, (int)szINW/4);

    // idx 3 (profiled): merged in-proj, M=4096, N=8192, K=1024
    t32_gemm<<<dim3(64, 32, 1), blk, DSMEM3>>>(
        xcv, DM, inwcv, DM,
        nullptr, nullptr, xz,
        8192, DM, 0, 0, 0, 0, 0);

    // remaining converts
    cvt_kernel<<<((int)szOUTW/4 + 255)/256, blk>>>(out_w[0], outwcv,          (int)szOUTW/4);
    cvt_kernel<<<((int)szOUTW/4 + 255)/256, blk>>>(out_w[1], outwcv + szOUTW, (int)szOUTW/4);
    cvt_kernel<<<(DFF*DM/4 + 255)/256, blk>>>(ff_w1, w1cv, DFF*DM/4);
    cvt_kernel<<<(DM*DFF/4 + 255)/256, blk>>>(ff_w2, w2cv, DM*DFF/4);

    // conv (both dirs)
    conv_kernel<<<(2*ML*DIN + 255)/256, blk>>>(xz, conv_w[0], conv_w[1],
                                               conv_b[0], conv_b[1], xc);

    // xdbl (both dirs), B/C interleaved
    xdbl_gemm<<<dim3(ML/32, 1, 2), dim3(128)>>>(xc, x_w[0], x_w[1], xdbl);

    // dt (both dirs) -> (dt, u) pairs
    dt_gemm<<<dim3(DIN/128, ML/128, 2), blk>>>(xdbl, xc, dt_w[0], dt_w[1],
                                               dt_b[0], dt_b[1], dtu);

    // scan (both dirs): 512 blocks = 2 dir x 2 b x 128 d-groups
    scan_kernel<<<512, blk>>>(dtu, xdbl, xz, A_log[0], A_log[1],
                              Dp[0], Dp[1], yb);

    // out-proj (both dirs via z): ydir[z] = y[z] @ out_w[z]^T
    t32_gemm<<<dim3(8, 32, 2), blk, DSMEM3>>>(
        yb, DIN, outwcv, DIN,
        nullptr, nullptr, ydir,
        DM, DIN, 0, 0, szXC, szOUTW, szYDIR);

    // fused residual + LN (ln tf32-rounded)
    resln_kernel<<<ML, blk>>>(x, ydir, ydir + szYDIR, ff_ln_g, ff_ln_b,
                              xsum, lnb);

    // ff1 = silu(ln @ ff_w1^T + b1), output tf32-rounded
    t32_gemm<<<dim3(32, 32, 1), blk, DSMEM3>>>(
        lnb, DM, w1cv, DM,
        ff_b1, nullptr, f1,
        DFF, DM, 1, 1, 0, 0, 0);

    // out = xsum + (ff1 @ ff_w2^T + b2)
    t32_gemm<<<dim3(8, 32, 1), blk, DSMEM3>>>(
        f1, DFF, w2cv, DFF,
        ff_b2, xsum, (float*)d_out,
        DM, DFF, 0, 0, 0, 0, 0);
}

// round 11
// speedup vs baseline: 1.0005x; 1.0005x over previous
#include <cuda_runtime.h>
#include <cuda_bf16.h>
#include <math.h>
#include <stdint.h>

// Problem constants
#define BB   2
#define LS   2048
#define DM   1024
#define DIN  2048
#define DST  16
#define RDT  64
#define ML   (BB*LS)      // 4096 rows
#define DFF  (4*DM)       // 4096

// ---------------- scratch (device globals) -----------------------------------
__device__ __align__(256) float g_xz  [(size_t)ML * 8192];
__device__ __align__(256) float g_xc  [2u * ML * DIN];
__device__ __align__(256) float g_xdbl[2u * ML * 96];
__device__ __align__(256) float g_dtu [2u * (size_t)ML * DIN * 2];
__device__ __align__(256) float g_y   [2u * ML * DIN];    // scan out, PERMUTED+tf32
__device__ __align__(256) float g_ydir[2u * ML * DM];
__device__ __align__(256) float g_xsum[(size_t)ML * DM];
__device__ __align__(256) float g_ln  [(size_t)ML * DM];  // PERMUTED+tf32
__device__ __align__(256) float g_f1  [(size_t)ML * DFF]; // PERMUTED+tf32
__device__ __align__(256) float g_xcv [(size_t)ML * DM];  // PERMUTED+tf32
__device__ __align__(256) float g_inwcv [2u * 2 * DIN * DM];
__device__ __align__(256) float g_outwcv[2u * DM * DIN];
__device__ __align__(256) float g_w1cv[(size_t)DFF * DM];
__device__ __align__(256) float g_w2cv[(size_t)DM * DFF];

// ---------------- helpers ------------------------------------------------------
__device__ __forceinline__ float siluf(float v) { return v / (1.f + __expf(-v)); }
__device__ __forceinline__ float softplusf(float v) {
    return (v > 20.f) ? v : log1pf(__expf(v));
}
__device__ __forceinline__ float rna_tf32(float f) {
    uint32_t u;
    asm("cvt.rna.tf32.f32 %0, %1;" : "=r"(u) : "f"(f));
    return __uint_as_float(u);
}
// permute k within each 32-block: p = (k%4)*8 + (k%32)/4
__device__ __forceinline__ int permk(int k) {
    int off = k & 31;
    return (k & ~31) + ((off & 3) << 3) + (off >> 2);
}

#define MMAT32(d, a0, a1, a2, a3, b0, b1) \
    asm volatile("mma.sync.aligned.m16n8k8.row.col.f32.tf32.tf32.f32 " \
        "{%0,%1,%2,%3}, {%4,%5,%6,%7}, {%8,%9}, {%0,%1,%2,%3};" \
        : "+f"((d)[0]), "+f"((d)[1]), "+f"((d)[2]), "+f"((d)[3]) \
        : "r"(a0), "r"(a1), "r"(a2), "r"(a3), "r"(b0), "r"(b1))

#define CPA16(sa, ga) \
    asm volatile("cp.async.cg.shared.global [%0], [%1], 16;" :: "r"(sa), "l"(ga))
#define CPA_COMMIT() asm volatile("cp.async.commit_group;" ::: "memory")
#define CPA_WAIT1()  asm volatile("cp.async.wait_group 1;" ::: "memory")

// ---------------- tf32 GEMM, pi-permuted inputs, float4 fragment loads ----------
#define KCF     32
#define ROWF    36
#define ARR_F   (128 * ROWF * 4)        // 18432 B
#define STAGE_F (2 * ARR_F)             // 36864 B
#define NSTG    3
#define DSMEM3  (NSTG * STAGE_F)        // 110592 B

__global__ __launch_bounds__(256, 2)
void t32_gemm(const float* __restrict__ A, int lda,
              const float* __restrict__ Bw, int ldb,
              const float* __restrict__ bias,
              const float* __restrict__ addsrc,
              float* __restrict__ Cf,
              int ldc, int K, int act, int permC,
              size_t zsA, size_t zsB, size_t zsC)
{
    extern __shared__ char sm[];
    const int tid  = threadIdx.x;
    const int lane = tid & 31;
    const int wid  = tid >> 5;
    const int wm   = wid >> 2;
    const int wn   = wid & 3;
    const int rowBase = blockIdx.y * 128;
    const int colBase = blockIdx.x * 128;
    const size_t zA = (size_t)blockIdx.z * zsA;
    const size_t zB = (size_t)blockIdx.z * zsB;
    const size_t zC = (size_t)blockIdx.z * zsC;
    const uint32_t smb = (uint32_t)__cvta_generic_to_shared(sm);

    // loader: thread t -> one row (A: 0..127, B: 128..255), 8 x 16B chunks
    const int isB  = tid >> 7;
    const int lrow = tid & 127;
    const size_t gRow = isB ? (zB + (size_t)(colBase + lrow) * ldb)
                            : (zA + (size_t)(rowBase + lrow) * lda);
    const float* gBase = isB ? Bw : A;
    const uint32_t sRow = (uint32_t)(isB ? ARR_F : 0) + (uint32_t)lrow * (ROWF * 4);

    const int gid  = lane >> 2;
    const int ctid = lane & 3;
    // fragment float4 base offsets (bytes): row*ROWF + ctid*8 floats
    uint32_t aOff[4], bOff[4];
    #pragma unroll
    for (int i = 0; i < 4; i++)
        aOff[i] = (uint32_t)((wm * 64 + i * 16 + gid) * ROWF + ctid * 8) * 4;
    #pragma unroll
    for (int j = 0; j < 4; j++)
        bOff[j] = (uint32_t)ARR_F + (uint32_t)((wn * 32 + j * 8 + gid) * ROWF + ctid * 8) * 4;

    float acc[16][4];
    #pragma unroll
    for (int i = 0; i < 16; i++)
        #pragma unroll
        for (int j = 0; j < 4; j++) acc[i][j] = 0.f;

    const int nk = K / KCF;

    auto issue = [&](int stg, int kt) {
        const uint32_t sb = smb + (uint32_t)stg * STAGE_F + sRow;
        const float* gp = gBase + gRow + (size_t)kt * KCF;
        #pragma unroll
        for (int c = 0; c < 8; c++)
            CPA16(sb + (uint32_t)c * 16, gp + c * 4);
    };

    issue(0, 0); CPA_COMMIT();
    issue(1, 1); CPA_COMMIT();

    int stg = 0;
    for (int kt = 0; kt < nk; kt++) {
        CPA_WAIT1();
        __syncthreads();
        if (kt + 2 < nk) issue((stg + 2) % NSTG, kt + 2);
        CPA_COMMIT();

        const char* base = sm + (size_t)stg * STAGE_F;
        #pragma unroll
        for (int ksp = 0; ksp < 2; ksp++) {
            const uint32_t kadd = (uint32_t)ksp * 16;   // 4 floats
            float4 aQ0[4], aQ1[4], bQ[4];
            #pragma unroll
            for (int j = 0; j < 4; j++)
                bQ[j] = *(const float4*)(base + bOff[j] + kadd);
            #pragma unroll
            for (int i = 0; i < 4; i++) {
                aQ0[i] = *(const float4*)(base + aOff[i] + kadd);
                aQ1[i] = *(const float4*)(base + aOff[i] + kadd + 8 * ROWF * 4);
            }
            #pragma unroll
            for (int i = 0; i < 4; i++)
                #pragma unroll
                for (int j = 0; j < 4; j++) {
                    MMAT32(acc[i*4+j],
                           __float_as_uint(aQ0[i].x), __float_as_uint(aQ1[i].x),
                           __float_as_uint(aQ0[i].y), __float_as_uint(aQ1[i].y),
                           __float_as_uint(bQ[j].x),  __float_as_uint(bQ[j].y));
                    MMAT32(acc[i*4+j],
                           __float_as_uint(aQ0[i].z), __float_as_uint(aQ1[i].z),
                           __float_as_uint(aQ0[i].w), __float_as_uint(aQ1[i].w),
                           __float_as_uint(bQ[j].z),  __float_as_uint(bQ[j].w));
                }
        }
        stg = (stg + 1) % NSTG;
    }

    const int erow  = wm * 64 + (lane >> 2);
    const int ecol0 = wn * 32 + (lane & 3) * 2;
    #pragma unroll
    for (int i = 0; i < 4; i++) {
        int r0 = rowBase + erow + i * 16;
        int r1 = r0 + 8;
        #pragma unroll
        for (int nt = 0; nt < 4; nt++) {
            int c = colBase + ecol0 + nt * 8;
            float v0 = acc[i*4+nt][0], v1 = acc[i*4+nt][1];
            float v2 = acc[i*4+nt][2], v3 = acc[i*4+nt][3];
            if (bias) {
                float b0 = __ldg(&bias[c]), b1 = __ldg(&bias[c+1]);
                v0 += b0; v1 += b1; v2 += b0; v3 += b1;
            }
            if (act == 1) { v0 = siluf(v0); v1 = siluf(v1); v2 = siluf(v2); v3 = siluf(v3); }
            else if (act == 2) { v0 = softplusf(v0); v1 = softplusf(v1); v2 = softplusf(v2); v3 = softplusf(v3); }
            if (addsrc) {
                v0 += addsrc[(size_t)r0 * ldc + c];
                v1 += addsrc[(size_t)r0 * ldc + c + 1];
                v2 += addsrc[(size_t)r1 * ldc + c];
                v3 += addsrc[(size_t)r1 * ldc + c + 1];
            }
            if (permC) {
                int p0 = permk(c), p1 = permk(c + 1);
                Cf[zC + (size_t)r0 * ldc + p0] = rna_tf32(v0);
                Cf[zC + (size_t)r0 * ldc + p1] = rna_tf32(v1);
                Cf[zC + (size_t)r1 * ldc + p0] = rna_tf32(v2);
                Cf[zC + (size_t)r1 * ldc + p1] = rna_tf32(v3);
            } else {
                *(float2*)&Cf[zC + (size_t)r0 * ldc + c] = make_float2(v0, v1);
                *(float2*)&Cf[zC + (size_t)r1 * ldc + c] = make_float2(v2, v3);
            }
        }
    }
}

// ---------------- fp32 -> tf32(RNA), pi-permuted ---------------------------------
__global__ void cvt_kernel(const float* __restrict__ in,
                           float* __restrict__ out, int n4)
{
    int i = blockIdx.x * blockDim.x + threadIdx.x;
    if (i >= n4) return;
    float4 v = ((const float4*)in)[i];
    int k0 = i * 4;
    int blk = k0 & ~31;
    int off = k0 & 31;          // multiple of 4
    int pbase = blk + (off >> 2);
    out[pbase +  0] = rna_tf32(v.x);
    out[pbase +  8] = rna_tf32(v.y);
    out[pbase + 16] = rna_tf32(v.z);
    out[pbase + 24] = rna_tf32(v.w);
}

// ---------------- xdbl GEMM: [2][ML][96], B/C interleaved in cols 64..95 --------
__global__ __launch_bounds__(128)
void xdbl_gemm(const float* __restrict__ xcA,
               const float* __restrict__ xw0,
               const float* __restrict__ xw1,
               float* __restrict__ out)
{
    __shared__ float As[16][36];
    __shared__ float Bs[16][100];
    const int dir = blockIdx.z;
    const float* A = xcA + (size_t)dir * ML * DIN + (size_t)blockIdx.x * 32 * DIN;
    const float* B = dir ? xw1 : xw0;
    float* C = out + (size_t)dir * ML * 96 + (size_t)blockIdx.x * 32 * 96;

    const int tid = threadIdx.x;
    const int tx = tid & 15, ty = tid >> 4;
    float acc[4][6];
    #pragma unroll
    for (int i = 0; i < 4; i++)
        #pragma unroll
        for (int j = 0; j < 6; j++) acc[i][j] = 0.f;

    const int ar = tid >> 2, akc = (tid & 3) * 4;

    for (int k0 = 0; k0 < DIN; k0 += 16) {
        {
            float4 v = *(const float4*)(A + (size_t)ar * DIN + k0 + akc);
            As[akc+0][ar] = v.x; As[akc+1][ar] = v.y;
            As[akc+2][ar] = v.z; As[akc+3][ar] = v.w;
        }
        #pragma unroll
        for (int j = 0; j < 3; j++) {
            int i = tid + j * 128;
            int n = i >> 2, kc = (i & 3) * 4;
            float4 v = *(const float4*)(B + (size_t)n * DIN + k0 + kc);
            Bs[kc+0][n] = v.x; Bs[kc+1][n] = v.y;
            Bs[kc+2][n] = v.z; Bs[kc+3][n] = v.w;
        }
        __syncthreads();
        #pragma unroll
        for (int kk = 0; kk < 16; kk++) {
            float4 a4 = *(const float4*)&As[kk][ty*4];
            float ar4[4] = {a4.x, a4.y, a4.z, a4.w};
            float2 b0 = *(const float2*)&Bs[kk][tx*6];
            float2 b1 = *(const float2*)&Bs[kk][tx*6+2];
            float2 b2 = *(const float2*)&Bs[kk][tx*6+4];
            float br[6] = {b0.x, b0.y, b1.x, b1.y, b2.x, b2.y};
            #pragma unroll
            for (int i = 0; i < 4; i++)
                #pragma unroll
                for (int j = 0; j < 6; j++)
                    acc[i][j] = fmaf(ar4[i], br[j], acc[i][j]);
        }
        __syncthreads();
    }
    #pragma unroll
    for (int i = 0; i < 4; i++)
        #pragma unroll
        for (int j = 0; j < 6; j++) {
            int c = tx*6 + j;
            int cw = (c < 64) ? c : ((c < 80) ? (64 + 2*(c - 64)) : (65 + 2*(c - 80)));
            C[(size_t)(ty*4+i) * 96 + cw] = acc[i][j];
        }
}

// ---------------- dt GEMM -> (dt, u) float2 pairs --------------------------------
__global__ __launch_bounds__(256)
void dt_gemm(const float* __restrict__ xdblA,
             const float* __restrict__ xcA,
             const float* __restrict__ w0, const float* __restrict__ w1,
             const float* __restrict__ b0, const float* __restrict__ b1,
             float* __restrict__ out)
{
    __shared__ float As[16][132];
    __shared__ float Bs[16][132];

    const int dir = blockIdx.z;
    const float* A = xdblA + (size_t)dir * ML * 96;
    const float* xcD = xcA + (size_t)dir * ML * DIN;
    const float* Bw = dir ? w1 : w0;
    const float* bias = dir ? b1 : b0;
    float* C = out + (size_t)dir * ML * DIN * 2;

    const int tid = threadIdx.x;
    const int tx = tid & 15;
    const int ty = tid >> 4;
    const int rowBase = blockIdx.y * 128;
    const int colBase = blockIdx.x * 128;

    const int lm = tid >> 1;
    const int lk = (tid & 1) * 8;

    const float* aPtr = A + (size_t)(rowBase + lm) * 96 + lk;
    const float* bPtr = Bw + (size_t)(colBase + lm) * RDT + lk;

    float acc[8][8];
    #pragma unroll
    for (int i = 0; i < 8; i++)
        #pragma unroll
        for (int j = 0; j < 8; j++) acc[i][j] = 0.f;

    for (int k0 = 0; k0 < RDT; k0 += 16) {
        float4 a0 = *(const float4*)(aPtr + k0);
        float4 a1 = *(const float4*)(aPtr + k0 + 4);
        float4 b0v = *(const float4*)(bPtr + k0);
        float4 b1v = *(const float4*)(bPtr + k0 + 4);

        As[lk+0][lm] = a0.x; As[lk+1][lm] = a0.y; As[lk+2][lm] = a0.z; As[lk+3][lm] = a0.w;
        As[lk+4][lm] = a1.x; As[lk+5][lm] = a1.y; As[lk+6][lm] = a1.z; As[lk+7][lm] = a1.w;
        Bs[lk+0][lm] = b0v.x; Bs[lk+1][lm] = b0v.y; Bs[lk+2][lm] = b0v.z; Bs[lk+3][lm] = b0v.w;
        Bs[lk+4][lm] = b1v.x; Bs[lk+5][lm] = b1v.y; Bs[lk+6][lm] = b1v.z; Bs[lk+7][lm] = b1v.w;
        __syncthreads();

        #pragma unroll
        for (int kk = 0; kk < 16; kk++) {
            float4 ra0 = *(const float4*)&As[kk][ty * 4];
            float4 ra1 = *(const float4*)&As[kk][64 + ty * 4];
            float4 rb0 = *(const float4*)&Bs[kk][tx * 4];
            float4 rb1 = *(const float4*)&Bs[kk][64 + tx * 4];
            float ar[8] = {ra0.x, ra0.y, ra0.z, ra0.w, ra1.x, ra1.y, ra1.z, ra1.w};
            float br[8] = {rb0.x, rb0.y, rb0.z, rb0.w, rb1.x, rb1.y, rb1.z, rb1.w};
            #pragma unroll
            for (int i = 0; i < 8; i++)
                #pragma unroll
                for (int j = 0; j < 8; j++)
                    acc[i][j] = fmaf(ar[i], br[j], acc[i][j]);
        }
        __syncthreads();
    }

    #pragma unroll
    for (int i = 0; i < 8; i++) {
        int r = rowBase + ((i < 4) ? (ty * 4 + i) : (64 + ty * 4 + i - 4));
        #pragma unroll
        for (int j = 0; j < 8; j++) {
            int c = colBase + ((j < 4) ? (tx * 4 + j) : (64 + tx * 4 + j - 4));
            float dtv = softplusf(acc[i][j] + bias[c]);
            float uv  = xcD[(size_t)r * DIN + c];
            *(float2*)&C[((size_t)r * DIN + c) * 2] = make_float2(dtv, uv);
        }
    }
}

// ---------------- depthwise causal conv (k=4, dir-dependent taps) ---------------
__global__ void conv_kernel(const float* __restrict__ xz,
                            const float* __restrict__ cw0, const float* __restrict__ cw1,
                            const float* __restrict__ cb0, const float* __restrict__ cb1,
                            float* __restrict__ xc)
{
    int idx = blockIdx.x * blockDim.x + threadIdx.x;
    if (idx >= 2 * ML * DIN) return;
    int dir = idx >= ML * DIN;
    int li = dir ? (idx - ML * DIN) : idx;
    int c = li & (DIN - 1);
    int r = li / DIN;
    int l = r & (LS - 1);
    int b = r >> 11;
    const float* cw = dir ? cw1 : cw0;
    const float* cb = dir ? cb1 : cb0;
    float acc = cb[c];
    float w0 = cw[c*4+0], w1 = cw[c*4+1], w2 = cw[c*4+2], w3 = cw[c*4+3];
    size_t colOff = (size_t)dir * 4096 + c;
    if (!dir) {
        #pragma unroll
        for (int k = 0; k < 4; k++) {
            int lp = l - 3 + k;
            if (lp >= 0) {
                float w = (k==0)?w0:(k==1)?w1:(k==2)?w2:w3;
                acc += xz[(size_t)(b * LS + lp) * 8192 + colOff] * w;
            }
        }
    } else {
        #pragma unroll
        for (int k = 0; k < 4; k++) {
            int lp = l + 3 - k;
            if (lp < LS) {
                float w = (k==0)?w0:(k==1)?w1:(k==2)?w2:w3;
                acc += xz[(size_t)(b * LS + lp) * 8192 + colOff] * w;
            }
        }
    }
    xc[(size_t)dir * ML * DIN + (size_t)r * DIN + c] = siluf(acc);
}

// ---------------- selective scan -> permuted tf32 y -------------------------------
__global__ __launch_bounds__(256)
void scan_kernel(const float* __restrict__ dtu,
                 const float* __restrict__ xdbl,
                 const float* __restrict__ xz,
                 const float* __restrict__ A0, const float* __restrict__ A1,
                 const float* __restrict__ D0, const float* __restrict__ D1,
                 float* __restrict__ yout)
{
    __shared__ float sy[32][16];

    const int tid  = threadIdx.x;
    const int wid  = tid >> 5;
    const int lane = tid & 31;
    const int half = lane >> 4;
    const int s    = lane & 15;

    const int dg  = blockIdx.x & 127;
    const int b   = (blockIdx.x >> 7) & 1;
    const int dir = blockIdx.x >> 8;
    const int dloc = wid * 2 + half;
    const int d    = dg * 16 + dloc;

    const float* Alog = dir ? A1 : A0;
    const float Av = -__expf(Alog[d * DST + s]);
    const float Dd = (dir ? D1 : D0)[d];
    float h = 0.f;
    const bool w0lane = (s == 0);

    const size_t base = (size_t)b * LS;
    const int l0 = dir ? (LS - 1) : 0;
    const int step = dir ? -1 : 1;

    const float* pDtu = dtu + ((size_t)dir * ML * DIN + (base + l0) * DIN + d) * 2;
    const float* pBC  = xdbl + (size_t)dir * ML * 96 + (base + l0) * 96 + RDT + 2 * s;
    const float* pZ   = xz + (base + l0) * 8192 + (size_t)dir * 4096 + 2048 + d;
    const ptrdiff_t sDtu = (ptrdiff_t)step * DIN * 2;
    const ptrdiff_t sBC  = (ptrdiff_t)step * 96;
    const ptrdiff_t sZ   = (ptrdiff_t)step * 8192;
    const size_t yBase = (size_t)dir * ML * DIN + base * DIN;

    // flush-store permuted columns (computed once)
    const int fcp = tid & 7;
    const int c0 = dg * 16 + 2 * fcp;
    const int p0 = permk(c0), p1 = permk(c0 + 1);

    float2 du = *(const float2*)pDtu;
    float2 bc = *(const float2*)pBC;
    float zv  = w0lane ? *pZ : 0.f;

    for (int it = 0; it < LS; it++) {
        const bool more = (it + 1 < LS);
        float2 dun = more ? *(const float2*)(pDtu + sDtu) : du;
        float2 bcn = more ? *(const float2*)(pBC + sBC)   : bc;
        float zn   = (w0lane && more) ? *(pZ + sZ) : zv;

        h = h * __expf(du.x * Av) + du.x * du.y * bc.x;
        float y = h * bc.y;
        y += __shfl_xor_sync(0xffffffffu, y, 8);
        y += __shfl_xor_sync(0xffffffffu, y, 4);
        y += __shfl_xor_sync(0xffffffffu, y, 2);
        y += __shfl_xor_sync(0xffffffffu, y, 1);
        if (w0lane) {
            float yv = (y + du.y * Dd) * siluf(zv);
            sy[it & 31][dloc] = rna_tf32(yv);
        }
        if ((it & 31) == 31) {
            __syncthreads();
            const int row = tid >> 3;
            const int itr = (it - 31) + row;
            const int gl  = l0 + step * itr;
            const size_t go = yBase + (size_t)gl * DIN;
            yout[go + p0] = sy[row][2 * fcp];
            yout[go + p1] = sy[row][2 * fcp + 1];
            __syncthreads();
        }
        pDtu += sDtu; pBC += sBC; pZ += sZ;
        du = dun; bc = bcn; zv = zn;
    }
}

// ---------------- fused residual + layernorm -> xsum + permuted tf32 ln ----------
__global__ void resln_kernel(const float* __restrict__ x,
                             const float* __restrict__ y0,
                             const float* __restrict__ y1,
                             const float* __restrict__ g,
                             const float* __restrict__ bta,
                             float* __restrict__ xsum,
                             float* __restrict__ lnout)
{
    int row = blockIdx.x;
    size_t off4 = (size_t)row * (DM / 4) + threadIdx.x;
    float4 xv = ((const float4*)x)[off4];
    float4 a = ((const float4*)y0)[off4];
    float4 b = ((const float4*)y1)[off4];
    float4 v;
    v.x = xv.x + 0.5f * (a.x + b.x);
    v.y = xv.y + 0.5f * (a.y + b.y);
    v.z = xv.z + 0.5f * (a.z + b.z);
    v.w = xv.w + 0.5f * (a.w + b.w);
    ((float4*)xsum)[off4] = v;

    float s  = v.x + v.y + v.z + v.w;
    float sq = v.x*v.x + v.y*v.y + v.z*v.z + v.w*v.w;
    #pragma unroll
    for (int o = 16; o >= 1; o >>= 1) {
        s  += __shfl_xor_sync(0xffffffffu, s, o);
        sq += __shfl_xor_sync(0xffffffffu, sq, o);
    }
    __shared__ float ss[8], ssq[8];
    int warp = threadIdx.x >> 5, lane = threadIdx.x & 31;
    if (lane == 0) { ss[warp] = s; ssq[warp] = sq; }
    __syncthreads();
    __shared__ float sh_mean, sh_inv;
    if (threadIdx.x == 0) {
        float ts = 0.f, tq = 0.f;
        #pragma unroll
        for (int w = 0; w < 8; w++) { ts += ss[w]; tq += ssq[w]; }
        float mean = ts / DM;
        float var = tq / DM - mean * mean;
        sh_mean = mean;
        sh_inv = rsqrtf(var + 1e-5f);
    }
    __syncthreads();
    float mean = sh_mean, inv = sh_inv;
    float4 gv = ((const float4*)g)[threadIdx.x];
    float4 bv = ((const float4*)bta)[threadIdx.x];
    float o0 = rna_tf32((v.x - mean) * inv * gv.x + bv.x);
    float o1 = rna_tf32((v.y - mean) * inv * gv.y + bv.y);
    float o2 = rna_tf32((v.z - mean) * inv * gv.z + bv.z);
    float o3 = rna_tf32((v.w - mean) * inv * gv.w + bv.w);
    int k0 = threadIdx.x * 4;
    int pbase = (k0 & ~31) + ((k0 & 31) >> 2);
    float* lr = lnout + (size_t)row * DM;
    lr[pbase +  0] = o0;
    lr[pbase +  8] = o1;
    lr[pbase + 16] = o2;
    lr[pbase + 24] = o3;
}

// ---------------- host orchestration ----------------------------------------------
extern "C" void kernel_launch(void* const* d_in, const int* in_sizes, int n_in,
                              void* d_out, int out_size)
{
    (void)in_sizes; (void)n_in; (void)out_size;

    const float* x = (const float*)d_in[0];
    const float* in_w[2]   = { (const float*)d_in[1],  (const float*)d_in[10] };
    const float* conv_w[2] = { (const float*)d_in[2],  (const float*)d_in[11] };
    const float* conv_b[2] = { (const float*)d_in[3],  (const float*)d_in[12] };
    const float* x_w[2]    = { (const float*)d_in[4],  (const float*)d_in[13] };
    const float* dt_w[2]   = { (const float*)d_in[5],  (const float*)d_in[14] };
    const float* dt_b[2]   = { (const float*)d_in[6],  (const float*)d_in[15] };
    const float* A_log[2]  = { (const float*)d_in[7],  (const float*)d_in[16] };
    const float* Dp[2]     = { (const float*)d_in[8],  (const float*)d_in[17] };
    const float* out_w[2]  = { (const float*)d_in[9],  (const float*)d_in[18] };
    const float* ff_ln_g = (const float*)d_in[19];
    const float* ff_ln_b = (const float*)d_in[20];
    const float* ff_w1   = (const float*)d_in[21];
    const float* ff_b1   = (const float*)d_in[22];
    const float* ff_w2   = (const float*)d_in[23];
    const float* ff_b2   = (const float*)d_in[24];

    float *xz, *xc, *xdbl, *dtu, *yb, *ydir, *xsum, *lnb, *f1;
    float *xcv, *inwcv, *outwcv, *w1cv, *w2cv;
    cudaGetSymbolAddress((void**)&xz,   g_xz);
    cudaGetSymbolAddress((void**)&xc,   g_xc);
    cudaGetSymbolAddress((void**)&xdbl, g_xdbl);
    cudaGetSymbolAddress((void**)&dtu,  g_dtu);
    cudaGetSymbolAddress((void**)&yb,   g_y);
    cudaGetSymbolAddress((void**)&ydir, g_ydir);
    cudaGetSymbolAddress((void**)&xsum, g_xsum);
    cudaGetSymbolAddress((void**)&lnb,  g_ln);
    cudaGetSymbolAddress((void**)&f1,   g_f1);
    cudaGetSymbolAddress((void**)&xcv,  g_xcv);
    cudaGetSymbolAddress((void**)&inwcv,  g_inwcv);
    cudaGetSymbolAddress((void**)&outwcv, g_outwcv);
    cudaGetSymbolAddress((void**)&w1cv, g_w1cv);
    cudaGetSymbolAddress((void**)&w2cv, g_w2cv);

    cudaFuncSetAttribute(t32_gemm, cudaFuncAttributeMaxDynamicSharedMemorySize, DSMEM3);

    const size_t szXC   = (size_t)ML * DIN;
    const size_t szYDIR = (size_t)ML * DM;
    const size_t szINW  = (size_t)2 * DIN * DM;
    const size_t szOUTW = (size_t)DM * DIN;

    dim3 blk(256);

    // idx 0-2: converts needed for in-proj
    cvt_kernel<<<(ML*DM/4 + 255)/256, blk>>>(x, xcv, ML*DM/4);
    cvt_kernel<<<((int)szINW/4 + 255)/256, blk>>>(in_w[0], inwcv,         (int)szINW/4);
    cvt_kernel<<<((int)szINW/4 + 255)/256, blk>>>(in_w[1], inwcv + szINW, (int)szINW/4);

    // idx 3 (profiled): merged in-proj, M=4096, N=8192, K=1024
    t32_gemm<<<dim3(64, 32, 1), blk, DSMEM3>>>(
        xcv, DM, inwcv, DM,
        nullptr, nullptr, xz,
        8192, DM, 0, 0, 0, 0, 0);

    // remaining converts
    cvt_kernel<<<((int)szOUTW/4 + 255)/256, blk>>>(out_w[0], outwcv,          (int)szOUTW/4);
    cvt_kernel<<<((int)szOUTW/4 + 255)/256, blk>>>(out_w[1], outwcv + szOUTW, (int)szOUTW/4);
    cvt_kernel<<<(DFF*DM/4 + 255)/256, blk>>>(ff_w1, w1cv, DFF*DM/4);
    cvt_kernel<<<(DM*DFF/4 + 255)/256, blk>>>(ff_w2, w2cv, DM*DFF/4);

    // conv (both dirs)
    conv_kernel<<<(2*ML*DIN + 255)/256, blk>>>(xz, conv_w[0], conv_w[1],
                                               conv_b[0], conv_b[1], xc);

    // xdbl (both dirs), B/C interleaved
    xdbl_gemm<<<dim3(ML/32, 1, 2), dim3(128)>>>(xc, x_w[0], x_w[1], xdbl);

    // dt (both dirs) -> (dt, u) pairs
    dt_gemm<<<dim3(DIN/128, ML/128, 2), blk>>>(xdbl, xc, dt_w[0], dt_w[1],
                                               dt_b[0], dt_b[1], dtu);

    // scan (both dirs) -> permuted tf32 y
    scan_kernel<<<512, blk>>>(dtu, xdbl, xz, A_log[0], A_log[1],
                              Dp[0], Dp[1], yb);

    // out-proj (both dirs via z)
    t32_gemm<<<dim3(8, 32, 2), blk, DSMEM3>>>(
        yb, DIN, outwcv, DIN,
        nullptr, nullptr, ydir,
        DM, DIN, 0, 0, szXC, szOUTW, szYDIR);

    // fused residual + LN (permuted tf32 ln)
    resln_kernel<<<ML, blk>>>(x, ydir, ydir + szYDIR, ff_ln_g, ff_ln_b,
                              xsum, lnb);

    // ff1 = silu(ln @ ff_w1^T + b1), permuted tf32 output
    t32_gemm<<<dim3(32, 32, 1), blk, DSMEM3>>>(
        lnb, DM, w1cv, DM,
        ff_b1, nullptr, f1,
        DFF, DM, 1, 1, 0, 0, 0);

    // out = xsum + (ff1 @ ff_w2^T + b2)
    t32_gemm<<<dim3(8, 32, 1), blk, DSMEM3>>>(
        f1, DFF, w2cv, DFF,
        ff_b2, xsum, (float*)d_out,
        DM, DFF, 0, 0, 0, 0, 0);
}

// round 12
// speedup vs baseline: 1.2778x; 1.2772x over previous
#include <cuda_runtime.h>
#include <cuda_bf16.h>
#include <math.h>
#include <stdint.h>

// Problem constants
#define BB   2
#define LS   2048
#define DM   1024
#define DIN  2048
#define DST  16
#define RDT  64
#define ML   (BB*LS)      // 4096 rows
#define DFF  (4*DM)       // 4096

typedef __nv_bfloat16 bf16;

// ---------------- scratch (device globals) -----------------------------------
// xz unified: [ML][8192], cols [dir*4096 .. +2047]=xi, [+2048..+4095]=z
__device__ __align__(256) float g_xz  [(size_t)ML * 8192];
__device__ __align__(256) float g_xc  [2u * ML * DIN];
__device__ __align__(256) float g_xdbl[2u * ML * 96];     // cols 64..95: B/C interleaved
__device__ __align__(256) float g_dtu [2u * (size_t)ML * DIN * 2];  // (dt, u) pairs
__device__ __align__(256) float g_ydir[2u * ML * DM];
__device__ __align__(256) float g_xsum[(size_t)ML * DM];

__device__ __align__(256) bf16 g_xhi [(size_t)ML * DM],  g_xlo [(size_t)ML * DM];
__device__ __align__(256) bf16 g_yhi [2u * ML * DIN],    g_ylo [2u * ML * DIN];
__device__ __align__(256) bf16 g_lnhi[(size_t)ML * DM],  g_lnlo[(size_t)ML * DM];
__device__ __align__(256) bf16 g_f1hi[(size_t)ML * DFF], g_f1lo[(size_t)ML * DFF];
__device__ __align__(256) bf16 g_inwhi [2u * 2 * DIN * DM], g_inwlo [2u * 2 * DIN * DM];
__device__ __align__(256) bf16 g_outwhi[2u * DM * DIN],     g_outwlo[2u * DM * DIN];
__device__ __align__(256) bf16 g_w1hi[(size_t)DFF * DM],  g_w1lo[(size_t)DFF * DM];
__device__ __align__(256) bf16 g_w2hi[(size_t)DM * DFF],  g_w2lo[(size_t)DM * DFF];

// ---------------- helpers ------------------------------------------------------
__device__ __forceinline__ float siluf(float v) { return v / (1.f + __expf(-v)); }
__device__ __forceinline__ float softplusf(float v) {
    return (v > 20.f) ? v : log1pf(__expf(v));
}
__device__ __forceinline__ void split1(float f, unsigned short& h, unsigned short& l) {
    __nv_bfloat16 hb = __float2bfloat16(f);
    h = __bfloat16_as_ushort(hb);
    l = __bfloat16_as_ushort(__float2bfloat16(f - __bfloat162float(hb)));
}

#define LDSM4(r0, r1, r2, r3, addr) \
    asm volatile("ldmatrix.sync.aligned.m8n8.x4.shared.b16 {%0,%1,%2,%3}, [%4];" \
        : "=r"(r0), "=r"(r1), "=r"(r2), "=r"(r3) : "r"(addr))

#define MMA16816(d, a, b0, b1) \
    asm volatile("mma.sync.aligned.m16n8k16.row.col.f32.bf16.bf16.f32 " \
        "{%0,%1,%2,%3}, {%4,%5,%6,%7}, {%8,%9}, {%0,%1,%2,%3};" \
        : "+f"((d)[0]), "+f"((d)[1]), "+f"((d)[2]), "+f"((d)[3]) \
        : "r"((a)[0]), "r"((a)[1]), "r"((a)[2]), "r"((a)[3]), "r"(b0), "r"(b1))

#define CPA16(sa, ga) \
    asm volatile("cp.async.cg.shared.global [%0], [%1], 16;" :: "r"(sa), "l"(ga))
#define CPA_COMMIT() asm volatile("cp.async.commit_group;" ::: "memory")
#define CPA_WAIT1()  asm volatile("cp.async.wait_group 1;" ::: "memory")

// ---------------- split-bf16 tensor-core GEMM (R6/R9 form, best measured) ------
#define KC       32
#define ARR_B    8192
#define STAGE_B  (4 * ARR_B)
#define NSTAGE   3
#define DSMEM2   (NSTAGE * STAGE_B)

__global__ __launch_bounds__(256, 2)
void mma_gemm2(const bf16* __restrict__ Ahi, const bf16* __restrict__ Alo, int lda,
               const bf16* __restrict__ Bhi, const bf16* __restrict__ Blo, int ldb,
               const float* __restrict__ bias,
               const float* __restrict__ addsrc,
               float* __restrict__ Cf,
               bf16* __restrict__ Chi, bf16* __restrict__ Clo,
               int ldc, int K, int act,
               size_t zsA, size_t zsB, size_t zsC)
{
    extern __shared__ char sm[];
    const int tid  = threadIdx.x;
    const int lane = tid & 31;
    const int wid  = tid >> 5;
    const int wm   = wid >> 2;
    const int wn   = wid & 3;
    const int rowBase = blockIdx.y * 128;
    const int colBase = blockIdx.x * 128;
    const size_t zA = (size_t)blockIdx.z * zsA;
    const size_t zB = (size_t)blockIdx.z * zsB;
    const size_t zC = (size_t)blockIdx.z * zsC;
    const uint32_t smb = (uint32_t)__cvta_generic_to_shared(sm);

    const int crow = tid >> 2;
    const int cck  = tid & 3;
    const size_t offA0 = zA + (size_t)(rowBase + crow) * lda + cck * 8;
    const size_t offA1 = zA + (size_t)(rowBase + crow + 64) * lda + cck * 8;
    const size_t offB0 = zB + (size_t)(colBase + crow) * ldb + cck * 8;
    const size_t offB1 = zB + (size_t)(colBase + crow + 64) * ldb + cck * 8;
    const uint32_t s0 = (uint32_t)crow * 64        + (uint32_t)((cck ^ ((crow >> 1) & 3)) * 16);
    const uint32_t s1 = (uint32_t)(crow + 64) * 64 + (uint32_t)((cck ^ (((crow + 64) >> 1) & 3)) * 16);

    const int laneAr = (lane & 7) + ((lane >> 3) & 1) * 8;
    const int aCk    = (lane >> 4);
    const int laneBr = (lane & 7) + ((lane >> 4) & 1) * 8;
    const int bCk    = (lane >> 3) & 1;
    uint32_t aRowB[4], aSw[4], bRowB[2], bSw[2];
    #pragma unroll
    for (int i = 0; i < 4; i++) {
        int r = wm * 64 + i * 16 + laneAr;
        aRowB[i] = (uint32_t)r * 64;
        aSw[i]   = (uint32_t)((r >> 1) & 3);
    }
    #pragma unroll
    for (int p = 0; p < 2; p++) {
        int r = wn * 32 + p * 16 + laneBr;
        bRowB[p] = (uint32_t)r * 64;
        bSw[p]   = (uint32_t)((r >> 1) & 3);
    }

    float acc[16][4];
    #pragma unroll
    for (int i = 0; i < 16; i++)
        #pragma unroll
        for (int j = 0; j < 4; j++) acc[i][j] = 0.f;

    const int nk = K / KC;

    auto issue = [&](int stg, int kt) {
        const uint32_t sb = smb + (uint32_t)stg * STAGE_B;
        const size_t ko = (size_t)kt * KC;
        CPA16(sb + 0*ARR_B + s0, Ahi + offA0 + ko);
        CPA16(sb + 0*ARR_B + s1, Ahi + offA1 + ko);
        CPA16(sb + 1*ARR_B + s0, Alo + offA0 + ko);
        CPA16(sb + 1*ARR_B + s1, Alo + offA1 + ko);
        CPA16(sb + 2*ARR_B + s0, Bhi + offB0 + ko);
        CPA16(sb + 2*ARR_B + s1, Bhi + offB1 + ko);
        CPA16(sb + 3*ARR_B + s0, Blo + offB0 + ko);
        CPA16(sb + 3*ARR_B + s1, Blo + offB1 + ko);
    };

    issue(0, 0); CPA_COMMIT();
    issue(1, 1); CPA_COMMIT();

    int stg = 0;
    for (int kt = 0; kt < nk; kt++) {
        CPA_WAIT1();
        __syncthreads();
        if (kt + 2 < nk) issue((stg + 2) % NSTAGE, kt + 2);
        CPA_COMMIT();

        const uint32_t base = smb + (uint32_t)stg * STAGE_B;
        #pragma unroll
        for (int ks = 0; ks < 2; ks++) {
            uint32_t aH[4][4], aL[4][4], bH[2][4], bL[2][4];
            #pragma unroll
            for (int i = 0; i < 4; i++)
                LDSM4(aH[i][0], aH[i][1], aH[i][2], aH[i][3],
                      base + 0*ARR_B + aRowB[i] + (((uint32_t)(ks*2 + aCk) ^ aSw[i]) * 16));
            #pragma unroll
            for (int p = 0; p < 2; p++)
                LDSM4(bH[p][0], bH[p][1], bH[p][2], bH[p][3],
                      base + 2*ARR_B + bRowB[p] + (((uint32_t)(ks*2 + bCk) ^ bSw[p]) * 16));
            #pragma unroll
            for (int i = 0; i < 4; i++)
                #pragma unroll
                for (int nt = 0; nt < 4; nt++)
                    MMA16816(acc[i*4+nt], aH[i], bH[nt>>1][(nt&1)*2], bH[nt>>1][(nt&1)*2+1]);
            #pragma unroll
            for (int i = 0; i < 4; i++)
                LDSM4(aL[i][0], aL[i][1], aL[i][2], aL[i][3],
                      base + 1*ARR_B + aRowB[i] + (((uint32_t)(ks*2 + aCk) ^ aSw[i]) * 16));
            #pragma unroll
            for (int i = 0; i < 4; i++)
                #pragma unroll
                for (int nt = 0; nt < 4; nt++)
                    MMA16816(acc[i*4+nt], aL[i], bH[nt>>1][(nt&1)*2], bH[nt>>1][(nt&1)*2+1]);
            #pragma unroll
            for (int p = 0; p < 2; p++)
                LDSM4(bL[p][0], bL[p][1], bL[p][2], bL[p][3],
                      base + 3*ARR_B + bRowB[p] + (((uint32_t)(ks*2 + bCk) ^ bSw[p]) * 16));
            #pragma unroll
            for (int i = 0; i < 4; i++)
                #pragma unroll
                for (int nt = 0; nt < 4; nt++)
                    MMA16816(acc[i*4+nt], aH[i], bL[nt>>1][(nt&1)*2], bL[nt>>1][(nt&1)*2+1]);
        }
        stg = (stg + 1) % NSTAGE;
    }

    const int erow  = wm * 64 + (lane >> 2);
    const int ecol0 = wn * 32 + (lane & 3) * 2;
    #pragma unroll
    for (int i = 0; i < 4; i++) {
        int r0 = rowBase + erow + i * 16;
        int r1 = r0 + 8;
        #pragma unroll
        for (int nt = 0; nt < 4; nt++) {
            int c = colBase + ecol0 + nt * 8;
            float v0 = acc[i*4+nt][0], v1 = acc[i*4+nt][1];
            float v2 = acc[i*4+nt][2], v3 = acc[i*4+nt][3];
            if (bias) {
                float b0 = __ldg(&bias[c]), b1 = __ldg(&bias[c+1]);
                v0 += b0; v1 += b1; v2 += b0; v3 += b1;
            }
            if (act == 1) { v0 = siluf(v0); v1 = siluf(v1); v2 = siluf(v2); v3 = siluf(v3); }
            else if (act == 2) { v0 = softplusf(v0); v1 = softplusf(v1); v2 = softplusf(v2); v3 = softplusf(v3); }
            if (addsrc) {
                v0 += addsrc[(size_t)r0 * ldc + c];
                v1 += addsrc[(size_t)r0 * ldc + c + 1];
                v2 += addsrc[(size_t)r1 * ldc + c];
                v3 += addsrc[(size_t)r1 * ldc + c + 1];
            }
            if (Cf) {
                *(float2*)&Cf[zC + (size_t)r0 * ldc + c] = make_float2(v0, v1);
                *(float2*)&Cf[zC + (size_t)r1 * ldc + c] = make_float2(v2, v3);
            } else {
                unsigned short h0,h1,h2,h3,l0,l1,l2,l3;
                split1(v0, h0, l0); split1(v1, h1, l1);
                split1(v2, h2, l2); split1(v3, h3, l3);
                *(uint32_t*)(Chi + zC + (size_t)r0 * ldc + c) = (uint32_t)h0 | ((uint32_t)h1 << 16);
                *(uint32_t*)(Clo + zC + (size_t)r0 * ldc + c) = (uint32_t)l0 | ((uint32_t)l1 << 16);
                *(uint32_t*)(Chi + zC + (size_t)r1 * ldc + c) = (uint32_t)h2 | ((uint32_t)h3 << 16);
                *(uint32_t*)(Clo + zC + (size_t)r1 * ldc + c) = (uint32_t)l2 | ((uint32_t)l3 << 16);
            }
        }
    }
}

// ---------------- fp32 -> bf16 hi/lo split --------------------------------------
__global__ void split_kernel(const float* __restrict__ in,
                             bf16* __restrict__ hi,
                             bf16* __restrict__ lo, int n4)
{
    int i = blockIdx.x * blockDim.x + threadIdx.x;
    if (i >= n4) return;
    float4 v = ((const float4*)in)[i];
    unsigned short h0,h1,h2,h3,l0,l1,l2,l3;
    split1(v.x, h0, l0); split1(v.y, h1, l1);
    split1(v.z, h2, l2); split1(v.w, h3, l3);
    uint2 hu, lu;
    hu.x = (uint32_t)h0 | ((uint32_t)h1 << 16);
    hu.y = (uint32_t)h2 | ((uint32_t)h3 << 16);
    lu.x = (uint32_t)l0 | ((uint32_t)l1 << 16);
    lu.y = (uint32_t)l2 | ((uint32_t)l3 << 16);
    *(uint2*)(hi + (size_t)i * 4) = hu;
    *(uint2*)(lo + (size_t)i * 4) = lu;
}

// ---------------- xdbl GEMM: [2][ML][96], B/C interleaved in cols 64..95 --------
__global__ __launch_bounds__(128)
void xdbl_gemm(const float* __restrict__ xcA,
               const float* __restrict__ xw0,
               const float* __restrict__ xw1,
               float* __restrict__ out)
{
    __shared__ float As[16][36];
    __shared__ float Bs[16][100];
    const int dir = blockIdx.z;
    const float* A = xcA + (size_t)dir * ML * DIN + (size_t)blockIdx.x * 32 * DIN;
    const float* B = dir ? xw1 : xw0;
    float* C = out + (size_t)dir * ML * 96 + (size_t)blockIdx.x * 32 * 96;

    const int tid = threadIdx.x;
    const int tx = tid & 15, ty = tid >> 4;
    float acc[4][6];
    #pragma unroll
    for (int i = 0; i < 4; i++)
        #pragma unroll
        for (int j = 0; j < 6; j++) acc[i][j] = 0.f;

    const int ar = tid >> 2, akc = (tid & 3) * 4;

    for (int k0 = 0; k0 < DIN; k0 += 16) {
        {
            float4 v = *(const float4*)(A + (size_t)ar * DIN + k0 + akc);
            As[akc+0][ar] = v.x; As[akc+1][ar] = v.y;
            As[akc+2][ar] = v.z; As[akc+3][ar] = v.w;
        }
        #pragma unroll
        for (int j = 0; j < 3; j++) {
            int i = tid + j * 128;
            int n = i >> 2, kc = (i & 3) * 4;
            float4 v = *(const float4*)(B + (size_t)n * DIN + k0 + kc);
            Bs[kc+0][n] = v.x; Bs[kc+1][n] = v.y;
            Bs[kc+2][n] = v.z; Bs[kc+3][n] = v.w;
        }
        __syncthreads();
        #pragma unroll
        for (int kk = 0; kk < 16; kk++) {
            float4 a4 = *(const float4*)&As[kk][ty*4];
            float ar4[4] = {a4.x, a4.y, a4.z, a4.w};
            float2 b0 = *(const float2*)&Bs[kk][tx*6];
            float2 b1 = *(const float2*)&Bs[kk][tx*6+2];
            float2 b2 = *(const float2*)&Bs[kk][tx*6+4];
            float br[6] = {b0.x, b0.y, b1.x, b1.y, b2.x, b2.y};
            #pragma unroll
            for (int i = 0; i < 4; i++)
                #pragma unroll
                for (int j = 0; j < 6; j++)
                    acc[i][j] = fmaf(ar4[i], br[j], acc[i][j]);
        }
        __syncthreads();
    }
    #pragma unroll
    for (int i = 0; i < 4; i++)
        #pragma unroll
        for (int j = 0; j < 6; j++) {
            int c = tx*6 + j;
            int cw = (c < 64) ? c : ((c < 80) ? (64 + 2*(c - 64)) : (65 + 2*(c - 80)));
            C[(size_t)(ty*4+i) * 96 + cw] = acc[i][j];
        }
}

// ---------------- dt GEMM -> (dt, u) float2 pairs, float4 stores ----------------
__global__ __launch_bounds__(256)
void dt_gemm(const float* __restrict__ xdblA,
             const float* __restrict__ xcA,
             const float* __restrict__ w0, const float* __restrict__ w1,
             const float* __restrict__ b0, const float* __restrict__ b1,
             float* __restrict__ out)          // [2][ML][DIN][2]
{
    __shared__ float As[16][132];
    __shared__ float Bs[16][132];

    const int dir = blockIdx.z;
    const float* A = xdblA + (size_t)dir * ML * 96;
    const float* xcD = xcA + (size_t)dir * ML * DIN;
    const float* Bw = dir ? w1 : w0;
    const float* bias = dir ? b1 : b0;
    float* C = out + (size_t)dir * ML * DIN * 2;

    const int tid = threadIdx.x;
    const int tx = tid & 15;
    const int ty = tid >> 4;
    const int rowBase = blockIdx.y * 128;
    const int colBase = blockIdx.x * 128;

    const int lm = tid >> 1;
    const int lk = (tid & 1) * 8;

    const float* aPtr = A + (size_t)(rowBase + lm) * 96 + lk;
    const float* bPtr = Bw + (size_t)(colBase + lm) * RDT + lk;

    float acc[8][8];
    #pragma unroll
    for (int i = 0; i < 8; i++)
        #pragma unroll
        for (int j = 0; j < 8; j++) acc[i][j] = 0.f;

    for (int k0 = 0; k0 < RDT; k0 += 16) {
        float4 a0 = *(const float4*)(aPtr + k0);
        float4 a1 = *(const float4*)(aPtr + k0 + 4);
        float4 b0v = *(const float4*)(bPtr + k0);
        float4 b1v = *(const float4*)(bPtr + k0 + 4);

        As[lk+0][lm] = a0.x; As[lk+1][lm] = a0.y; As[lk+2][lm] = a0.z; As[lk+3][lm] = a0.w;
        As[lk+4][lm] = a1.x; As[lk+5][lm] = a1.y; As[lk+6][lm] = a1.z; As[lk+7][lm] = a1.w;
        Bs[lk+0][lm] = b0v.x; Bs[lk+1][lm] = b0v.y; Bs[lk+2][lm] = b0v.z; Bs[lk+3][lm] = b0v.w;
        Bs[lk+4][lm] = b1v.x; Bs[lk+5][lm] = b1v.y; Bs[lk+6][lm] = b1v.z; Bs[lk+7][lm] = b1v.w;
        __syncthreads();

        #pragma unroll
        for (int kk = 0; kk < 16; kk++) {
            float4 ra0 = *(const float4*)&As[kk][ty * 4];
            float4 ra1 = *(const float4*)&As[kk][64 + ty * 4];
            float4 rb0 = *(const float4*)&Bs[kk][tx * 4];
            float4 rb1 = *(const float4*)&Bs[kk][64 + tx * 4];
            float ar[8] = {ra0.x, ra0.y, ra0.z, ra0.w, ra1.x, ra1.y, ra1.z, ra1.w};
            float br[8] = {rb0.x, rb0.y, rb0.z, rb0.w, rb1.x, rb1.y, rb1.z, rb1.w};
            #pragma unroll
            for (int i = 0; i < 8; i++)
                #pragma unroll
                for (int j = 0; j < 8; j++)
                    acc[i][j] = fmaf(ar[i], br[j], acc[i][j]);
        }
        __syncthreads();
    }

    #pragma unroll
    for (int i = 0; i < 8; i++) {
        int r = rowBase + ((i < 4) ? (ty * 4 + i) : (64 + ty * 4 + i - 4));
        #pragma unroll
        for (int j = 0; j < 8; j += 2) {
            int c = colBase + ((j < 4) ? (tx * 4 + j) : (64 + tx * 4 + j - 4));
            float dt0 = softplusf(acc[i][j]   + bias[c]);
            float dt1 = softplusf(acc[i][j+1] + bias[c+1]);
            float2 uv = *(const float2*)&xcD[(size_t)r * DIN + c];
            float4 o = make_float4(dt0, uv.x, dt1, uv.y);
            *(float4*)&C[((size_t)r * DIN + c) * 2] = o;
        }
    }
}

// ---------------- depthwise causal conv, float4 over channels -------------------
__global__ void conv_kernel(const float* __restrict__ xz,
                            const float* __restrict__ cw0, const float* __restrict__ cw1,
                            const float* __restrict__ cb0, const float* __restrict__ cb1,
                            float* __restrict__ xc)
{
    int idx = blockIdx.x * blockDim.x + threadIdx.x;   // over (2*ML*DIN)/4
    if (idx >= 2 * ML * DIN / 4) return;
    int dir = idx >= ML * DIN / 4;
    int li = dir ? (idx - ML * DIN / 4) : idx;
    int c4 = li & (DIN / 4 - 1);          // channel group
    int r  = li / (DIN / 4);
    int l  = r & (LS - 1);
    int b  = r >> 11;
    int c  = c4 * 4;
    const float* cw = dir ? cw1 : cw0;
    const float* cb = dir ? cb1 : cb0;
    float4 w[4];
    #pragma unroll
    for (int q = 0; q < 4; q++) w[q] = *(const float4*)&cw[(c + q) * 4];
    float4 acc = *(const float4*)&cb[c];
    float* accp = &acc.x;

    const size_t colOff = (size_t)dir * 4096 + c;
    #pragma unroll
    for (int k = 0; k < 4; k++) {
        int lp = dir ? (l + 3 - k) : (l - 3 + k);
        bool ok = dir ? (lp < LS) : (lp >= 0);
        if (ok) {
            float4 xv = *(const float4*)&xz[(size_t)(b * LS + lp) * 8192 + colOff];
            const float* xp = &xv.x;
            #pragma unroll
            for (int q = 0; q < 4; q++) {
                float wt = (&w[q].x)[k];
                accp[q] = fmaf(xp[q], wt, accp[q]);
            }
        }
    }
    float4 o;
    o.x = siluf(acc.x); o.y = siluf(acc.y);
    o.z = siluf(acc.z); o.w = siluf(acc.w);
    *(float4*)&xc[(size_t)dir * ML * DIN + (size_t)r * DIN + c] = o;
}

// ---------------- selective scan: (dir,b,16d) blocks, smem-staged y out ---------
__global__ __launch_bounds__(256)
void scan_kernel(const float* __restrict__ dtu,   // [2][ML][DIN][2]
                 const float* __restrict__ xdbl,  // [2][ML][96] (B/C paired)
                 const float* __restrict__ xz,    // [ML][8192]
                 const float* __restrict__ A0, const float* __restrict__ A1,
                 const float* __restrict__ D0, const float* __restrict__ D1,
                 bf16* __restrict__ yhi, bf16* __restrict__ ylo)
{
    __shared__ unsigned short syh[32][16];
    __shared__ unsigned short syl[32][16];

    const int tid  = threadIdx.x;
    const int wid  = tid >> 5;
    const int lane = tid & 31;
    const int half = lane >> 4;
    const int s    = lane & 15;

    const int dg  = blockIdx.x & 127;
    const int b   = (blockIdx.x >> 7) & 1;
    const int dir = blockIdx.x >> 8;
    const int dloc = wid * 2 + half;       // 0..15
    const int d    = dg * 16 + dloc;

    const float* Alog = dir ? A1 : A0;
    const float Av = -__expf(Alog[d * DST + s]);
    const float Dd = (dir ? D1 : D0)[d];
    float h = 0.f;
    const bool w0lane = (s == 0);

    const size_t base = (size_t)b * LS;
    const int l0 = dir ? (LS - 1) : 0;
    const int step = dir ? -1 : 1;

    const float* pDtu = dtu + ((size_t)dir * ML * DIN + (base + l0) * DIN + d) * 2;
    const float* pBC  = xdbl + (size_t)dir * ML * 96 + (base + l0) * 96 + RDT + 2 * s;
    const float* pZ   = xz + (base + l0) * 8192 + (size_t)dir * 4096 + 2048 + d;
    const ptrdiff_t sDtu = (ptrdiff_t)step * DIN * 2;
    const ptrdiff_t sBC  = (ptrdiff_t)step * 96;
    const ptrdiff_t sZ   = (ptrdiff_t)step * 8192;
    const size_t yBase = (size_t)dir * ML * DIN + base * DIN;

    float2 du = *(const float2*)pDtu;
    float2 bc = *(const float2*)pBC;
    float zv  = w0lane ? *pZ : 0.f;

    for (int it = 0; it < LS; it++) {
        const bool more = (it + 1 < LS);
        float2 dun = more ? *(const float2*)(pDtu + sDtu) : du;
        float2 bcn = more ? *(const float2*)(pBC + sBC)   : bc;
        float zn   = (w0lane && more) ? *(pZ + sZ) : zv;

        h = h * __expf(du.x * Av) + du.x * du.y * bc.x;
        float y = h * bc.y;
        y += __shfl_xor_sync(0xffffffffu, y, 8);
        y += __shfl_xor_sync(0xffffffffu, y, 4);
        y += __shfl_xor_sync(0xffffffffu, y, 2);
        y += __shfl_xor_sync(0xffffffffu, y, 1);
        if (w0lane) {
            float yv = (y + du.y * Dd) * siluf(zv);
            __nv_bfloat16 hb = __float2bfloat16(yv);
            syh[it & 31][dloc] = __bfloat16_as_ushort(hb);
            syl[it & 31][dloc] =
                __bfloat16_as_ushort(__float2bfloat16(yv - __bfloat162float(hb)));
        }
        if ((it & 31) == 31) {
            __syncthreads();
            const int row = tid >> 3;
            const int cp  = tid & 7;
            const int itr = (it - 31) + row;
            const int gl  = l0 + step * itr;
            const size_t go = yBase + (size_t)gl * DIN + dg * 16 + 2 * cp;
            *(uint32_t*)(yhi + go) = *(const uint32_t*)&syh[row][2 * cp];
            *(uint32_t*)(ylo + go) = *(const uint32_t*)&syl[row][2 * cp];
            __syncthreads();
        }
        pDtu += sDtu; pBC += sBC; pZ += sZ;
        du = dun; bc = bcn; zv = zn;
    }
}

// ---------------- fused residual + layernorm -> xsum + bf16 hi/lo ----------------
__global__ void resln_kernel(const float* __restrict__ x,
                             const float* __restrict__ y0,
                             const float* __restrict__ y1,
                             const float* __restrict__ g,
                             const float* __restrict__ bta,
                             float* __restrict__ xsum,
                             bf16* __restrict__ outhi,
                             bf16* __restrict__ outlo)
{
    int row = blockIdx.x;
    size_t off4 = (size_t)row * (DM / 4) + threadIdx.x;
    float4 xv = ((const float4*)x)[off4];
    float4 a = ((const float4*)y0)[off4];
    float4 b = ((const float4*)y1)[off4];
    float4 v;
    v.x = xv.x + 0.5f * (a.x + b.x);
    v.y = xv.y + 0.5f * (a.y + b.y);
    v.z = xv.z + 0.5f * (a.z + b.z);
    v.w = xv.w + 0.5f * (a.w + b.w);
    ((float4*)xsum)[off4] = v;

    float s  = v.x + v.y + v.z + v.w;
    float sq = v.x*v.x + v.y*v.y + v.z*v.z + v.w*v.w;
    #pragma unroll
    for (int o = 16; o >= 1; o >>= 1) {
        s  += __shfl_xor_sync(0xffffffffu, s, o);
        sq += __shfl_xor_sync(0xffffffffu, sq, o);
    }
    __shared__ float ss[8], ssq[8];
    int warp = threadIdx.x >> 5, lane = threadIdx.x & 31;
    if (lane == 0) { ss[warp] = s; ssq[warp] = sq; }
    __syncthreads();
    __shared__ float sh_mean, sh_inv;
    if (threadIdx.x == 0) {
        float ts = 0.f, tq = 0.f;
        #pragma unroll
        for (int w = 0; w < 8; w++) { ts += ss[w]; tq += ssq[w]; }
        float mean = ts / DM;
        float var = tq / DM - mean * mean;
        sh_mean = mean;
        sh_inv = rsqrtf(var + 1e-5f);
    }
    __syncthreads();
    float mean = sh_mean, inv = sh_inv;
    float4 gv = ((const float4*)g)[threadIdx.x];
    float4 bv = ((const float4*)bta)[threadIdx.x];
    float o0 = (v.x - mean) * inv * gv.x + bv.x;
    float o1 = (v.y - mean) * inv * gv.y + bv.y;
    float o2 = (v.z - mean) * inv * gv.z + bv.z;
    float o3 = (v.w - mean) * inv * gv.w + bv.w;
    unsigned short h0,h1,h2,h3,l0,l1,l2,l3;
    split1(o0, h0, l0); split1(o1, h1, l1);
    split1(o2, h2, l2); split1(o3, h3, l3);
    uint2 hu, lu;
    hu.x = (uint32_t)h0 | ((uint32_t)h1 << 16);
    hu.y = (uint32_t)h2 | ((uint32_t)h3 << 16);
    lu.x = (uint32_t)l0 | ((uint32_t)l1 << 16);
    lu.y = (uint32_t)l2 | ((uint32_t)l3 << 16);
    size_t off = (size_t)row * DM + threadIdx.x * 4;
    *(uint2*)(outhi + off) = hu;
    *(uint2*)(outlo + off) = lu;
}

// ---------------- host orchestration ----------------------------------------------
extern "C" void kernel_launch(void* const* d_in, const int* in_sizes, int n_in,
                              void* d_out, int out_size)
{
    (void)in_sizes; (void)n_in; (void)out_size;

    const float* x = (const float*)d_in[0];
    const float* in_w[2]   = { (const float*)d_in[1],  (const float*)d_in[10] };
    const float* conv_w[2] = { (const float*)d_in[2],  (const float*)d_in[11] };
    const float* conv_b[2] = { (const float*)d_in[3],  (const float*)d_in[12] };
    const float* x_w[2]    = { (const float*)d_in[4],  (const float*)d_in[13] };
    const float* dt_w[2]   = { (const float*)d_in[5],  (const float*)d_in[14] };
    const float* dt_b[2]   = { (const float*)d_in[6],  (const float*)d_in[15] };
    const float* A_log[2]  = { (const float*)d_in[7],  (const float*)d_in[16] };
    const float* Dp[2]     = { (const float*)d_in[8],  (const float*)d_in[17] };
    const float* out_w[2]  = { (const float*)d_in[9],  (const float*)d_in[18] };
    const float* ff_ln_g = (const float*)d_in[19];
    const float* ff_ln_b = (const float*)d_in[20];
    const float* ff_w1   = (const float*)d_in[21];
    const float* ff_b1   = (const float*)d_in[22];
    const float* ff_w2   = (const float*)d_in[23];
    const float* ff_b2   = (const float*)d_in[24];

    float *xz, *xc, *xdbl, *dtu, *ydir, *xsum;
    bf16 *xhi, *xlo, *yhi, *ylo, *lnhi, *lnlo, *f1hi, *f1lo;
    bf16 *inwhi, *inwlo, *outwhi, *outwlo, *w1hi, *w1lo, *w2hi, *w2lo;
    cudaGetSymbolAddress((void**)&xz,   g_xz);
    cudaGetSymbolAddress((void**)&xc,   g_xc);
    cudaGetSymbolAddress((void**)&xdbl, g_xdbl);
    cudaGetSymbolAddress((void**)&dtu,  g_dtu);
    cudaGetSymbolAddress((void**)&ydir, g_ydir);
    cudaGetSymbolAddress((void**)&xsum, g_xsum);
    cudaGetSymbolAddress((void**)&xhi,  g_xhi);
    cudaGetSymbolAddress((void**)&xlo,  g_xlo);
    cudaGetSymbolAddress((void**)&yhi,  g_yhi);
    cudaGetSymbolAddress((void**)&ylo,  g_ylo);
    cudaGetSymbolAddress((void**)&lnhi, g_lnhi);
    cudaGetSymbolAddress((void**)&lnlo, g_lnlo);
    cudaGetSymbolAddress((void**)&f1hi, g_f1hi);
    cudaGetSymbolAddress((void**)&f1lo, g_f1lo);
    cudaGetSymbolAddress((void**)&inwhi,  g_inwhi);
    cudaGetSymbolAddress((void**)&inwlo,  g_inwlo);
    cudaGetSymbolAddress((void**)&outwhi, g_outwhi);
    cudaGetSymbolAddress((void**)&outwlo, g_outwlo);
    cudaGetSymbolAddress((void**)&w1hi, g_w1hi);
    cudaGetSymbolAddress((void**)&w1lo, g_w1lo);
    cudaGetSymbolAddress((void**)&w2hi, g_w2hi);
    cudaGetSymbolAddress((void**)&w2lo, g_w2lo);

    cudaFuncSetAttribute(mma_gemm2, cudaFuncAttributeMaxDynamicSharedMemorySize, DSMEM2);

    const size_t szXC   = (size_t)ML * DIN;
    const size_t szYDIR = (size_t)ML * DM;
    const size_t szINW  = (size_t)2 * DIN * DM;
    const size_t szOUTW = (size_t)DM * DIN;

    dim3 blk(256);

    // idx 0-2: splits needed for in-proj
    split_kernel<<<(ML*DM/4 + 255)/256, blk>>>(x, xhi, xlo, ML*DM/4);
    split_kernel<<<((int)szINW/4 + 255)/256, blk>>>(in_w[0], inwhi,         inwlo,         (int)szINW/4);
    split_kernel<<<((int)szINW/4 + 255)/256, blk>>>(in_w[1], inwhi + szINW, inwlo + szINW, (int)szINW/4);

    // idx 3 (profiled): merged in-proj, M=4096, N=8192, K=1024
    mma_gemm2<<<dim3(64, 32, 1), blk, DSMEM2>>>(
        xhi, xlo, DM, inwhi, inwlo, DM,
        nullptr, nullptr, xz, nullptr, nullptr,
        8192, DM, 0, 0, 0, 0);

    // remaining splits
    split_kernel<<<(DFF*DM/4 + 255)/256, blk>>>(ff_w1, w1hi, w1lo, DFF*DM/4);
    split_kernel<<<((int)szOUTW/4 + 255)/256, blk>>>(out_w[0], outwhi,          outwlo,          (int)szOUTW/4);
    split_kernel<<<((int)szOUTW/4 + 255)/256, blk>>>(out_w[1], outwhi + szOUTW, outwlo + szOUTW, (int)szOUTW/4);
    split_kernel<<<(DM*DFF/4 + 255)/256, blk>>>(ff_w2, w2hi, w2lo, DM*DFF/4);

    // conv (both dirs), float4 over channels
    conv_kernel<<<(2*ML*DIN/4 + 255)/256, blk>>>(xz, conv_w[0], conv_w[1],
                                                 conv_b[0], conv_b[1], xc);

    // xdbl (both dirs), B/C interleaved
    xdbl_gemm<<<dim3(ML/32, 1, 2), dim3(128)>>>(xc, x_w[0], x_w[1], xdbl);

    // dt (both dirs) -> (dt, u) pairs
    dt_gemm<<<dim3(DIN/128, ML/128, 2), blk>>>(xdbl, xc, dt_w[0], dt_w[1],
                                               dt_b[0], dt_b[1], dtu);

    // scan (both dirs): 512 blocks = 2 dir x 2 b x 128 d-groups
    scan_kernel<<<512, blk>>>(dtu, xdbl, xz, A_log[0], A_log[1],
                              Dp[0], Dp[1], yhi, ylo);

    // out-proj (both dirs via z)
    mma_gemm2<<<dim3(8, 32, 2), blk, DSMEM2>>>(
        yhi, ylo, DIN, outwhi, outwlo, DIN,
        nullptr, nullptr, ydir, nullptr, nullptr,
        DM, DIN, 0, szXC, szOUTW, szYDIR);

    // fused residual + LN
    resln_kernel<<<ML, blk>>>(x, ydir, ydir + szYDIR, ff_ln_g, ff_ln_b,
                              xsum, lnhi, lnlo);

    // ff1 = silu(ln @ ff_w1^T + b1) -> bf16 hi/lo
    mma_gemm2<<<dim3(32, 32, 1), blk, DSMEM2>>>(
        lnhi, lnlo, DM, w1hi, w1lo, DM,
        ff_b1, nullptr, nullptr, f1hi, f1lo,
        DFF, DM, 1, 0, 0, 0);

    // out = xsum + (ff1 @ ff_w2^T + b2)
    mma_gemm2<<<dim3(8, 32, 1), blk, DSMEM2>>>(
        f1hi, f1lo, DFF, w2hi, w2lo, DFF,
        ff_b2, xsum, (float*)d_out, nullptr, nullptr,
        DM, DFF, 0, 0, 0, 0);
}

// round 13
// speedup vs baseline: 1.4702x; 1.1506x over previous
#include <cuda_runtime.h>
#include <cuda_fp16.h>
#include <math.h>
#include <stdint.h>

// Problem constants
#define BB   2
#define LS   2048
#define DM   1024
#define DIN  2048
#define DST  16
#define RDT  64
#define ML   (BB*LS)      // 4096 rows
#define DFF  (4*DM)       // 4096

typedef __half fp16;

// ---------------- scratch (device globals) -----------------------------------
// xz unified: [ML][8192], cols [dir*4096 .. +2047]=xi, [+2048..+4095]=z
__device__ __align__(256) float g_xz  [(size_t)ML * 8192];
__device__ __align__(256) float g_xc  [2u * ML * DIN];
__device__ __align__(256) float g_xdbl[2u * ML * 96];     // cols 64..95: B/C interleaved
__device__ __align__(256) float g_dtu [2u * (size_t)ML * DIN * 2];  // (dt, u) pairs
__device__ __align__(256) float g_ydir[2u * ML * DM];
__device__ __align__(256) float g_xsum[(size_t)ML * DM];

__device__ __align__(256) fp16 g_xhi [(size_t)ML * DM],  g_xlo [(size_t)ML * DM];
__device__ __align__(256) fp16 g_yhi [2u * ML * DIN],    g_ylo [2u * ML * DIN];
__device__ __align__(256) fp16 g_lnhi[(size_t)ML * DM],  g_lnlo[(size_t)ML * DM];
__device__ __align__(256) fp16 g_f1hi[(size_t)ML * DFF], g_f1lo[(size_t)ML * DFF];
__device__ __align__(256) fp16 g_inw16 [2u * 2 * DIN * DM];
__device__ __align__(256) fp16 g_outw16[2u * DM * DIN];
__device__ __align__(256) fp16 g_w116[(size_t)DFF * DM];
__device__ __align__(256) fp16 g_w216[(size_t)DM * DFF];

// ---------------- helpers ------------------------------------------------------
__device__ __forceinline__ float siluf(float v) { return v / (1.f + __expf(-v)); }
__device__ __forceinline__ float softplusf(float v) {
    return (v > 20.f) ? v : log1pf(__expf(v));
}
__device__ __forceinline__ void split1h(float f, unsigned short& h, unsigned short& l) {
    __half hb = __float2half_rn(f);
    h = __half_as_ushort(hb);
    l = __half_as_ushort(__float2half_rn(f - __half2float(hb)));
}

#define LDSM4(r0, r1, r2, r3, addr) \
    asm volatile("ldmatrix.sync.aligned.m8n8.x4.shared.b16 {%0,%1,%2,%3}, [%4];" \
        : "=r"(r0), "=r"(r1), "=r"(r2), "=r"(r3) : "r"(addr))

#define MMAF16(d, a, b0, b1) \
    asm volatile("mma.sync.aligned.m16n8k16.row.col.f32.f16.f16.f32 " \
        "{%0,%1,%2,%3}, {%4,%5,%6,%7}, {%8,%9}, {%0,%1,%2,%3};" \
        : "+f"((d)[0]), "+f"((d)[1]), "+f"((d)[2]), "+f"((d)[3]) \
        : "r"((a)[0]), "r"((a)[1]), "r"((a)[2]), "r"((a)[3]), "r"(b0), "r"(b1))

#define CPA16(sa, ga) \
    asm volatile("cp.async.cg.shared.global [%0], [%1], 16;" :: "r"(sa), "l"(ga))
#define CPA_COMMIT() asm volatile("cp.async.commit_group;" ::: "memory")
#define CPA_WAIT1()  asm volatile("cp.async.wait_group 1;" ::: "memory")

// ---------------- fp16 2-product tensor-core GEMM ------------------------------
// C[M,N] = A[M,K] * B[N,K]^T, A as fp16 hi/lo, B single fp16.
// 128x128 tiles, KC=16x2, 3-stage cp.async, 8 warps (2Mx4N).
#define KC       32
#define ARR_B    8192                  // one [128][32] fp16 array
#define STAGE_B  (3 * ARR_B)           // Ahi, Alo, B = 24KB
#define NSTAGE   3
#define DSMEM2   (NSTAGE * STAGE_B)    // 73728 B

__global__ __launch_bounds__(256, 2)
void mma_gemm2(const fp16* __restrict__ Ahi, const fp16* __restrict__ Alo, int lda,
               const fp16* __restrict__ Bf, int ldb,
               const float* __restrict__ bias,
               const float* __restrict__ addsrc,
               float* __restrict__ Cf,
               fp16* __restrict__ Chi, fp16* __restrict__ Clo,
               int ldc, int K, int act,
               size_t zsA, size_t zsB, size_t zsC)
{
    extern __shared__ char sm[];
    const int tid  = threadIdx.x;
    const int lane = tid & 31;
    const int wid  = tid >> 5;
    const int wm   = wid >> 2;
    const int wn   = wid & 3;
    const int rowBase = blockIdx.y * 128;
    const int colBase = blockIdx.x * 128;
    const size_t zA = (size_t)blockIdx.z * zsA;
    const size_t zB = (size_t)blockIdx.z * zsB;
    const size_t zC = (size_t)blockIdx.z * zsC;
    const uint32_t smb = (uint32_t)__cvta_generic_to_shared(sm);

    const int crow = tid >> 2;
    const int cck  = tid & 3;
    const size_t offA0 = zA + (size_t)(rowBase + crow) * lda + cck * 8;
    const size_t offA1 = zA + (size_t)(rowBase + crow + 64) * lda + cck * 8;
    const size_t offB0 = zB + (size_t)(colBase + crow) * ldb + cck * 8;
    const size_t offB1 = zB + (size_t)(colBase + crow + 64) * ldb + cck * 8;
    const uint32_t s0 = (uint32_t)crow * 64        + (uint32_t)((cck ^ ((crow >> 1) & 3)) * 16);
    const uint32_t s1 = (uint32_t)(crow + 64) * 64 + (uint32_t)((cck ^ (((crow + 64) >> 1) & 3)) * 16);

    const int laneAr = (lane & 7) + ((lane >> 3) & 1) * 8;
    const int aCk    = (lane >> 4);
    const int laneBr = (lane & 7) + ((lane >> 4) & 1) * 8;
    const int bCk    = (lane >> 3) & 1;
    uint32_t aRowB[4], aSw[4], bRowB[2], bSw[2];
    #pragma unroll
    for (int i = 0; i < 4; i++) {
        int r = wm * 64 + i * 16 + laneAr;
        aRowB[i] = (uint32_t)r * 64;
        aSw[i]   = (uint32_t)((r >> 1) & 3);
    }
    #pragma unroll
    for (int p = 0; p < 2; p++) {
        int r = wn * 32 + p * 16 + laneBr;
        bRowB[p] = (uint32_t)r * 64;
        bSw[p]   = (uint32_t)((r >> 1) & 3);
    }

    float acc[16][4];
    #pragma unroll
    for (int i = 0; i < 16; i++)
        #pragma unroll
        for (int j = 0; j < 4; j++) acc[i][j] = 0.f;

    const int nk = K / KC;

    auto issue = [&](int stg, int kt) {
        const uint32_t sb = smb + (uint32_t)stg * STAGE_B;
        const size_t ko = (size_t)kt * KC;
        CPA16(sb + 0*ARR_B + s0, Ahi + offA0 + ko);
        CPA16(sb + 0*ARR_B + s1, Ahi + offA1 + ko);
        CPA16(sb + 1*ARR_B + s0, Alo + offA0 + ko);
        CPA16(sb + 1*ARR_B + s1, Alo + offA1 + ko);
        CPA16(sb + 2*ARR_B + s0, Bf + offB0 + ko);
        CPA16(sb + 2*ARR_B + s1, Bf + offB1 + ko);
    };

    issue(0, 0); CPA_COMMIT();
    issue(1, 1); CPA_COMMIT();

    int stg = 0;
    for (int kt = 0; kt < nk; kt++) {
        CPA_WAIT1();
        __syncthreads();
        if (kt + 2 < nk) issue((stg + 2) % NSTAGE, kt + 2);
        CPA_COMMIT();

        const uint32_t base = smb + (uint32_t)stg * STAGE_B;
        #pragma unroll
        for (int ks = 0; ks < 2; ks++) {
            uint32_t aH[4][4], aL[4][4], bF[2][4];
            #pragma unroll
            for (int i = 0; i < 4; i++)
                LDSM4(aH[i][0], aH[i][1], aH[i][2], aH[i][3],
                      base + 0*ARR_B + aRowB[i] + (((uint32_t)(ks*2 + aCk) ^ aSw[i]) * 16));
            #pragma unroll
            for (int p = 0; p < 2; p++)
                LDSM4(bF[p][0], bF[p][1], bF[p][2], bF[p][3],
                      base + 2*ARR_B + bRowB[p] + (((uint32_t)(ks*2 + bCk) ^ bSw[p]) * 16));
            #pragma unroll
            for (int i = 0; i < 4; i++)
                #pragma unroll
                for (int nt = 0; nt < 4; nt++)
                    MMAF16(acc[i*4+nt], aH[i], bF[nt>>1][(nt&1)*2], bF[nt>>1][(nt&1)*2+1]);
            #pragma unroll
            for (int i = 0; i < 4; i++)
                LDSM4(aL[i][0], aL[i][1], aL[i][2], aL[i][3],
                      base + 1*ARR_B + aRowB[i] + (((uint32_t)(ks*2 + aCk) ^ aSw[i]) * 16));
            #pragma unroll
            for (int i = 0; i < 4; i++)
                #pragma unroll
                for (int nt = 0; nt < 4; nt++)
                    MMAF16(acc[i*4+nt], aL[i], bF[nt>>1][(nt&1)*2], bF[nt>>1][(nt&1)*2+1]);
        }
        stg = (stg + 1) % NSTAGE;
    }

    const int erow  = wm * 64 + (lane >> 2);
    const int ecol0 = wn * 32 + (lane & 3) * 2;
    #pragma unroll
    for (int i = 0; i < 4; i++) {
        int r0 = rowBase + erow + i * 16;
        int r1 = r0 + 8;
        #pragma unroll
        for (int nt = 0; nt < 4; nt++) {
            int c = colBase + ecol0 + nt * 8;
            float v0 = acc[i*4+nt][0], v1 = acc[i*4+nt][1];
            float v2 = acc[i*4+nt][2], v3 = acc[i*4+nt][3];
            if (bias) {
                float b0 = __ldg(&bias[c]), b1 = __ldg(&bias[c+1]);
                v0 += b0; v1 += b1; v2 += b0; v3 += b1;
            }
            if (act == 1) { v0 = siluf(v0); v1 = siluf(v1); v2 = siluf(v2); v3 = siluf(v3); }
            else if (act == 2) { v0 = softplusf(v0); v1 = softplusf(v1); v2 = softplusf(v2); v3 = softplusf(v3); }
            if (addsrc) {
                v0 += addsrc[(size_t)r0 * ldc + c];
                v1 += addsrc[(size_t)r0 * ldc + c + 1];
                v2 += addsrc[(size_t)r1 * ldc + c];
                v3 += addsrc[(size_t)r1 * ldc + c + 1];
            }
            if (Cf) {
                *(float2*)&Cf[zC + (size_t)r0 * ldc + c] = make_float2(v0, v1);
                *(float2*)&Cf[zC + (size_t)r1 * ldc + c] = make_float2(v2, v3);
            } else {
                unsigned short h0,h1,h2,h3,l0,l1,l2,l3;
                split1h(v0, h0, l0); split1h(v1, h1, l1);
                split1h(v2, h2, l2); split1h(v3, h3, l3);
                *(uint32_t*)(Chi + zC + (size_t)r0 * ldc + c) = (uint32_t)h0 | ((uint32_t)h1 << 16);
                *(uint32_t*)(Clo + zC + (size_t)r0 * ldc + c) = (uint32_t)l0 | ((uint32_t)l1 << 16);
                *(uint32_t*)(Chi + zC + (size_t)r1 * ldc + c) = (uint32_t)h2 | ((uint32_t)h3 << 16);
                *(uint32_t*)(Clo + zC + (size_t)r1 * ldc + c) = (uint32_t)l2 | ((uint32_t)l3 << 16);
            }
        }
    }
}

// ---------------- fp32 -> fp16 hi/lo split (activations) -------------------------
__global__ void split_kernel(const float* __restrict__ in,
                             fp16* __restrict__ hi,
                             fp16* __restrict__ lo, int n4)
{
    int i = blockIdx.x * blockDim.x + threadIdx.x;
    if (i >= n4) return;
    float4 v = ((const float4*)in)[i];
    unsigned short h0,h1,h2,h3,l0,l1,l2,l3;
    split1h(v.x, h0, l0); split1h(v.y, h1, l1);
    split1h(v.z, h2, l2); split1h(v.w, h3, l3);
    uint2 hu, lu;
    hu.x = (uint32_t)h0 | ((uint32_t)h1 << 16);
    hu.y = (uint32_t)h2 | ((uint32_t)h3 << 16);
    lu.x = (uint32_t)l0 | ((uint32_t)l1 << 16);
    lu.y = (uint32_t)l2 | ((uint32_t)l3 << 16);
    *(uint2*)(hi + (size_t)i * 4) = hu;
    *(uint2*)(lo + (size_t)i * 4) = lu;
}

// ---------------- fp32 -> fp16 convert (weights) ---------------------------------
__global__ void wcvt_kernel(const float* __restrict__ in,
                            fp16* __restrict__ out, int n4)
{
    int i = blockIdx.x * blockDim.x + threadIdx.x;
    if (i >= n4) return;
    float4 v = ((const float4*)in)[i];
    uint2 u;
    u.x = (uint32_t)__half_as_ushort(__float2half_rn(v.x)) |
          ((uint32_t)__half_as_ushort(__float2half_rn(v.y)) << 16);
    u.y = (uint32_t)__half_as_ushort(__float2half_rn(v.z)) |
          ((uint32_t)__half_as_ushort(__float2half_rn(v.w)) << 16);
    *(uint2*)(out + (size_t)i * 4) = u;
}

// ---------------- xdbl GEMM: [2][ML][96], B/C interleaved in cols 64..95 --------
__global__ __launch_bounds__(128)
void xdbl_gemm(const float* __restrict__ xcA,
               const float* __restrict__ xw0,
               const float* __restrict__ xw1,
               float* __restrict__ out)
{
    __shared__ float As[16][36];
    __shared__ float Bs[16][100];
    const int dir = blockIdx.z;
    const float* A = xcA + (size_t)dir * ML * DIN + (size_t)blockIdx.x * 32 * DIN;
    const float* B = dir ? xw1 : xw0;
    float* C = out + (size_t)dir * ML * 96 + (size_t)blockIdx.x * 32 * 96;

    const int tid = threadIdx.x;
    const int tx = tid & 15, ty = tid >> 4;
    float acc[4][6];
    #pragma unroll
    for (int i = 0; i < 4; i++)
        #pragma unroll
        for (int j = 0; j < 6; j++) acc[i][j] = 0.f;

    const int ar = tid >> 2, akc = (tid & 3) * 4;

    for (int k0 = 0; k0 < DIN; k0 += 16) {
        {
            float4 v = *(const float4*)(A + (size_t)ar * DIN + k0 + akc);
            As[akc+0][ar] = v.x; As[akc+1][ar] = v.y;
            As[akc+2][ar] = v.z; As[akc+3][ar] = v.w;
        }
        #pragma unroll
        for (int j = 0; j < 3; j++) {
            int i = tid + j * 128;
            int n = i >> 2, kc = (i & 3) * 4;
            float4 v = *(const float4*)(B + (size_t)n * DIN + k0 + kc);
            Bs[kc+0][n] = v.x; Bs[kc+1][n] = v.y;
            Bs[kc+2][n] = v.z; Bs[kc+3][n] = v.w;
        }
        __syncthreads();
        #pragma unroll
        for (int kk = 0; kk < 16; kk++) {
            float4 a4 = *(const float4*)&As[kk][ty*4];
            float ar4[4] = {a4.x, a4.y, a4.z, a4.w};
            float2 b0 = *(const float2*)&Bs[kk][tx*6];
            float2 b1 = *(const float2*)&Bs[kk][tx*6+2];
            float2 b2 = *(const float2*)&Bs[kk][tx*6+4];
            float br[6] = {b0.x, b0.y, b1.x, b1.y, b2.x, b2.y};
            #pragma unroll
            for (int i = 0; i < 4; i++)
                #pragma unroll
                for (int j = 0; j < 6; j++)
                    acc[i][j] = fmaf(ar4[i], br[j], acc[i][j]);
        }
        __syncthreads();
    }
    #pragma unroll
    for (int i = 0; i < 4; i++)
        #pragma unroll
        for (int j = 0; j < 6; j++) {
            int c = tx*6 + j;
            int cw = (c < 64) ? c : ((c < 80) ? (64 + 2*(c - 64)) : (65 + 2*(c - 80)));
            C[(size_t)(ty*4+i) * 96 + cw] = acc[i][j];
        }
}

// ---------------- dt GEMM -> (dt, u) float2 pairs, float4 stores ----------------
__global__ __launch_bounds__(256)
void dt_gemm(const float* __restrict__ xdblA,
             const float* __restrict__ xcA,
             const float* __restrict__ w0, const float* __restrict__ w1,
             const float* __restrict__ b0, const float* __restrict__ b1,
             float* __restrict__ out)          // [2][ML][DIN][2]
{
    __shared__ float As[16][132];
    __shared__ float Bs[16][132];

    const int dir = blockIdx.z;
    const float* A = xdblA + (size_t)dir * ML * 96;
    const float* xcD = xcA + (size_t)dir * ML * DIN;
    const float* Bw = dir ? w1 : w0;
    const float* bias = dir ? b1 : b0;
    float* C = out + (size_t)dir * ML * DIN * 2;

    const int tid = threadIdx.x;
    const int tx = tid & 15;
    const int ty = tid >> 4;
    const int rowBase = blockIdx.y * 128;
    const int colBase = blockIdx.x * 128;

    const int lm = tid >> 1;
    const int lk = (tid & 1) * 8;

    const float* aPtr = A + (size_t)(rowBase + lm) * 96 + lk;
    const float* bPtr = Bw + (size_t)(colBase + lm) * RDT + lk;

    float acc[8][8];
    #pragma unroll
    for (int i = 0; i < 8; i++)
        #pragma unroll
        for (int j = 0; j < 8; j++) acc[i][j] = 0.f;

    for (int k0 = 0; k0 < RDT; k0 += 16) {
        float4 a0 = *(const float4*)(aPtr + k0);
        float4 a1 = *(const float4*)(aPtr + k0 + 4);
        float4 b0v = *(const float4*)(bPtr + k0);
        float4 b1v = *(const float4*)(bPtr + k0 + 4);

        As[lk+0][lm] = a0.x; As[lk+1][lm] = a0.y; As[lk+2][lm] = a0.z; As[lk+3][lm] = a0.w;
        As[lk+4][lm] = a1.x; As[lk+5][lm] = a1.y; As[lk+6][lm] = a1.z; As[lk+7][lm] = a1.w;
        Bs[lk+0][lm] = b0v.x; Bs[lk+1][lm] = b0v.y; Bs[lk+2][lm] = b0v.z; Bs[lk+3][lm] = b0v.w;
        Bs[lk+4][lm] = b1v.x; Bs[lk+5][lm] = b1v.y; Bs[lk+6][lm] = b1v.z; Bs[lk+7][lm] = b1v.w;
        __syncthreads();

        #pragma unroll
        for (int kk = 0; kk < 16; kk++) {
            float4 ra0 = *(const float4*)&As[kk][ty * 4];
            float4 ra1 = *(const float4*)&As[kk][64 + ty * 4];
            float4 rb0 = *(const float4*)&Bs[kk][tx * 4];
            float4 rb1 = *(const float4*)&Bs[kk][64 + tx * 4];
            float ar[8] = {ra0.x, ra0.y, ra0.z, ra0.w, ra1.x, ra1.y, ra1.z, ra1.w};
            float br[8] = {rb0.x, rb0.y, rb0.z, rb0.w, rb1.x, rb1.y, rb1.z, rb1.w};
            #pragma unroll
            for (int i = 0; i < 8; i++)
                #pragma unroll
                for (int j = 0; j < 8; j++)
                    acc[i][j] = fmaf(ar[i], br[j], acc[i][j]);
        }
        __syncthreads();
    }

    #pragma unroll
    for (int i = 0; i < 8; i++) {
        int r = rowBase + ((i < 4) ? (ty * 4 + i) : (64 + ty * 4 + i - 4));
        #pragma unroll
        for (int j = 0; j < 8; j += 2) {
            int c = colBase + ((j < 4) ? (tx * 4 + j) : (64 + tx * 4 + j - 4));
            float dt0 = softplusf(acc[i][j]   + bias[c]);
            float dt1 = softplusf(acc[i][j+1] + bias[c+1]);
            float2 uv = *(const float2*)&xcD[(size_t)r * DIN + c];
            float4 o = make_float4(dt0, uv.x, dt1, uv.y);
            *(float4*)&C[((size_t)r * DIN + c) * 2] = o;
        }
    }
}

// ---------------- depthwise causal conv, float4 over channels -------------------
__global__ void conv_kernel(const float* __restrict__ xz,
                            const float* __restrict__ cw0, const float* __restrict__ cw1,
                            const float* __restrict__ cb0, const float* __restrict__ cb1,
                            float* __restrict__ xc)
{
    int idx = blockIdx.x * blockDim.x + threadIdx.x;
    if (idx >= 2 * ML * DIN / 4) return;
    int dir = idx >= ML * DIN / 4;
    int li = dir ? (idx - ML * DIN / 4) : idx;
    int c4 = li & (DIN / 4 - 1);
    int r  = li / (DIN / 4);
    int l  = r & (LS - 1);
    int b  = r >> 11;
    int c  = c4 * 4;
    const float* cw = dir ? cw1 : cw0;
    const float* cb = dir ? cb1 : cb0;
    float4 w[4];
    #pragma unroll
    for (int q = 0; q < 4; q++) w[q] = *(const float4*)&cw[(c + q) * 4];
    float4 acc = *(const float4*)&cb[c];
    float* accp = &acc.x;

    const size_t colOff = (size_t)dir * 4096 + c;
    #pragma unroll
    for (int k = 0; k < 4; k++) {
        int lp = dir ? (l + 3 - k) : (l - 3 + k);
        bool ok = dir ? (lp < LS) : (lp >= 0);
        if (ok) {
            float4 xv = *(const float4*)&xz[(size_t)(b * LS + lp) * 8192 + colOff];
            const float* xp = &xv.x;
            #pragma unroll
            for (int q = 0; q < 4; q++) {
                float wt = (&w[q].x)[k];
                accp[q] = fmaf(xp[q], wt, accp[q]);
            }
        }
    }
    float4 o;
    o.x = siluf(acc.x); o.y = siluf(acc.y);
    o.z = siluf(acc.z); o.w = siluf(acc.w);
    *(float4*)&xc[(size_t)dir * ML * DIN + (size_t)r * DIN + c] = o;
}

// ---------------- selective scan: (dir,b,16d) blocks, smem-staged y out ---------
__global__ __launch_bounds__(256)
void scan_kernel(const float* __restrict__ dtu,
                 const float* __restrict__ xdbl,
                 const float* __restrict__ xz,
                 const float* __restrict__ A0, const float* __restrict__ A1,
                 const float* __restrict__ D0, const float* __restrict__ D1,
                 fp16* __restrict__ yhi, fp16* __restrict__ ylo)
{
    __shared__ unsigned short syh[32][16];
    __shared__ unsigned short syl[32][16];

    const int tid  = threadIdx.x;
    const int wid  = tid >> 5;
    const int lane = tid & 31;
    const int half = lane >> 4;
    const int s    = lane & 15;

    const int dg  = blockIdx.x & 127;
    const int b   = (blockIdx.x >> 7) & 1;
    const int dir = blockIdx.x >> 8;
    const int dloc = wid * 2 + half;
    const int d    = dg * 16 + dloc;

    const float* Alog = dir ? A1 : A0;
    const float Av = -__expf(Alog[d * DST + s]);
    const float Dd = (dir ? D1 : D0)[d];
    float h = 0.f;
    const bool w0lane = (s == 0);

    const size_t base = (size_t)b * LS;
    const int l0 = dir ? (LS - 1) : 0;
    const int step = dir ? -1 : 1;

    const float* pDtu = dtu + ((size_t)dir * ML * DIN + (base + l0) * DIN + d) * 2;
    const float* pBC  = xdbl + (size_t)dir * ML * 96 + (base + l0) * 96 + RDT + 2 * s;
    const float* pZ   = xz + (base + l0) * 8192 + (size_t)dir * 4096 + 2048 + d;
    const ptrdiff_t sDtu = (ptrdiff_t)step * DIN * 2;
    const ptrdiff_t sBC  = (ptrdiff_t)step * 96;
    const ptrdiff_t sZ   = (ptrdiff_t)step * 8192;
    const size_t yBase = (size_t)dir * ML * DIN + base * DIN;

    float2 du = *(const float2*)pDtu;
    float2 bc = *(const float2*)pBC;
    float zv  = w0lane ? *pZ : 0.f;

    for (int it = 0; it < LS; it++) {
        const bool more = (it + 1 < LS);
        float2 dun = more ? *(const float2*)(pDtu + sDtu) : du;
        float2 bcn = more ? *(const float2*)(pBC + sBC)   : bc;
        float zn   = (w0lane && more) ? *(pZ + sZ) : zv;

        h = h * __expf(du.x * Av) + du.x * du.y * bc.x;
        float y = h * bc.y;
        y += __shfl_xor_sync(0xffffffffu, y, 8);
        y += __shfl_xor_sync(0xffffffffu, y, 4);
        y += __shfl_xor_sync(0xffffffffu, y, 2);
        y += __shfl_xor_sync(0xffffffffu, y, 1);
        if (w0lane) {
            float yv = (y + du.y * Dd) * siluf(zv);
            unsigned short hh, ll;
            split1h(yv, hh, ll);
            syh[it & 31][dloc] = hh;
            syl[it & 31][dloc] = ll;
        }
        if ((it & 31) == 31) {
            __syncthreads();
            const int row = tid >> 3;
            const int cp  = tid & 7;
            const int itr = (it - 31) + row;
            const int gl  = l0 + step * itr;
            const size_t go = yBase + (size_t)gl * DIN + dg * 16 + 2 * cp;
            *(uint32_t*)(yhi + go) = *(const uint32_t*)&syh[row][2 * cp];
            *(uint32_t*)(ylo + go) = *(const uint32_t*)&syl[row][2 * cp];
            __syncthreads();
        }
        pDtu += sDtu; pBC += sBC; pZ += sZ;
        du = dun; bc = bcn; zv = zn;
    }
}

// ---------------- fused residual + layernorm -> xsum + fp16 hi/lo ----------------
__global__ void resln_kernel(const float* __restrict__ x,
                             const float* __restrict__ y0,
                             const float* __restrict__ y1,
                             const float* __restrict__ g,
                             const float* __restrict__ bta,
                             float* __restrict__ xsum,
                             fp16* __restrict__ outhi,
                             fp16* __restrict__ outlo)
{
    int row = blockIdx.x;
    size_t off4 = (size_t)row * (DM / 4) + threadIdx.x;
    float4 xv = ((const float4*)x)[off4];
    float4 a = ((const float4*)y0)[off4];
    float4 b = ((const float4*)y1)[off4];
    float4 v;
    v.x = xv.x + 0.5f * (a.x + b.x);
    v.y = xv.y + 0.5f * (a.y + b.y);
    v.z = xv.z + 0.5f * (a.z + b.z);
    v.w = xv.w + 0.5f * (a.w + b.w);
    ((float4*)xsum)[off4] = v;

    float s  = v.x + v.y + v.z + v.w;
    float sq = v.x*v.x + v.y*v.y + v.z*v.z + v.w*v.w;
    #pragma unroll
    for (int o = 16; o >= 1; o >>= 1) {
        s  += __shfl_xor_sync(0xffffffffu, s, o);
        sq += __shfl_xor_sync(0xffffffffu, sq, o);
    }
    __shared__ float ss[8], ssq[8];
    int warp = threadIdx.x >> 5, lane = threadIdx.x & 31;
    if (lane == 0) { ss[warp] = s; ssq[warp] = sq; }
    __syncthreads();
    __shared__ float sh_mean, sh_inv;
    if (threadIdx.x == 0) {
        float ts = 0.f, tq = 0.f;
        #pragma unroll
        for (int w = 0; w < 8; w++) { ts += ss[w]; tq += ssq[w]; }
        float mean = ts / DM;
        float var = tq / DM - mean * mean;
        sh_mean = mean;
        sh_inv = rsqrtf(var + 1e-5f);
    }
    __syncthreads();
    float mean = sh_mean, inv = sh_inv;
    float4 gv = ((const float4*)g)[threadIdx.x];
    float4 bv = ((const float4*)bta)[threadIdx.x];
    float o0 = (v.x - mean) * inv * gv.x + bv.x;
    float o1 = (v.y - mean) * inv * gv.y + bv.y;
    float o2 = (v.z - mean) * inv * gv.z + bv.z;
    float o3 = (v.w - mean) * inv * gv.w + bv.w;
    unsigned short h0,h1,h2,h3,l0,l1,l2,l3;
    split1h(o0, h0, l0); split1h(o1, h1, l1);
    split1h(o2, h2, l2); split1h(o3, h3, l3);
    uint2 hu, lu;
    hu.x = (uint32_t)h0 | ((uint32_t)h1 << 16);
    hu.y = (uint32_t)h2 | ((uint32_t)h3 << 16);
    lu.x = (uint32_t)l0 | ((uint32_t)l1 << 16);
    lu.y = (uint32_t)l2 | ((uint32_t)l3 << 16);
    size_t off = (size_t)row * DM + threadIdx.x * 4;
    *(uint2*)(outhi + off) = hu;
    *(uint2*)(outlo + off) = lu;
}

// ---------------- host orchestration ----------------------------------------------
extern "C" void kernel_launch(void* const* d_in, const int* in_sizes, int n_in,
                              void* d_out, int out_size)
{
    (void)in_sizes; (void)n_in; (void)out_size;

    const float* x = (const float*)d_in[0];
    const float* in_w[2]   = { (const float*)d_in[1],  (const float*)d_in[10] };
    const float* conv_w[2] = { (const float*)d_in[2],  (const float*)d_in[11] };
    const float* conv_b[2] = { (const float*)d_in[3],  (const float*)d_in[12] };
    const float* x_w[2]    = { (const float*)d_in[4],  (const float*)d_in[13] };
    const float* dt_w[2]   = { (const float*)d_in[5],  (const float*)d_in[14] };
    const float* dt_b[2]   = { (const float*)d_in[6],  (const float*)d_in[15] };
    const float* A_log[2]  = { (const float*)d_in[7],  (const float*)d_in[16] };
    const float* Dp[2]     = { (const float*)d_in[8],  (const float*)d_in[17] };
    const float* out_w[2]  = { (const float*)d_in[9],  (const float*)d_in[18] };
    const float* ff_ln_g = (const float*)d_in[19];
    const float* ff_ln_b = (const float*)d_in[20];
    const float* ff_w1   = (const float*)d_in[21];
    const float* ff_b1   = (const float*)d_in[22];
    const float* ff_w2   = (const float*)d_in[23];
    const float* ff_b2   = (const float*)d_in[24];

    float *xz, *xc, *xdbl, *dtu, *ydir, *xsum;
    fp16 *xhi, *xlo, *yhi, *ylo, *lnhi, *lnlo, *f1hi, *f1lo;
    fp16 *inw16, *outw16, *w116, *w216;
    cudaGetSymbolAddress((void**)&xz,   g_xz);
    cudaGetSymbolAddress((void**)&xc,   g_xc);
    cudaGetSymbolAddress((void**)&xdbl, g_xdbl);
    cudaGetSymbolAddress((void**)&dtu,  g_dtu);
    cudaGetSymbolAddress((void**)&ydir, g_ydir);
    cudaGetSymbolAddress((void**)&xsum, g_xsum);
    cudaGetSymbolAddress((void**)&xhi,  g_xhi);
    cudaGetSymbolAddress((void**)&xlo,  g_xlo);
    cudaGetSymbolAddress((void**)&yhi,  g_yhi);
    cudaGetSymbolAddress((void**)&ylo,  g_ylo);
    cudaGetSymbolAddress((void**)&lnhi, g_lnhi);
    cudaGetSymbolAddress((void**)&lnlo, g_lnlo);
    cudaGetSymbolAddress((void**)&f1hi, g_f1hi);
    cudaGetSymbolAddress((void**)&f1lo, g_f1lo);
    cudaGetSymbolAddress((void**)&inw16,  g_inw16);
    cudaGetSymbolAddress((void**)&outw16, g_outw16);
    cudaGetSymbolAddress((void**)&w116, g_w116);
    cudaGetSymbolAddress((void**)&w216, g_w216);

    cudaFuncSetAttribute(mma_gemm2, cudaFuncAttributeMaxDynamicSharedMemorySize, DSMEM2);

    const size_t szXC   = (size_t)ML * DIN;
    const size_t szYDIR = (size_t)ML * DM;
    const size_t szINW  = (size_t)2 * DIN * DM;
    const size_t szOUTW = (size_t)DM * DIN;

    dim3 blk(256);

    // idx 0-2: converts needed for in-proj
    split_kernel<<<(ML*DM/4 + 255)/256, blk>>>(x, xhi, xlo, ML*DM/4);
    wcvt_kernel<<<((int)szINW/4 + 255)/256, blk>>>(in_w[0], inw16,         (int)szINW/4);
    wcvt_kernel<<<((int)szINW/4 + 255)/256, blk>>>(in_w[1], inw16 + szINW, (int)szINW/4);

    // idx 3 (profiled): merged in-proj, M=4096, N=8192, K=1024
    mma_gemm2<<<dim3(64, 32, 1), blk, DSMEM2>>>(
        xhi, xlo, DM, inw16, DM,
        nullptr, nullptr, xz, nullptr, nullptr,
        8192, DM, 0, 0, 0, 0);

    // remaining weight converts
    wcvt_kernel<<<(DFF*DM/4 + 255)/256, blk>>>(ff_w1, w116, DFF*DM/4);
    wcvt_kernel<<<((int)szOUTW/4 + 255)/256, blk>>>(out_w[0], outw16,          (int)szOUTW/4);
    wcvt_kernel<<<((int)szOUTW/4 + 255)/256, blk>>>(out_w[1], outw16 + szOUTW, (int)szOUTW/4);
    wcvt_kernel<<<(DM*DFF/4 + 255)/256, blk>>>(ff_w2, w216, DM*DFF/4);

    // conv (both dirs), float4 over channels
    conv_kernel<<<(2*ML*DIN/4 + 255)/256, blk>>>(xz, conv_w[0], conv_w[1],
                                                 conv_b[0], conv_b[1], xc);

    // xdbl (both dirs), B/C interleaved
    xdbl_gemm<<<dim3(ML/32, 1, 2), dim3(128)>>>(xc, x_w[0], x_w[1], xdbl);

    // dt (both dirs) -> (dt, u) pairs
    dt_gemm<<<dim3(DIN/128, ML/128, 2), blk>>>(xdbl, xc, dt_w[0], dt_w[1],
                                               dt_b[0], dt_b[1], dtu);

    // scan (both dirs): 512 blocks = 2 dir x 2 b x 128 d-groups
    scan_kernel<<<512, blk>>>(dtu, xdbl, xz, A_log[0], A_log[1],
                              Dp[0], Dp[1], yhi, ylo);

    // out-proj (both dirs via z)
    mma_gemm2<<<dim3(8, 32, 2), blk, DSMEM2>>>(
        yhi, ylo, DIN, outw16, DIN,
        nullptr, nullptr, ydir, nullptr, nullptr,
        DM, DIN, 0, szXC, szOUTW, szYDIR);

    // fused residual + LN
    resln_kernel<<<ML, blk>>>(x, ydir, ydir + szYDIR, ff_ln_g, ff_ln_b,
                              xsum, lnhi, lnlo);

    // ff1 = silu(ln @ ff_w1^T + b1) -> fp16 hi/lo
    mma_gemm2<<<dim3(32, 32, 1), blk, DSMEM2>>>(
        lnhi, lnlo, DM, w116, DM,
        ff_b1, nullptr, nullptr, f1hi, f1lo,
        DFF, DM, 1, 0, 0, 0);

    // out = xsum + (ff1 @ ff_w2^T + b2)
    mma_gemm2<<<dim3(8, 32, 1), blk, DSMEM2>>>(
        f1hi, f1lo, DFF, w216, DFF,
        ff_b2, xsum, (float*)d_out, nullptr, nullptr,
        DM, DFF, 0, 0, 0, 0);
}

// round 14
// speedup vs baseline: 1.7773x; 1.2089x over previous
#include <cuda_runtime.h>
#include <cuda_fp16.h>
#include <math.h>
#include <stdint.h>

// Problem constants
#define BB   2
#define LS   2048
#define DM   1024
#define DIN  2048
#define DST  16
#define RDT  64
#define ML   (BB*LS)      // 4096 rows
#define DFF  (4*DM)       // 4096

typedef __half fp16;

// ---------------- scratch (device globals) -----------------------------------
// xz unified: [ML][8192], cols [dir*4096 .. +2047]=xi, [+2048..+4095]=z
__device__ __align__(256) float g_xz  [(size_t)ML * 8192];
__device__ __align__(256) float g_xc  [2u * ML * DIN];
__device__ __align__(256) float g_xdbl[2u * ML * 96];     // cols 64..95: B/C interleaved
__device__ __align__(256) float g_dtu [2u * (size_t)ML * DIN * 2];  // (dt, u) pairs
__device__ __align__(256) float g_ydir[2u * ML * DM];
__device__ __align__(256) float g_xsum[(size_t)ML * DM];

__device__ __align__(256) fp16 g_x16 [(size_t)ML * DM];
__device__ __align__(256) fp16 g_y16 [2u * ML * DIN];
__device__ __align__(256) fp16 g_ln16[(size_t)ML * DM];
__device__ __align__(256) fp16 g_f116[(size_t)ML * DFF];
__device__ __align__(256) fp16 g_inw16 [2u * 2 * DIN * DM];
__device__ __align__(256) fp16 g_outw16[2u * DM * DIN];
__device__ __align__(256) fp16 g_w116[(size_t)DFF * DM];
__device__ __align__(256) fp16 g_w216[(size_t)DM * DFF];

// ---------------- helpers ------------------------------------------------------
__device__ __forceinline__ float siluf(float v) { return v / (1.f + __expf(-v)); }
__device__ __forceinline__ float softplusf(float v) {
    return (v > 20.f) ? v : log1pf(__expf(v));
}

#define LDSM4(r0, r1, r2, r3, addr) \
    asm volatile("ldmatrix.sync.aligned.m8n8.x4.shared.b16 {%0,%1,%2,%3}, [%4];" \
        : "=r"(r0), "=r"(r1), "=r"(r2), "=r"(r3) : "r"(addr))

#define MMAF16(d, a, b0, b1) \
    asm volatile("mma.sync.aligned.m16n8k16.row.col.f32.f16.f16.f32 " \
        "{%0,%1,%2,%3}, {%4,%5,%6,%7}, {%8,%9}, {%0,%1,%2,%3};" \
        : "+f"((d)[0]), "+f"((d)[1]), "+f"((d)[2]), "+f"((d)[3]) \
        : "r"((a)[0]), "r"((a)[1]), "r"((a)[2]), "r"((a)[3]), "r"(b0), "r"(b1))

#define CPA16(sa, ga) \
    asm volatile("cp.async.cg.shared.global [%0], [%1], 16;" :: "r"(sa), "l"(ga))
#define CPA_COMMIT() asm volatile("cp.async.commit_group;" ::: "memory")
#define CPA_WAIT1()  asm volatile("cp.async.wait_group 1;" ::: "memory")

// ---------------- fp16 1-product tensor-core GEMM ------------------------------
// C[M,N] = A[M,K] * B[N,K]^T, A and B single fp16 (numerics == tf32xtf32,
// measured rel_err 2.5e-4 end-to-end in R10).
// 128x128 tiles, KC=32, 3-stage cp.async, 8 warps (2Mx4N).
#define KC       32
#define ARR_B    8192                  // one [128][32] fp16 array
#define STAGE_B  (2 * ARR_B)           // A, B = 16KB
#define NSTAGE   3
#define DSMEM2   (NSTAGE * STAGE_B)    // 49152 B

__global__ __launch_bounds__(256, 2)
void mma_gemm2(const fp16* __restrict__ Af, int lda,
               const fp16* __restrict__ Bf, int ldb,
               const float* __restrict__ bias,
               const float* __restrict__ addsrc,
               float* __restrict__ Cf,
               fp16* __restrict__ C16,
               int ldc, int K, int act,
               size_t zsA, size_t zsB, size_t zsC)
{
    extern __shared__ char sm[];
    const int tid  = threadIdx.x;
    const int lane = tid & 31;
    const int wid  = tid >> 5;
    const int wm   = wid >> 2;
    const int wn   = wid & 3;
    const int rowBase = blockIdx.y * 128;
    const int colBase = blockIdx.x * 128;
    const size_t zA = (size_t)blockIdx.z * zsA;
    const size_t zB = (size_t)blockIdx.z * zsB;
    const size_t zC = (size_t)blockIdx.z * zsC;
    const uint32_t smb = (uint32_t)__cvta_generic_to_shared(sm);

    const int crow = tid >> 2;
    const int cck  = tid & 3;
    const size_t offA0 = zA + (size_t)(rowBase + crow) * lda + cck * 8;
    const size_t offA1 = zA + (size_t)(rowBase + crow + 64) * lda + cck * 8;
    const size_t offB0 = zB + (size_t)(colBase + crow) * ldb + cck * 8;
    const size_t offB1 = zB + (size_t)(colBase + crow + 64) * ldb + cck * 8;
    const uint32_t s0 = (uint32_t)crow * 64        + (uint32_t)((cck ^ ((crow >> 1) & 3)) * 16);
    const uint32_t s1 = (uint32_t)(crow + 64) * 64 + (uint32_t)((cck ^ (((crow + 64) >> 1) & 3)) * 16);

    const int laneAr = (lane & 7) + ((lane >> 3) & 1) * 8;
    const int aCk    = (lane >> 4);
    const int laneBr = (lane & 7) + ((lane >> 4) & 1) * 8;
    const int bCk    = (lane >> 3) & 1;
    uint32_t aRowB[4], aSw[4], bRowB[2], bSw[2];
    #pragma unroll
    for (int i = 0; i < 4; i++) {
        int r = wm * 64 + i * 16 + laneAr;
        aRowB[i] = (uint32_t)r * 64;
        aSw[i]   = (uint32_t)((r >> 1) & 3);
    }
    #pragma unroll
    for (int p = 0; p < 2; p++) {
        int r = wn * 32 + p * 16 + laneBr;
        bRowB[p] = (uint32_t)r * 64;
        bSw[p]   = (uint32_t)((r >> 1) & 3);
    }

    float acc[16][4];
    #pragma unroll
    for (int i = 0; i < 16; i++)
        #pragma unroll
        for (int j = 0; j < 4; j++) acc[i][j] = 0.f;

    const int nk = K / KC;

    auto issue = [&](int stg, int kt) {
        const uint32_t sb = smb + (uint32_t)stg * STAGE_B;
        const size_t ko = (size_t)kt * KC;
        CPA16(sb + 0*ARR_B + s0, Af + offA0 + ko);
        CPA16(sb + 0*ARR_B + s1, Af + offA1 + ko);
        CPA16(sb + 1*ARR_B + s0, Bf + offB0 + ko);
        CPA16(sb + 1*ARR_B + s1, Bf + offB1 + ko);
    };

    issue(0, 0); CPA_COMMIT();
    issue(1, 1); CPA_COMMIT();

    int stg = 0;
    for (int kt = 0; kt < nk; kt++) {
        CPA_WAIT1();
        __syncthreads();
        if (kt + 2 < nk) issue((stg + 2) % NSTAGE, kt + 2);
        CPA_COMMIT();

        const uint32_t base = smb + (uint32_t)stg * STAGE_B;
        #pragma unroll
        for (int ks = 0; ks < 2; ks++) {
            uint32_t aF[4][4], bF[2][4];
            #pragma unroll
            for (int i = 0; i < 4; i++)
                LDSM4(aF[i][0], aF[i][1], aF[i][2], aF[i][3],
                      base + 0*ARR_B + aRowB[i] + (((uint32_t)(ks*2 + aCk) ^ aSw[i]) * 16));
            #pragma unroll
            for (int p = 0; p < 2; p++)
                LDSM4(bF[p][0], bF[p][1], bF[p][2], bF[p][3],
                      base + 1*ARR_B + bRowB[p] + (((uint32_t)(ks*2 + bCk) ^ bSw[p]) * 16));
            #pragma unroll
            for (int i = 0; i < 4; i++)
                #pragma unroll
                for (int nt = 0; nt < 4; nt++)
                    MMAF16(acc[i*4+nt], aF[i], bF[nt>>1][(nt&1)*2], bF[nt>>1][(nt&1)*2+1]);
        }
        stg = (stg + 1) % NSTAGE;
    }

    const int erow  = wm * 64 + (lane >> 2);
    const int ecol0 = wn * 32 + (lane & 3) * 2;
    #pragma unroll
    for (int i = 0; i < 4; i++) {
        int r0 = rowBase + erow + i * 16;
        int r1 = r0 + 8;
        #pragma unroll
        for (int nt = 0; nt < 4; nt++) {
            int c = colBase + ecol0 + nt * 8;
            float v0 = acc[i*4+nt][0], v1 = acc[i*4+nt][1];
            float v2 = acc[i*4+nt][2], v3 = acc[i*4+nt][3];
            if (bias) {
                float b0 = __ldg(&bias[c]), b1 = __ldg(&bias[c+1]);
                v0 += b0; v1 += b1; v2 += b0; v3 += b1;
            }
            if (act == 1) { v0 = siluf(v0); v1 = siluf(v1); v2 = siluf(v2); v3 = siluf(v3); }
            else if (act == 2) { v0 = softplusf(v0); v1 = softplusf(v1); v2 = softplusf(v2); v3 = softplusf(v3); }
            if (addsrc) {
                v0 += addsrc[(size_t)r0 * ldc + c];
                v1 += addsrc[(size_t)r0 * ldc + c + 1];
                v2 += addsrc[(size_t)r1 * ldc + c];
                v3 += addsrc[(size_t)r1 * ldc + c + 1];
            }
            if (Cf) {
                *(float2*)&Cf[zC + (size_t)r0 * ldc + c] = make_float2(v0, v1);
                *(float2*)&Cf[zC + (size_t)r1 * ldc + c] = make_float2(v2, v3);
            } else {
                uint32_t u0 = (uint32_t)__half_as_ushort(__float2half_rn(v0)) |
                              ((uint32_t)__half_as_ushort(__float2half_rn(v1)) << 16);
                uint32_t u1 = (uint32_t)__half_as_ushort(__float2half_rn(v2)) |
                              ((uint32_t)__half_as_ushort(__float2half_rn(v3)) << 16);
                *(uint32_t*)(C16 + zC + (size_t)r0 * ldc + c) = u0;
                *(uint32_t*)(C16 + zC + (size_t)r1 * ldc + c) = u1;
            }
        }
    }
}

// ---------------- fp32 -> fp16 convert --------------------------------------------
__global__ void wcvt_kernel(const float* __restrict__ in,
                            fp16* __restrict__ out, int n4)
{
    int i = blockIdx.x * blockDim.x + threadIdx.x;
    if (i >= n4) return;
    float4 v = ((const float4*)in)[i];
    uint2 u;
    u.x = (uint32_t)__half_as_ushort(__float2half_rn(v.x)) |
          ((uint32_t)__half_as_ushort(__float2half_rn(v.y)) << 16);
    u.y = (uint32_t)__half_as_ushort(__float2half_rn(v.z)) |
          ((uint32_t)__half_as_ushort(__float2half_rn(v.w)) << 16);
    *(uint2*)(out + (size_t)i * 4) = u;
}

// ---------------- xdbl GEMM: [2][ML][96], B/C interleaved in cols 64..95 --------
__global__ __launch_bounds__(128)
void xdbl_gemm(const float* __restrict__ xcA,
               const float* __restrict__ xw0,
               const float* __restrict__ xw1,
               float* __restrict__ out)
{
    __shared__ float As[16][36];
    __shared__ float Bs[16][100];
    const int dir = blockIdx.z;
    const float* A = xcA + (size_t)dir * ML * DIN + (size_t)blockIdx.x * 32 * DIN;
    const float* B = dir ? xw1 : xw0;
    float* C = out + (size_t)dir * ML * 96 + (size_t)blockIdx.x * 32 * 96;

    const int tid = threadIdx.x;
    const int tx = tid & 15, ty = tid >> 4;
    float acc[4][6];
    #pragma unroll
    for (int i = 0; i < 4; i++)
        #pragma unroll
        for (int j = 0; j < 6; j++) acc[i][j] = 0.f;

    const int ar = tid >> 2, akc = (tid & 3) * 4;

    for (int k0 = 0; k0 < DIN; k0 += 16) {
        {
            float4 v = *(const float4*)(A + (size_t)ar * DIN + k0 + akc);
            As[akc+0][ar] = v.x; As[akc+1][ar] = v.y;
            As[akc+2][ar] = v.z; As[akc+3][ar] = v.w;
        }
        #pragma unroll
        for (int j = 0; j < 3; j++) {
            int i = tid + j * 128;
            int n = i >> 2, kc = (i & 3) * 4;
            float4 v = *(const float4*)(B + (size_t)n * DIN + k0 + kc);
            Bs[kc+0][n] = v.x; Bs[kc+1][n] = v.y;
            Bs[kc+2][n] = v.z; Bs[kc+3][n] = v.w;
        }
        __syncthreads();
        #pragma unroll
        for (int kk = 0; kk < 16; kk++) {
            float4 a4 = *(const float4*)&As[kk][ty*4];
            float ar4[4] = {a4.x, a4.y, a4.z, a4.w};
            float2 b0 = *(const float2*)&Bs[kk][tx*6];
            float2 b1 = *(const float2*)&Bs[kk][tx*6+2];
            float2 b2 = *(const float2*)&Bs[kk][tx*6+4];
            float br[6] = {b0.x, b0.y, b1.x, b1.y, b2.x, b2.y};
            #pragma unroll
            for (int i = 0; i < 4; i++)
                #pragma unroll
                for (int j = 0; j < 6; j++)
                    acc[i][j] = fmaf(ar4[i], br[j], acc[i][j]);
        }
        __syncthreads();
    }
    #pragma unroll
    for (int i = 0; i < 4; i++)
        #pragma unroll
        for (int j = 0; j < 6; j++) {
            int c = tx*6 + j;
            int cw = (c < 64) ? c : ((c < 80) ? (64 + 2*(c - 64)) : (65 + 2*(c - 80)));
            C[(size_t)(ty*4+i) * 96 + cw] = acc[i][j];
        }
}

// ---------------- dt GEMM -> (dt, u) float2 pairs, float4 stores ----------------
__global__ __launch_bounds__(256)
void dt_gemm(const float* __restrict__ xdblA,
             const float* __restrict__ xcA,
             const float* __restrict__ w0, const float* __restrict__ w1,
             const float* __restrict__ b0, const float* __restrict__ b1,
             float* __restrict__ out)          // [2][ML][DIN][2]
{
    __shared__ float As[16][132];
    __shared__ float Bs[16][132];

    const int dir = blockIdx.z;
    const float* A = xdblA + (size_t)dir * ML * 96;
    const float* xcD = xcA + (size_t)dir * ML * DIN;
    const float* Bw = dir ? w1 : w0;
    const float* bias = dir ? b1 : b0;
    float* C = out + (size_t)dir * ML * DIN * 2;

    const int tid = threadIdx.x;
    const int tx = tid & 15;
    const int ty = tid >> 4;
    const int rowBase = blockIdx.y * 128;
    const int colBase = blockIdx.x * 128;

    const int lm = tid >> 1;
    const int lk = (tid & 1) * 8;

    const float* aPtr = A + (size_t)(rowBase + lm) * 96 + lk;
    const float* bPtr = Bw + (size_t)(colBase + lm) * RDT + lk;

    float acc[8][8];
    #pragma unroll
    for (int i = 0; i < 8; i++)
        #pragma unroll
        for (int j = 0; j < 8; j++) acc[i][j] = 0.f;

    for (int k0 = 0; k0 < RDT; k0 += 16) {
        float4 a0 = *(const float4*)(aPtr + k0);
        float4 a1 = *(const float4*)(aPtr + k0 + 4);
        float4 b0v = *(const float4*)(bPtr + k0);
        float4 b1v = *(const float4*)(bPtr + k0 + 4);

        As[lk+0][lm] = a0.x; As[lk+1][lm] = a0.y; As[lk+2][lm] = a0.z; As[lk+3][lm] = a0.w;
        As[lk+4][lm] = a1.x; As[lk+5][lm] = a1.y; As[lk+6][lm] = a1.z; As[lk+7][lm] = a1.w;
        Bs[lk+0][lm] = b0v.x; Bs[lk+1][lm] = b0v.y; Bs[lk+2][lm] = b0v.z; Bs[lk+3][lm] = b0v.w;
        Bs[lk+4][lm] = b1v.x; Bs[lk+5][lm] = b1v.y; Bs[lk+6][lm] = b1v.z; Bs[lk+7][lm] = b1v.w;
        __syncthreads();

        #pragma unroll
        for (int kk = 0; kk < 16; kk++) {
            float4 ra0 = *(const float4*)&As[kk][ty * 4];
            float4 ra1 = *(const float4*)&As[kk][64 + ty * 4];
            float4 rb0 = *(const float4*)&Bs[kk][tx * 4];
            float4 rb1 = *(const float4*)&Bs[kk][64 + tx * 4];
            float ar[8] = {ra0.x, ra0.y, ra0.z, ra0.w, ra1.x, ra1.y, ra1.z, ra1.w};
            float br[8] = {rb0.x, rb0.y, rb0.z, rb0.w, rb1.x, rb1.y, rb1.z, rb1.w};
            #pragma unroll
            for (int i = 0; i < 8; i++)
                #pragma unroll
                for (int j = 0; j < 8; j++)
                    acc[i][j] = fmaf(ar[i], br[j], acc[i][j]);
        }
        __syncthreads();
    }

    #pragma unroll
    for (int i = 0; i < 8; i++) {
        int r = rowBase + ((i < 4) ? (ty * 4 + i) : (64 + ty * 4 + i - 4));
        #pragma unroll
        for (int j = 0; j < 8; j += 2) {
            int c = colBase + ((j < 4) ? (tx * 4 + j) : (64 + tx * 4 + j - 4));
            float dt0 = softplusf(acc[i][j]   + bias[c]);
            float dt1 = softplusf(acc[i][j+1] + bias[c+1]);
            float2 uv = *(const float2*)&xcD[(size_t)r * DIN + c];
            float4 o = make_float4(dt0, uv.x, dt1, uv.y);
            *(float4*)&C[((size_t)r * DIN + c) * 2] = o;
        }
    }
}

// ---------------- depthwise causal conv, float4 over channels -------------------
__global__ void conv_kernel(const float* __restrict__ xz,
                            const float* __restrict__ cw0, const float* __restrict__ cw1,
                            const float* __restrict__ cb0, const float* __restrict__ cb1,
                            float* __restrict__ xc)
{
    int idx = blockIdx.x * blockDim.x + threadIdx.x;
    if (idx >= 2 * ML * DIN / 4) return;
    int dir = idx >= ML * DIN / 4;
    int li = dir ? (idx - ML * DIN / 4) : idx;
    int c4 = li & (DIN / 4 - 1);
    int r  = li / (DIN / 4);
    int l  = r & (LS - 1);
    int b  = r >> 11;
    int c  = c4 * 4;
    const float* cw = dir ? cw1 : cw0;
    const float* cb = dir ? cb1 : cb0;
    float4 w[4];
    #pragma unroll
    for (int q = 0; q < 4; q++) w[q] = *(const float4*)&cw[(c + q) * 4];
    float4 acc = *(const float4*)&cb[c];
    float* accp = &acc.x;

    const size_t colOff = (size_t)dir * 4096 + c;
    #pragma unroll
    for (int k = 0; k < 4; k++) {
        int lp = dir ? (l + 3 - k) : (l - 3 + k);
        bool ok = dir ? (lp < LS) : (lp >= 0);
        if (ok) {
            float4 xv = *(const float4*)&xz[(size_t)(b * LS + lp) * 8192 + colOff];
            const float* xp = &xv.x;
            #pragma unroll
            for (int q = 0; q < 4; q++) {
                float wt = (&w[q].x)[k];
                accp[q] = fmaf(xp[q], wt, accp[q]);
            }
        }
    }
    float4 o;
    o.x = siluf(acc.x); o.y = siluf(acc.y);
    o.z = siluf(acc.z); o.w = siluf(acc.w);
    *(float4*)&xc[(size_t)dir * ML * DIN + (size_t)r * DIN + c] = o;
}

// ---------------- selective scan: (dir,b,16d) blocks, smem-staged y out ---------
__global__ __launch_bounds__(256)
void scan_kernel(const float* __restrict__ dtu,
                 const float* __restrict__ xdbl,
                 const float* __restrict__ xz,
                 const float* __restrict__ A0, const float* __restrict__ A1,
                 const float* __restrict__ D0, const float* __restrict__ D1,
                 fp16* __restrict__ yout)
{
    __shared__ unsigned short sy[32][16];

    const int tid  = threadIdx.x;
    const int wid  = tid >> 5;
    const int lane = tid & 31;
    const int half = lane >> 4;
    const int s    = lane & 15;

    const int dg  = blockIdx.x & 127;
    const int b   = (blockIdx.x >> 7) & 1;
    const int dir = blockIdx.x >> 8;
    const int dloc = wid * 2 + half;
    const int d    = dg * 16 + dloc;

    const float* Alog = dir ? A1 : A0;
    const float Av = -__expf(Alog[d * DST + s]);
    const float Dd = (dir ? D1 : D0)[d];
    float h = 0.f;
    const bool w0lane = (s == 0);

    const size_t base = (size_t)b * LS;
    const int l0 = dir ? (LS - 1) : 0;
    const int step = dir ? -1 : 1;

    const float* pDtu = dtu + ((size_t)dir * ML * DIN + (base + l0) * DIN + d) * 2;
    const float* pBC  = xdbl + (size_t)dir * ML * 96 + (base + l0) * 96 + RDT + 2 * s;
    const float* pZ   = xz + (base + l0) * 8192 + (size_t)dir * 4096 + 2048 + d;
    const ptrdiff_t sDtu = (ptrdiff_t)step * DIN * 2;
    const ptrdiff_t sBC  = (ptrdiff_t)step * 96;
    const ptrdiff_t sZ   = (ptrdiff_t)step * 8192;
    const size_t yBase = (size_t)dir * ML * DIN + base * DIN;

    float2 du = *(const float2*)pDtu;
    float2 bc = *(const float2*)pBC;
    float zv  = w0lane ? *pZ : 0.f;

    for (int it = 0; it < LS; it++) {
        const bool more = (it + 1 < LS);
        float2 dun = more ? *(const float2*)(pDtu + sDtu) : du;
        float2 bcn = more ? *(const float2*)(pBC + sBC)   : bc;
        float zn   = (w0lane && more) ? *(pZ + sZ) : zv;

        h = h * __expf(du.x * Av) + du.x * du.y * bc.x;
        float y = h * bc.y;
        y += __shfl_xor_sync(0xffffffffu, y, 8);
        y += __shfl_xor_sync(0xffffffffu, y, 4);
        y += __shfl_xor_sync(0xffffffffu, y, 2);
        y += __shfl_xor_sync(0xffffffffu, y, 1);
        if (w0lane) {
            float yv = (y + du.y * Dd) * siluf(zv);
            sy[it & 31][dloc] = __half_as_ushort(__float2half_rn(yv));
        }
        if ((it & 31) == 31) {
            __syncthreads();
            const int row = tid >> 3;
            const int cp  = tid & 7;
            const int itr = (it - 31) + row;
            const int gl  = l0 + step * itr;
            const size_t go = yBase + (size_t)gl * DIN + dg * 16 + 2 * cp;
            *(uint32_t*)(yout + go) = *(const uint32_t*)&sy[row][2 * cp];
            __syncthreads();
        }
        pDtu += sDtu; pBC += sBC; pZ += sZ;
        du = dun; bc = bcn; zv = zn;
    }
}

// ---------------- fused residual + layernorm -> xsum + fp16 ln -------------------
__global__ void resln_kernel(const float* __restrict__ x,
                             const float* __restrict__ y0,
                             const float* __restrict__ y1,
                             const float* __restrict__ g,
                             const float* __restrict__ bta,
                             float* __restrict__ xsum,
                             fp16* __restrict__ lnout)
{
    int row = blockIdx.x;
    size_t off4 = (size_t)row * (DM / 4) + threadIdx.x;
    float4 xv = ((const float4*)x)[off4];
    float4 a = ((const float4*)y0)[off4];
    float4 b = ((const float4*)y1)[off4];
    float4 v;
    v.x = xv.x + 0.5f * (a.x + b.x);
    v.y = xv.y + 0.5f * (a.y + b.y);
    v.z = xv.z + 0.5f * (a.z + b.z);
    v.w = xv.w + 0.5f * (a.w + b.w);
    ((float4*)xsum)[off4] = v;

    float s  = v.x + v.y + v.z + v.w;
    float sq = v.x*v.x + v.y*v.y + v.z*v.z + v.w*v.w;
    #pragma unroll
    for (int o = 16; o >= 1; o >>= 1) {
        s  += __shfl_xor_sync(0xffffffffu, s, o);
        sq += __shfl_xor_sync(0xffffffffu, sq, o);
    }
    __shared__ float ss[8], ssq[8];
    int warp = threadIdx.x >> 5, lane = threadIdx.x & 31;
    if (lane == 0) { ss[warp] = s; ssq[warp] = sq; }
    __syncthreads();
    __shared__ float sh_mean, sh_inv;
    if (threadIdx.x == 0) {
        float ts = 0.f, tq = 0.f;
        #pragma unroll
        for (int w = 0; w < 8; w++) { ts += ss[w]; tq += ssq[w]; }
        float mean = ts / DM;
        float var = tq / DM - mean * mean;
        sh_mean = mean;
        sh_inv = rsqrtf(var + 1e-5f);
    }
    __syncthreads();
    float mean = sh_mean, inv = sh_inv;
    float4 gv = ((const float4*)g)[threadIdx.x];
    float4 bv = ((const float4*)bta)[threadIdx.x];
    float o0 = (v.x - mean) * inv * gv.x + bv.x;
    float o1 = (v.y - mean) * inv * gv.y + bv.y;
    float o2 = (v.z - mean) * inv * gv.z + bv.z;
    float o3 = (v.w - mean) * inv * gv.w + bv.w;
    uint2 u;
    u.x = (uint32_t)__half_as_ushort(__float2half_rn(o0)) |
          ((uint32_t)__half_as_ushort(__float2half_rn(o1)) << 16);
    u.y = (uint32_t)__half_as_ushort(__float2half_rn(o2)) |
          ((uint32_t)__half_as_ushort(__float2half_rn(o3)) << 16);
    size_t off = (size_t)row * DM + threadIdx.x * 4;
    *(uint2*)(lnout + off) = u;
}

// ---------------- host orchestration ----------------------------------------------
extern "C" void kernel_launch(void* const* d_in, const int* in_sizes, int n_in,
                              void* d_out, int out_size)
{
    (void)in_sizes; (void)n_in; (void)out_size;

    const float* x = (const float*)d_in[0];
    const float* in_w[2]   = { (const float*)d_in[1],  (const float*)d_in[10] };
    const float* conv_w[2] = { (const float*)d_in[2],  (const float*)d_in[11] };
    const float* conv_b[2] = { (const float*)d_in[3],  (const float*)d_in[12] };
    const float* x_w[2]    = { (const float*)d_in[4],  (const float*)d_in[13] };
    const float* dt_w[2]   = { (const float*)d_in[5],  (const float*)d_in[14] };
    const float* dt_b[2]   = { (const float*)d_in[6],  (const float*)d_in[15] };
    const float* A_log[2]  = { (const float*)d_in[7],  (const float*)d_in[16] };
    const float* Dp[2]     = { (const float*)d_in[8],  (const float*)d_in[17] };
    const float* out_w[2]  = { (const float*)d_in[9],  (const float*)d_in[18] };
    const float* ff_ln_g = (const float*)d_in[19];
    const float* ff_ln_b = (const float*)d_in[20];
    const float* ff_w1   = (const float*)d_in[21];
    const float* ff_b1   = (const float*)d_in[22];
    const float* ff_w2   = (const float*)d_in[23];
    const float* ff_b2   = (const float*)d_in[24];

    float *xz, *xc, *xdbl, *dtu, *ydir, *xsum;
    fp16 *x16, *y16, *ln16, *f116;
    fp16 *inw16, *outw16, *w116, *w216;
    cudaGetSymbolAddress((void**)&xz,   g_xz);
    cudaGetSymbolAddress((void**)&xc,   g_xc);
    cudaGetSymbolAddress((void**)&xdbl, g_xdbl);
    cudaGetSymbolAddress((void**)&dtu,  g_dtu);
    cudaGetSymbolAddress((void**)&ydir, g_ydir);
    cudaGetSymbolAddress((void**)&xsum, g_xsum);
    cudaGetSymbolAddress((void**)&x16,  g_x16);
    cudaGetSymbolAddress((void**)&y16,  g_y16);
    cudaGetSymbolAddress((void**)&ln16, g_ln16);
    cudaGetSymbolAddress((void**)&f116, g_f116);
    cudaGetSymbolAddress((void**)&inw16,  g_inw16);
    cudaGetSymbolAddress((void**)&outw16, g_outw16);
    cudaGetSymbolAddress((void**)&w116, g_w116);
    cudaGetSymbolAddress((void**)&w216, g_w216);

    cudaFuncSetAttribute(mma_gemm2, cudaFuncAttributeMaxDynamicSharedMemorySize, DSMEM2);

    const size_t szXC   = (size_t)ML * DIN;
    const size_t szYDIR = (size_t)ML * DM;
    const size_t szINW  = (size_t)2 * DIN * DM;
    const size_t szOUTW = (size_t)DM * DIN;

    dim3 blk(256);

    // idx 0-2: converts needed for in-proj
    wcvt_kernel<<<(ML*DM/4 + 255)/256, blk>>>(x, x16, ML*DM/4);
    wcvt_kernel<<<((int)szINW/4 + 255)/256, blk>>>(in_w[0], inw16,         (int)szINW/4);
    wcvt_kernel<<<((int)szINW/4 + 255)/256, blk>>>(in_w[1], inw16 + szINW, (int)szINW/4);

    // idx 3 (profiled): merged in-proj, M=4096, N=8192, K=1024
    mma_gemm2<<<dim3(64, 32, 1), blk, DSMEM2>>>(
        x16, DM, inw16, DM,
        nullptr, nullptr, xz, nullptr,
        8192, DM, 0, 0, 0, 0);

    // remaining weight converts
    wcvt_kernel<<<(DFF*DM/4 + 255)/256, blk>>>(ff_w1, w116, DFF*DM/4);
    wcvt_kernel<<<((int)szOUTW/4 + 255)/256, blk>>>(out_w[0], outw16,          (int)szOUTW/4);
    wcvt_kernel<<<((int)szOUTW/4 + 255)/256, blk>>>(out_w[1], outw16 + szOUTW, (int)szOUTW/4);
    wcvt_kernel<<<(DM*DFF/4 + 255)/256, blk>>>(ff_w2, w216, DM*DFF/4);

    // conv (both dirs), float4 over channels
    conv_kernel<<<(2*ML*DIN/4 + 255)/256, blk>>>(xz, conv_w[0], conv_w[1],
                                                 conv_b[0], conv_b[1], xc);

    // xdbl (both dirs), B/C interleaved
    xdbl_gemm<<<dim3(ML/32, 1, 2), dim3(128)>>>(xc, x_w[0], x_w[1], xdbl);

    // dt (both dirs) -> (dt, u) pairs
    dt_gemm<<<dim3(DIN/128, ML/128, 2), blk>>>(xdbl, xc, dt_w[0], dt_w[1],
                                               dt_b[0], dt_b[1], dtu);

    // scan (both dirs): 512 blocks = 2 dir x 2 b x 128 d-groups
    scan_kernel<<<512, blk>>>(dtu, xdbl, xz, A_log[0], A_log[1],
                              Dp[0], Dp[1], y16);

    // out-proj (both dirs via z)
    mma_gemm2<<<dim3(8, 32, 2), blk, DSMEM2>>>(
        y16, DIN, outw16, DIN,
        nullptr, nullptr, ydir, nullptr,
        DM, DIN, 0, szXC, szOUTW, szYDIR);

    // fused residual + LN
    resln_kernel<<<ML, blk>>>(x, ydir, ydir + szYDIR, ff_ln_g, ff_ln_b,
                              xsum, ln16);

    // ff1 = silu(ln @ ff_w1^T + b1) -> fp16
    mma_gemm2<<<dim3(32, 32, 1), blk, DSMEM2>>>(
        ln16, DM, w116, DM,
        ff_b1, nullptr, nullptr, f116,
        DFF, DM, 1, 0, 0, 0);

    // out = xsum + (ff1 @ ff_w2^T + b2)
    mma_gemm2<<<dim3(8, 32, 1), blk, DSMEM2>>>(
        f116, DFF, w216, DFF,
        ff_b2, xsum, (float*)d_out, nullptr,
        DM, DFF, 0, 0, 0, 0);
}

// round 15
// speedup vs baseline: 1.8434x; 1.0372x over previous
#include <cuda_runtime.h>
#include <cuda_fp16.h>
#include <math.h>
#include <stdint.h>

// Problem constants
#define BB   2
#define LS   2048
#define DM   1024
#define DIN  2048
#define DST  16
#define RDT  64
#define ML   (BB*LS)      // 4096 rows
#define DFF  (4*DM)       // 4096

typedef __half fp16;

// ---------------- scratch (device globals) -----------------------------------
// xz16 unified: [ML][8192] fp16, cols [dir*4096..+2047]=xi, [+2048..+4095]=z
__device__ __align__(256) fp16   g_xz16[(size_t)ML * 8192];
__device__ __align__(256) float  g_xc  [2u * ML * DIN];
__device__ __align__(256) float  g_xdbl[2u * ML * 96];    // cols 64..95: B/C interleaved
__device__ __align__(256) float4 g_dtuz[(size_t)2 * ML * DIN];  // (dt, u, silu(z), _)
__device__ __align__(256) float  g_ydir[2u * ML * DM];
__device__ __align__(256) float  g_xsum[(size_t)ML * DM];

__device__ __align__(256) fp16 g_x16 [(size_t)ML * DM];
__device__ __align__(256) fp16 g_y16 [2u * ML * DIN];
__device__ __align__(256) fp16 g_ln16[(size_t)ML * DM];
__device__ __align__(256) fp16 g_f116[(size_t)ML * DFF];
__device__ __align__(256) fp16 g_inw16 [2u * 2 * DIN * DM];
__device__ __align__(256) fp16 g_outw16[2u * DM * DIN];
__device__ __align__(256) fp16 g_w116[(size_t)DFF * DM];
__device__ __align__(256) fp16 g_w216[(size_t)DM * DFF];

// ---------------- helpers ------------------------------------------------------
__device__ __forceinline__ float siluf(float v) { return v / (1.f + __expf(-v)); }
__device__ __forceinline__ float softplusf(float v) {
    return (v > 20.f) ? v : log1pf(__expf(v));
}

#define LDSM4(r0, r1, r2, r3, addr) \
    asm volatile("ldmatrix.sync.aligned.m8n8.x4.shared.b16 {%0,%1,%2,%3}, [%4];" \
        : "=r"(r0), "=r"(r1), "=r"(r2), "=r"(r3) : "r"(addr))

#define MMAF16(d, a, b0, b1) \
    asm volatile("mma.sync.aligned.m16n8k16.row.col.f32.f16.f16.f32 " \
        "{%0,%1,%2,%3}, {%4,%5,%6,%7}, {%8,%9}, {%0,%1,%2,%3};" \
        : "+f"((d)[0]), "+f"((d)[1]), "+f"((d)[2]), "+f"((d)[3]) \
        : "r"((a)[0]), "r"((a)[1]), "r"((a)[2]), "r"((a)[3]), "r"(b0), "r"(b1))

#define CPA16(sa, ga) \
    asm volatile("cp.async.cg.shared.global [%0], [%1], 16;" :: "r"(sa), "l"(ga))
#define CPA_COMMIT() asm volatile("cp.async.commit_group;" ::: "memory")
#define CPA_WAIT1()  asm volatile("cp.async.wait_group 1;" ::: "memory")

// ---------------- fp16 1-product tensor-core GEMM ------------------------------
#define KC       32
#define ARR_B    8192
#define STAGE_B  (2 * ARR_B)
#define NSTAGE   3
#define DSMEM2   (NSTAGE * STAGE_B)

__global__ __launch_bounds__(256, 2)
void mma_gemm2(const fp16* __restrict__ Af, int lda,
               const fp16* __restrict__ Bf, int ldb,
               const float* __restrict__ bias,
               const float* __restrict__ addsrc,
               float* __restrict__ Cf,
               fp16* __restrict__ C16,
               int ldc, int K, int act,
               size_t zsA, size_t zsB, size_t zsC)
{
    extern __shared__ char sm[];
    const int tid  = threadIdx.x;
    const int lane = tid & 31;
    const int wid  = tid >> 5;
    const int wm   = wid >> 2;
    const int wn   = wid & 3;
    const int rowBase = blockIdx.y * 128;
    const int colBase = blockIdx.x * 128;
    const size_t zA = (size_t)blockIdx.z * zsA;
    const size_t zB = (size_t)blockIdx.z * zsB;
    const size_t zC = (size_t)blockIdx.z * zsC;
    const uint32_t smb = (uint32_t)__cvta_generic_to_shared(sm);

    const int crow = tid >> 2;
    const int cck  = tid & 3;
    const size_t offA0 = zA + (size_t)(rowBase + crow) * lda + cck * 8;
    const size_t offA1 = zA + (size_t)(rowBase + crow + 64) * lda + cck * 8;
    const size_t offB0 = zB + (size_t)(colBase + crow) * ldb + cck * 8;
    const size_t offB1 = zB + (size_t)(colBase + crow + 64) * ldb + cck * 8;
    const uint32_t s0 = (uint32_t)crow * 64        + (uint32_t)((cck ^ ((crow >> 1) & 3)) * 16);
    const uint32_t s1 = (uint32_t)(crow + 64) * 64 + (uint32_t)((cck ^ (((crow + 64) >> 1) & 3)) * 16);

    const int laneAr = (lane & 7) + ((lane >> 3) & 1) * 8;
    const int aCk    = (lane >> 4);
    const int laneBr = (lane & 7) + ((lane >> 4) & 1) * 8;
    const int bCk    = (lane >> 3) & 1;
    uint32_t aRowB[4], aSw[4], bRowB[2], bSw[2];
    #pragma unroll
    for (int i = 0; i < 4; i++) {
        int r = wm * 64 + i * 16 + laneAr;
        aRowB[i] = (uint32_t)r * 64;
        aSw[i]   = (uint32_t)((r >> 1) & 3);
    }
    #pragma unroll
    for (int p = 0; p < 2; p++) {
        int r = wn * 32 + p * 16 + laneBr;
        bRowB[p] = (uint32_t)r * 64;
        bSw[p]   = (uint32_t)((r >> 1) & 3);
    }

    float acc[16][4];
    #pragma unroll
    for (int i = 0; i < 16; i++)
        #pragma unroll
        for (int j = 0; j < 4; j++) acc[i][j] = 0.f;

    const int nk = K / KC;

    auto issue = [&](int stg, int kt) {
        const uint32_t sb = smb + (uint32_t)stg * STAGE_B;
        const size_t ko = (size_t)kt * KC;
        CPA16(sb + 0*ARR_B + s0, Af + offA0 + ko);
        CPA16(sb + 0*ARR_B + s1, Af + offA1 + ko);
        CPA16(sb + 1*ARR_B + s0, Bf + offB0 + ko);
        CPA16(sb + 1*ARR_B + s1, Bf + offB1 + ko);
    };

    issue(0, 0); CPA_COMMIT();
    issue(1, 1); CPA_COMMIT();

    int stg = 0;
    for (int kt = 0; kt < nk; kt++) {
        CPA_WAIT1();
        __syncthreads();
        if (kt + 2 < nk) issue((stg + 2) % NSTAGE, kt + 2);
        CPA_COMMIT();

        const uint32_t base = smb + (uint32_t)stg * STAGE_B;
        #pragma unroll
        for (int ks = 0; ks < 2; ks++) {
            uint32_t aF[4][4], bF[2][4];
            #pragma unroll
            for (int i = 0; i < 4; i++)
                LDSM4(aF[i][0], aF[i][1], aF[i][2], aF[i][3],
                      base + 0*ARR_B + aRowB[i] + (((uint32_t)(ks*2 + aCk) ^ aSw[i]) * 16));
            #pragma unroll
            for (int p = 0; p < 2; p++)
                LDSM4(bF[p][0], bF[p][1], bF[p][2], bF[p][3],
                      base + 1*ARR_B + bRowB[p] + (((uint32_t)(ks*2 + bCk) ^ bSw[p]) * 16));
            #pragma unroll
            for (int i = 0; i < 4; i++)
                #pragma unroll
                for (int nt = 0; nt < 4; nt++)
                    MMAF16(acc[i*4+nt], aF[i], bF[nt>>1][(nt&1)*2], bF[nt>>1][(nt&1)*2+1]);
        }
        stg = (stg + 1) % NSTAGE;
    }

    const int erow  = wm * 64 + (lane >> 2);
    const int ecol0 = wn * 32 + (lane & 3) * 2;
    #pragma unroll
    for (int i = 0; i < 4; i++) {
        int r0 = rowBase + erow + i * 16;
        int r1 = r0 + 8;
        #pragma unroll
        for (int nt = 0; nt < 4; nt++) {
            int c = colBase + ecol0 + nt * 8;
            float v0 = acc[i*4+nt][0], v1 = acc[i*4+nt][1];
            float v2 = acc[i*4+nt][2], v3 = acc[i*4+nt][3];
            if (bias) {
                float b0 = __ldg(&bias[c]), b1 = __ldg(&bias[c+1]);
                v0 += b0; v1 += b1; v2 += b0; v3 += b1;
            }
            if (act == 1) { v0 = siluf(v0); v1 = siluf(v1); v2 = siluf(v2); v3 = siluf(v3); }
            else if (act == 2) { v0 = softplusf(v0); v1 = softplusf(v1); v2 = softplusf(v2); v3 = softplusf(v3); }
            if (addsrc) {
                v0 += addsrc[(size_t)r0 * ldc + c];
                v1 += addsrc[(size_t)r0 * ldc + c + 1];
                v2 += addsrc[(size_t)r1 * ldc + c];
                v3 += addsrc[(size_t)r1 * ldc + c + 1];
            }
            if (Cf) {
                *(float2*)&Cf[zC + (size_t)r0 * ldc + c] = make_float2(v0, v1);
                *(float2*)&Cf[zC + (size_t)r1 * ldc + c] = make_float2(v2, v3);
            } else {
                uint32_t u0 = (uint32_t)__half_as_ushort(__float2half_rn(v0)) |
                              ((uint32_t)__half_as_ushort(__float2half_rn(v1)) << 16);
                uint32_t u1 = (uint32_t)__half_as_ushort(__float2half_rn(v2)) |
                              ((uint32_t)__half_as_ushort(__float2half_rn(v3)) << 16);
                *(uint32_t*)(C16 + zC + (size_t)r0 * ldc + c) = u0;
                *(uint32_t*)(C16 + zC + (size_t)r1 * ldc + c) = u1;
            }
        }
    }
}

// ---------------- fp32 -> fp16 convert --------------------------------------------
__global__ void wcvt_kernel(const float* __restrict__ in,
                            fp16* __restrict__ out, int n4)
{
    int i = blockIdx.x * blockDim.x + threadIdx.x;
    if (i >= n4) return;
    float4 v = ((const float4*)in)[i];
    uint2 u;
    u.x = (uint32_t)__half_as_ushort(__float2half_rn(v.x)) |
          ((uint32_t)__half_as_ushort(__float2half_rn(v.y)) << 16);
    u.y = (uint32_t)__half_as_ushort(__float2half_rn(v.z)) |
          ((uint32_t)__half_as_ushort(__float2half_rn(v.w)) << 16);
    *(uint2*)(out + (size_t)i * 4) = u;
}

// ---------------- xdbl GEMM: [2][ML][96], B/C interleaved in cols 64..95 --------
__global__ __launch_bounds__(128)
void xdbl_gemm(const float* __restrict__ xcA,
               const float* __restrict__ xw0,
               const float* __restrict__ xw1,
               float* __restrict__ out)
{
    __shared__ float As[16][36];
    __shared__ float Bs[16][100];
    const int dir = blockIdx.z;
    const float* A = xcA + (size_t)dir * ML * DIN + (size_t)blockIdx.x * 32 * DIN;
    const float* B = dir ? xw1 : xw0;
    float* C = out + (size_t)dir * ML * 96 + (size_t)blockIdx.x * 32 * 96;

    const int tid = threadIdx.x;
    const int tx = tid & 15, ty = tid >> 4;
    float acc[4][6];
    #pragma unroll
    for (int i = 0; i < 4; i++)
        #pragma unroll
        for (int j = 0; j < 6; j++) acc[i][j] = 0.f;

    const int ar = tid >> 2, akc = (tid & 3) * 4;

    for (int k0 = 0; k0 < DIN; k0 += 16) {
        {
            float4 v = *(const float4*)(A + (size_t)ar * DIN + k0 + akc);
            As[akc+0][ar] = v.x; As[akc+1][ar] = v.y;
            As[akc+2][ar] = v.z; As[akc+3][ar] = v.w;
        }
        #pragma unroll
        for (int j = 0; j < 3; j++) {
            int i = tid + j * 128;
            int n = i >> 2, kc = (i & 3) * 4;
            float4 v = *(const float4*)(B + (size_t)n * DIN + k0 + kc);
            Bs[kc+0][n] = v.x; Bs[kc+1][n] = v.y;
            Bs[kc+2][n] = v.z; Bs[kc+3][n] = v.w;
        }
        __syncthreads();
        #pragma unroll
        for (int kk = 0; kk < 16; kk++) {
            float4 a4 = *(const float4*)&As[kk][ty*4];
            float ar4[4] = {a4.x, a4.y, a4.z, a4.w};
            float2 b0 = *(const float2*)&Bs[kk][tx*6];
            float2 b1 = *(const float2*)&Bs[kk][tx*6+2];
            float2 b2 = *(const float2*)&Bs[kk][tx*6+4];
            float br[6] = {b0.x, b0.y, b1.x, b1.y, b2.x, b2.y};
            #pragma unroll
            for (int i = 0; i < 4; i++)
                #pragma unroll
                for (int j = 0; j < 6; j++)
                    acc[i][j] = fmaf(ar4[i], br[j], acc[i][j]);
        }
        __syncthreads();
    }
    #pragma unroll
    for (int i = 0; i < 4; i++)
        #pragma unroll
        for (int j = 0; j < 6; j++) {
            int c = tx*6 + j;
            int cw = (c < 64) ? c : ((c < 80) ? (64 + 2*(c - 64)) : (65 + 2*(c - 80)));
            C[(size_t)(ty*4+i) * 96 + cw] = acc[i][j];
        }
}

// ---------------- dt GEMM -> (dt, u, silu(z), _) float4 --------------------------
__global__ __launch_bounds__(256)
void dt_gemm(const float* __restrict__ xdblA,
             const float* __restrict__ xcA,
             const fp16* __restrict__ xz16,
             const float* __restrict__ w0, const float* __restrict__ w1,
             const float* __restrict__ b0, const float* __restrict__ b1,
             float4* __restrict__ dtuz)        // [2][ML][DIN]
{
    __shared__ float As[16][132];
    __shared__ float Bs[16][132];

    const int dir = blockIdx.z;
    const float* A = xdblA + (size_t)dir * ML * 96;
    const float* xcD = xcA + (size_t)dir * ML * DIN;
    const float* Bw = dir ? w1 : w0;
    const float* bias = dir ? b1 : b0;
    float4* C = dtuz + (size_t)dir * ML * DIN;

    const int tid = threadIdx.x;
    const int tx = tid & 15;
    const int ty = tid >> 4;
    const int rowBase = blockIdx.y * 128;
    const int colBase = blockIdx.x * 128;

    const int lm = tid >> 1;
    const int lk = (tid & 1) * 8;

    const float* aPtr = A + (size_t)(rowBase + lm) * 96 + lk;
    const float* bPtr = Bw + (size_t)(colBase + lm) * RDT + lk;

    float acc[8][8];
    #pragma unroll
    for (int i = 0; i < 8; i++)
        #pragma unroll
        for (int j = 0; j < 8; j++) acc[i][j] = 0.f;

    for (int k0 = 0; k0 < RDT; k0 += 16) {
        float4 a0 = *(const float4*)(aPtr + k0);
        float4 a1 = *(const float4*)(aPtr + k0 + 4);
        float4 b0v = *(const float4*)(bPtr + k0);
        float4 b1v = *(const float4*)(bPtr + k0 + 4);

        As[lk+0][lm] = a0.x; As[lk+1][lm] = a0.y; As[lk+2][lm] = a0.z; As[lk+3][lm] = a0.w;
        As[lk+4][lm] = a1.x; As[lk+5][lm] = a1.y; As[lk+6][lm] = a1.z; As[lk+7][lm] = a1.w;
        Bs[lk+0][lm] = b0v.x; Bs[lk+1][lm] = b0v.y; Bs[lk+2][lm] = b0v.z; Bs[lk+3][lm] = b0v.w;
        Bs[lk+4][lm] = b1v.x; Bs[lk+5][lm] = b1v.y; Bs[lk+6][lm] = b1v.z; Bs[lk+7][lm] = b1v.w;
        __syncthreads();

        #pragma unroll
        for (int kk = 0; kk < 16; kk++) {
            float4 ra0 = *(const float4*)&As[kk][ty * 4];
            float4 ra1 = *(const float4*)&As[kk][64 + ty * 4];
            float4 rb0 = *(const float4*)&Bs[kk][tx * 4];
            float4 rb1 = *(const float4*)&Bs[kk][64 + tx * 4];
            float ar[8] = {ra0.x, ra0.y, ra0.z, ra0.w, ra1.x, ra1.y, ra1.z, ra1.w};
            float br[8] = {rb0.x, rb0.y, rb0.z, rb0.w, rb1.x, rb1.y, rb1.z, rb1.w};
            #pragma unroll
            for (int i = 0; i < 8; i++)
                #pragma unroll
                for (int j = 0; j < 8; j++)
                    acc[i][j] = fmaf(ar[i], br[j], acc[i][j]);
        }
        __syncthreads();
    }

    #pragma unroll
    for (int i = 0; i < 8; i++) {
        int r = rowBase + ((i < 4) ? (ty * 4 + i) : (64 + ty * 4 + i - 4));
        #pragma unroll
        for (int j = 0; j < 8; j += 2) {
            int c = colBase + ((j < 4) ? (tx * 4 + j) : (64 + tx * 4 + j - 4));
            float dt0 = softplusf(acc[i][j]   + bias[c]);
            float dt1 = softplusf(acc[i][j+1] + bias[c+1]);
            float2 uv = *(const float2*)&xcD[(size_t)r * DIN + c];
            __half2 zh = *(const __half2*)&xz16[(size_t)r * 8192 + dir * 4096 + 2048 + c];
            float sz0 = siluf(__low2float(zh));
            float sz1 = siluf(__high2float(zh));
            C[(size_t)r * DIN + c]     = make_float4(dt0, uv.x, sz0, 0.f);
            C[(size_t)r * DIN + c + 1] = make_float4(dt1, uv.y, sz1, 0.f);
        }
    }
}

// ---------------- depthwise causal conv, fp16 input, float4 over channels -------
__global__ void conv_kernel(const fp16* __restrict__ xz,
                            const float* __restrict__ cw0, const float* __restrict__ cw1,
                            const float* __restrict__ cb0, const float* __restrict__ cb1,
                            float* __restrict__ xc)
{
    int idx = blockIdx.x * blockDim.x + threadIdx.x;
    if (idx >= 2 * ML * DIN / 4) return;
    int dir = idx >= ML * DIN / 4;
    int li = dir ? (idx - ML * DIN / 4) : idx;
    int c4 = li & (DIN / 4 - 1);
    int r  = li / (DIN / 4);
    int l  = r & (LS - 1);
    int b  = r >> 11;
    int c  = c4 * 4;
    const float* cw = dir ? cw1 : cw0;
    const float* cb = dir ? cb1 : cb0;
    float4 w[4];
    #pragma unroll
    for (int q = 0; q < 4; q++) w[q] = *(const float4*)&cw[(c + q) * 4];
    float4 acc = *(const float4*)&cb[c];
    float* accp = &acc.x;

    const size_t colOff = (size_t)dir * 4096 + c;
    #pragma unroll
    for (int k = 0; k < 4; k++) {
        int lp = dir ? (l + 3 - k) : (l - 3 + k);
        bool ok = dir ? (lp < LS) : (lp >= 0);
        if (ok) {
            const __half2* hp = (const __half2*)&xz[(size_t)(b * LS + lp) * 8192 + colOff];
            float2 f0 = __half22float2(hp[0]);
            float2 f1 = __half22float2(hp[1]);
            float xp[4] = {f0.x, f0.y, f1.x, f1.y};
            #pragma unroll
            for (int q = 0; q < 4; q++) {
                float wt = (&w[q].x)[k];
                accp[q] = fmaf(xp[q], wt, accp[q]);
            }
        }
    }
    float4 o;
    o.x = siluf(acc.x); o.y = siluf(acc.y);
    o.z = siluf(acc.z); o.w = siluf(acc.w);
    *(float4*)&xc[(size_t)dir * ML * DIN + (size_t)r * DIN + c] = o;
}

// ---------------- selective scan: broadcast float4 operand, smem-staged y -------
__global__ __launch_bounds__(256)
void scan_kernel(const float4* __restrict__ dtuz,  // [2][ML][DIN] (dt,u,sz,_)
                 const float* __restrict__ xdbl,   // [2][ML][96] (B/C paired)
                 const float* __restrict__ A0, const float* __restrict__ A1,
                 const float* __restrict__ D0, const float* __restrict__ D1,
                 fp16* __restrict__ yout)
{
    __shared__ unsigned short sy[32][16];

    const int tid  = threadIdx.x;
    const int wid  = tid >> 5;
    const int lane = tid & 31;
    const int half = lane >> 4;
    const int s    = lane & 15;

    const int dg  = blockIdx.x & 127;
    const int b   = (blockIdx.x >> 7) & 1;
    const int dir = blockIdx.x >> 8;
    const int dloc = wid * 2 + half;
    const int d    = dg * 16 + dloc;

    const float* Alog = dir ? A1 : A0;
    const float Av = -__expf(Alog[d * DST + s]);
    const float Dd = (dir ? D1 : D0)[d];
    float h = 0.f;
    const bool w0lane = (s == 0);

    const size_t base = (size_t)b * LS;
    const int l0 = dir ? (LS - 1) : 0;
    const int step = dir ? -1 : 1;

    const float4* pD = dtuz + (size_t)dir * ML * DIN + (base + l0) * DIN + d;
    const float* pBC = xdbl + (size_t)dir * ML * 96 + (base + l0) * 96 + RDT + 2 * s;
    const ptrdiff_t sD  = (ptrdiff_t)step * DIN;
    const ptrdiff_t sBC = (ptrdiff_t)step * 96;
    const size_t yBase = (size_t)dir * ML * DIN + base * DIN;

    float4 duz = *pD;
    float2 bc = *(const float2*)pBC;

    for (int it = 0; it < LS; it++) {
        const bool more = (it + 1 < LS);
        float4 duzn = more ? *(pD + sD) : duz;
        float2 bcn = more ? *(const float2*)(pBC + sBC) : bc;

        h = h * __expf(duz.x * Av) + duz.x * duz.y * bc.x;
        float y = h * bc.y;
        y += __shfl_xor_sync(0xffffffffu, y, 8);
        y += __shfl_xor_sync(0xffffffffu, y, 4);
        y += __shfl_xor_sync(0xffffffffu, y, 2);
        y += __shfl_xor_sync(0xffffffffu, y, 1);
        if (w0lane) {
            float yv = (y + duz.y * Dd) * duz.z;
            sy[it & 31][dloc] = __half_as_ushort(__float2half_rn(yv));
        }
        if ((it & 31) == 31) {
            __syncthreads();
            const int row = tid >> 3;
            const int cp  = tid & 7;
            const int itr = (it - 31) + row;
            const int gl  = l0 + step * itr;
            const size_t go = yBase + (size_t)gl * DIN + dg * 16 + 2 * cp;
            *(uint32_t*)(yout + go) = *(const uint32_t*)&sy[row][2 * cp];
            __syncthreads();
        }
        pD += sD; pBC += sBC;
        duz = duzn; bc = bcn;
    }
}

// ---------------- fused residual + layernorm -> xsum + fp16 ln -------------------
__global__ void resln_kernel(const float* __restrict__ x,
                             const float* __restrict__ y0,
                             const float* __restrict__ y1,
                             const float* __restrict__ g,
                             const float* __restrict__ bta,
                             float* __restrict__ xsum,
                             fp16* __restrict__ lnout)
{
    int row = blockIdx.x;
    size_t off4 = (size_t)row * (DM / 4) + threadIdx.x;
    float4 xv = ((const float4*)x)[off4];
    float4 a = ((const float4*)y0)[off4];
    float4 b = ((const float4*)y1)[off4];
    float4 v;
    v.x = xv.x + 0.5f * (a.x + b.x);
    v.y = xv.y + 0.5f * (a.y + b.y);
    v.z = xv.z + 0.5f * (a.z + b.z);
    v.w = xv.w + 0.5f * (a.w + b.w);
    ((float4*)xsum)[off4] = v;

    float s  = v.x + v.y + v.z + v.w;
    float sq = v.x*v.x + v.y*v.y + v.z*v.z + v.w*v.w;
    #pragma unroll
    for (int o = 16; o >= 1; o >>= 1) {
        s  += __shfl_xor_sync(0xffffffffu, s, o);
        sq += __shfl_xor_sync(0xffffffffu, sq, o);
    }
    __shared__ float ss[8], ssq[8];
    int warp = threadIdx.x >> 5, lane = threadIdx.x & 31;
    if (lane == 0) { ss[warp] = s; ssq[warp] = sq; }
    __syncthreads();
    __shared__ float sh_mean, sh_inv;
    if (threadIdx.x == 0) {
        float ts = 0.f, tq = 0.f;
        #pragma unroll
        for (int w = 0; w < 8; w++) { ts += ss[w]; tq += ssq[w]; }
        float mean = ts / DM;
        float var = tq / DM - mean * mean;
        sh_mean = mean;
        sh_inv = rsqrtf(var + 1e-5f);
    }
    __syncthreads();
    float mean = sh_mean, inv = sh_inv;
    float4 gv = ((const float4*)g)[threadIdx.x];
    float4 bv = ((const float4*)bta)[threadIdx.x];
    float o0 = (v.x - mean) * inv * gv.x + bv.x;
    float o1 = (v.y - mean) * inv * gv.y + bv.y;
    float o2 = (v.z - mean) * inv * gv.z + bv.z;
    float o3 = (v.w - mean) * inv * gv.w + bv.w;
    uint2 u;
    u.x = (uint32_t)__half_as_ushort(__float2half_rn(o0)) |
          ((uint32_t)__half_as_ushort(__float2half_rn(o1)) << 16);
    u.y = (uint32_t)__half_as_ushort(__float2half_rn(o2)) |
          ((uint32_t)__half_as_ushort(__float2half_rn(o3)) << 16);
    size_t off = (size_t)row * DM + threadIdx.x * 4;
    *(uint2*)(lnout + off) = u;
}

// ---------------- host orchestration ----------------------------------------------
extern "C" void kernel_launch(void* const* d_in, const int* in_sizes, int n_in,
                              void* d_out, int out_size)
{
    (void)in_sizes; (void)n_in; (void)out_size;

    const float* x = (const float*)d_in[0];
    const float* in_w[2]   = { (const float*)d_in[1],  (const float*)d_in[10] };
    const float* conv_w[2] = { (const float*)d_in[2],  (const float*)d_in[11] };
    const float* conv_b[2] = { (const float*)d_in[3],  (const float*)d_in[12] };
    const float* x_w[2]    = { (const float*)d_in[4],  (const float*)d_in[13] };
    const float* dt_w[2]   = { (const float*)d_in[5],  (const float*)d_in[14] };
    const float* dt_b[2]   = { (const float*)d_in[6],  (const float*)d_in[15] };
    const float* A_log[2]  = { (const float*)d_in[7],  (const float*)d_in[16] };
    const float* Dp[2]     = { (const float*)d_in[8],  (const float*)d_in[17] };
    const float* out_w[2]  = { (const float*)d_in[9],  (const float*)d_in[18] };
    const float* ff_ln_g = (const float*)d_in[19];
    const float* ff_ln_b = (const float*)d_in[20];
    const float* ff_w1   = (const float*)d_in[21];
    const float* ff_b1   = (const float*)d_in[22];
    const float* ff_w2   = (const float*)d_in[23];
    const float* ff_b2   = (const float*)d_in[24];

    float *xc, *xdbl, *ydir, *xsum;
    float4 *dtuz;
    fp16 *xz16, *x16, *y16, *ln16, *f116;
    fp16 *inw16, *outw16, *w116, *w216;
    cudaGetSymbolAddress((void**)&xz16, g_xz16);
    cudaGetSymbolAddress((void**)&xc,   g_xc);
    cudaGetSymbolAddress((void**)&xdbl, g_xdbl);
    cudaGetSymbolAddress((void**)&dtuz, g_dtuz);
    cudaGetSymbolAddress((void**)&ydir, g_ydir);
    cudaGetSymbolAddress((void**)&xsum, g_xsum);
    cudaGetSymbolAddress((void**)&x16,  g_x16);
    cudaGetSymbolAddress((void**)&y16,  g_y16);
    cudaGetSymbolAddress((void**)&ln16, g_ln16);
    cudaGetSymbolAddress((void**)&f116, g_f116);
    cudaGetSymbolAddress((void**)&inw16,  g_inw16);
    cudaGetSymbolAddress((void**)&outw16, g_outw16);
    cudaGetSymbolAddress((void**)&w116, g_w116);
    cudaGetSymbolAddress((void**)&w216, g_w216);

    cudaFuncSetAttribute(mma_gemm2, cudaFuncAttributeMaxDynamicSharedMemorySize, DSMEM2);

    const size_t szXC   = (size_t)ML * DIN;
    const size_t szYDIR = (size_t)ML * DM;
    const size_t szINW  = (size_t)2 * DIN * DM;
    const size_t szOUTW = (size_t)DM * DIN;

    dim3 blk(256);

    // idx 0-2: converts needed for in-proj
    wcvt_kernel<<<(ML*DM/4 + 255)/256, blk>>>(x, x16, ML*DM/4);
    wcvt_kernel<<<((int)szINW/4 + 255)/256, blk>>>(in_w[0], inw16,         (int)szINW/4);
    wcvt_kernel<<<((int)szINW/4 + 255)/256, blk>>>(in_w[1], inw16 + szINW, (int)szINW/4);

    // idx 3 (profiled): merged in-proj -> fp16 xz, M=4096, N=8192, K=1024
    mma_gemm2<<<dim3(64, 32, 1), blk, DSMEM2>>>(
        x16, DM, inw16, DM,
        nullptr, nullptr, nullptr, xz16,
        8192, DM, 0, 0, 0, 0);

    // remaining weight converts
    wcvt_kernel<<<(DFF*DM/4 + 255)/256, blk>>>(ff_w1, w116, DFF*DM/4);
    wcvt_kernel<<<((int)szOUTW/4 + 255)/256, blk>>>(out_w[0], outw16,          (int)szOUTW/4);
    wcvt_kernel<<<((int)szOUTW/4 + 255)/256, blk>>>(out_w[1], outw16 + szOUTW, (int)szOUTW/4);
    wcvt_kernel<<<(DM*DFF/4 + 255)/256, blk>>>(ff_w2, w216, DM*DFF/4);

    // conv (both dirs), fp16 input
    conv_kernel<<<(2*ML*DIN/4 + 255)/256, blk>>>(xz16, conv_w[0], conv_w[1],
                                                 conv_b[0], conv_b[1], xc);

    // xdbl (both dirs), B/C interleaved
    xdbl_gemm<<<dim3(ML/32, 1, 2), dim3(128)>>>(xc, x_w[0], x_w[1], xdbl);

    // dt (both dirs) -> (dt, u, silu(z), _) float4
    dt_gemm<<<dim3(DIN/128, ML/128, 2), blk>>>(xdbl, xc, xz16, dt_w[0], dt_w[1],
                                               dt_b[0], dt_b[1], dtuz);

    // scan (both dirs): 512 blocks = 2 dir x 2 b x 128 d-groups
    scan_kernel<<<512, blk>>>(dtuz, xdbl, A_log[0], A_log[1],
                              Dp[0], Dp[1], y16);

    // out-proj (both dirs via z)
    mma_gemm2<<<dim3(8, 32, 2), blk, DSMEM2>>>(
        y16, DIN, outw16, DIN,
        nullptr, nullptr, ydir, nullptr,
        DM, DIN, 0, szXC, szOUTW, szYDIR);

    // fused residual + LN
    resln_kernel<<<ML, blk>>>(x, ydir, ydir + szYDIR, ff_ln_g, ff_ln_b,
                              xsum, ln16);

    // ff1 = silu(ln @ ff_w1^T + b1) -> fp16
    mma_gemm2<<<dim3(32, 32, 1), blk, DSMEM2>>>(
        ln16, DM, w116, DM,
        ff_b1, nullptr, nullptr, f116,
        DFF, DM, 1, 0, 0, 0);

    // out = xsum + (ff1 @ ff_w2^T + b2)
    mma_gemm2<<<dim3(8, 32, 1), blk, DSMEM2>>>(
        f116, DFF, w216, DFF,
        ff_b2, xsum, (float*)d_out, nullptr,
        DM, DFF, 0, 0, 0, 0);
}

// round 16
// speedup vs baseline: 1.8597x; 1.0089x over previous
#include <cuda_runtime.h>
#include <cuda_fp16.h>
#include <math.h>
#include <stdint.h>

// Problem constants
#define BB   2
#define LS   2048
#define DM   1024
#define DIN  2048
#define DST  16
#define RDT  64
#define ML   (BB*LS)      // 4096 rows
#define DFF  (4*DM)       // 4096

typedef __half fp16;

// ---------------- scratch (device globals) -----------------------------------
// xz16 unified: [ML][8192] fp16, cols [dir*4096..+2047]=xi, [+2048..+4095]=z
__device__ __align__(256) fp16  g_xz16[(size_t)ML * 8192];
__device__ __align__(256) fp16  g_xc16[2u * ML * DIN];
__device__ __align__(256) float g_xdbl[2u * ML * 96];    // cols 64..95: B/C interleaved
__device__ __align__(256) float g_dtu [2u * (size_t)ML * DIN * 2];  // (dt,u) fp32 pairs
__device__ __align__(256) fp16  g_sz16[2u * ML * DIN];   // silu(z) fp16
__device__ __align__(256) float g_ydir[2u * ML * DM];
__device__ __align__(256) float g_xsum[(size_t)ML * DM];

__device__ __align__(256) fp16 g_x16 [(size_t)ML * DM];
__device__ __align__(256) fp16 g_y16 [2u * ML * DIN];
__device__ __align__(256) fp16 g_ln16[(size_t)ML * DM];
__device__ __align__(256) fp16 g_f116[(size_t)ML * DFF];
__device__ __align__(256) fp16 g_inw16 [2u * 2 * DIN * DM];
__device__ __align__(256) fp16 g_outw16[2u * DM * DIN];
__device__ __align__(256) fp16 g_w116[(size_t)DFF * DM];
__device__ __align__(256) fp16 g_w216[(size_t)DM * DFF];

// ---------------- helpers ------------------------------------------------------
__device__ __forceinline__ float siluf(float v) { return v / (1.f + __expf(-v)); }
__device__ __forceinline__ float softplusf(float v) {
    return (v > 20.f) ? v : log1pf(__expf(v));
}

#define LDSM4(r0, r1, r2, r3, addr) \
    asm volatile("ldmatrix.sync.aligned.m8n8.x4.shared.b16 {%0,%1,%2,%3}, [%4];" \
        : "=r"(r0), "=r"(r1), "=r"(r2), "=r"(r3) : "r"(addr))

#define MMAF16(d, a, b0, b1) \
    asm volatile("mma.sync.aligned.m16n8k16.row.col.f32.f16.f16.f32 " \
        "{%0,%1,%2,%3}, {%4,%5,%6,%7}, {%8,%9}, {%0,%1,%2,%3};" \
        : "+f"((d)[0]), "+f"((d)[1]), "+f"((d)[2]), "+f"((d)[3]) \
        : "r"((a)[0]), "r"((a)[1]), "r"((a)[2]), "r"((a)[3]), "r"(b0), "r"(b1))

#define CPA16(sa, ga) \
    asm volatile("cp.async.cg.shared.global [%0], [%1], 16;" :: "r"(sa), "l"(ga))
#define CPA_COMMIT() asm volatile("cp.async.commit_group;" ::: "memory")
#define CPA_WAIT1()  asm volatile("cp.async.wait_group 1;" ::: "memory")

// ---------------- fp16 1-product tensor-core GEMM ------------------------------
#define KC       32
#define ARR_B    8192
#define STAGE_B  (2 * ARR_B)
#define NSTAGE   3
#define DSMEM2   (NSTAGE * STAGE_B)

__global__ __launch_bounds__(256, 2)
void mma_gemm2(const fp16* __restrict__ Af, int lda,
               const fp16* __restrict__ Bf, int ldb,
               const float* __restrict__ bias,
               const float* __restrict__ addsrc,
               float* __restrict__ Cf,
               fp16* __restrict__ C16,
               int ldc, int K, int act,
               size_t zsA, size_t zsB, size_t zsC)
{
    extern __shared__ char sm[];
    const int tid  = threadIdx.x;
    const int lane = tid & 31;
    const int wid  = tid >> 5;
    const int wm   = wid >> 2;
    const int wn   = wid & 3;
    const int rowBase = blockIdx.y * 128;
    const int colBase = blockIdx.x * 128;
    const size_t zA = (size_t)blockIdx.z * zsA;
    const size_t zB = (size_t)blockIdx.z * zsB;
    const size_t zC = (size_t)blockIdx.z * zsC;
    const uint32_t smb = (uint32_t)__cvta_generic_to_shared(sm);

    const int crow = tid >> 2;
    const int cck  = tid & 3;
    const size_t offA0 = zA + (size_t)(rowBase + crow) * lda + cck * 8;
    const size_t offA1 = zA + (size_t)(rowBase + crow + 64) * lda + cck * 8;
    const size_t offB0 = zB + (size_t)(colBase + crow) * ldb + cck * 8;
    const size_t offB1 = zB + (size_t)(colBase + crow + 64) * ldb + cck * 8;
    const uint32_t s0 = (uint32_t)crow * 64        + (uint32_t)((cck ^ ((crow >> 1) & 3)) * 16);
    const uint32_t s1 = (uint32_t)(crow + 64) * 64 + (uint32_t)((cck ^ (((crow + 64) >> 1) & 3)) * 16);

    const int laneAr = (lane & 7) + ((lane >> 3) & 1) * 8;
    const int aCk    = (lane >> 4);
    const int laneBr = (lane & 7) + ((lane >> 4) & 1) * 8;
    const int bCk    = (lane >> 3) & 1;
    uint32_t aRowB[4], aSw[4], bRowB[2], bSw[2];
    #pragma unroll
    for (int i = 0; i < 4; i++) {
        int r = wm * 64 + i * 16 + laneAr;
        aRowB[i] = (uint32_t)r * 64;
        aSw[i]   = (uint32_t)((r >> 1) & 3);
    }
    #pragma unroll
    for (int p = 0; p < 2; p++) {
        int r = wn * 32 + p * 16 + laneBr;
        bRowB[p] = (uint32_t)r * 64;
        bSw[p]   = (uint32_t)((r >> 1) & 3);
    }

    float acc[16][4];
    #pragma unroll
    for (int i = 0; i < 16; i++)
        #pragma unroll
        for (int j = 0; j < 4; j++) acc[i][j] = 0.f;

    const int nk = K / KC;

    auto issue = [&](int stg, int kt) {
        const uint32_t sb = smb + (uint32_t)stg * STAGE_B;
        const size_t ko = (size_t)kt * KC;
        CPA16(sb + 0*ARR_B + s0, Af + offA0 + ko);
        CPA16(sb + 0*ARR_B + s1, Af + offA1 + ko);
        CPA16(sb + 1*ARR_B + s0, Bf + offB0 + ko);
        CPA16(sb + 1*ARR_B + s1, Bf + offB1 + ko);
    };

    issue(0, 0); CPA_COMMIT();
    issue(1, 1); CPA_COMMIT();

    int stg = 0;
    for (int kt = 0; kt < nk; kt++) {
        CPA_WAIT1();
        __syncthreads();
        if (kt + 2 < nk) issue((stg + 2) % NSTAGE, kt + 2);
        CPA_COMMIT();

        const uint32_t base = smb + (uint32_t)stg * STAGE_B;
        #pragma unroll
        for (int ks = 0; ks < 2; ks++) {
            uint32_t aF[4][4], bF[2][4];
            #pragma unroll
            for (int i = 0; i < 4; i++)
                LDSM4(aF[i][0], aF[i][1], aF[i][2], aF[i][3],
                      base + 0*ARR_B + aRowB[i] + (((uint32_t)(ks*2 + aCk) ^ aSw[i]) * 16));
            #pragma unroll
            for (int p = 0; p < 2; p++)
                LDSM4(bF[p][0], bF[p][1], bF[p][2], bF[p][3],
                      base + 1*ARR_B + bRowB[p] + (((uint32_t)(ks*2 + bCk) ^ bSw[p]) * 16));
            #pragma unroll
            for (int i = 0; i < 4; i++)
                #pragma unroll
                for (int nt = 0; nt < 4; nt++)
                    MMAF16(acc[i*4+nt], aF[i], bF[nt>>1][(nt&1)*2], bF[nt>>1][(nt&1)*2+1]);
        }
        stg = (stg + 1) % NSTAGE;
    }

    const int erow  = wm * 64 + (lane >> 2);
    const int ecol0 = wn * 32 + (lane & 3) * 2;
    #pragma unroll
    for (int i = 0; i < 4; i++) {
        int r0 = rowBase + erow + i * 16;
        int r1 = r0 + 8;
        #pragma unroll
        for (int nt = 0; nt < 4; nt++) {
            int c = colBase + ecol0 + nt * 8;
            float v0 = acc[i*4+nt][0], v1 = acc[i*4+nt][1];
            float v2 = acc[i*4+nt][2], v3 = acc[i*4+nt][3];
            if (bias) {
                float b0 = __ldg(&bias[c]), b1 = __ldg(&bias[c+1]);
                v0 += b0; v1 += b1; v2 += b0; v3 += b1;
            }
            if (act == 1) { v0 = siluf(v0); v1 = siluf(v1); v2 = siluf(v2); v3 = siluf(v3); }
            else if (act == 2) { v0 = softplusf(v0); v1 = softplusf(v1); v2 = softplusf(v2); v3 = softplusf(v3); }
            if (addsrc) {
                v0 += addsrc[(size_t)r0 * ldc + c];
                v1 += addsrc[(size_t)r0 * ldc + c + 1];
                v2 += addsrc[(size_t)r1 * ldc + c];
                v3 += addsrc[(size_t)r1 * ldc + c + 1];
            }
            if (Cf) {
                *(float2*)&Cf[zC + (size_t)r0 * ldc + c] = make_float2(v0, v1);
                *(float2*)&Cf[zC + (size_t)r1 * ldc + c] = make_float2(v2, v3);
            } else {
                uint32_t u0 = (uint32_t)__half_as_ushort(__float2half_rn(v0)) |
                              ((uint32_t)__half_as_ushort(__float2half_rn(v1)) << 16);
                uint32_t u1 = (uint32_t)__half_as_ushort(__float2half_rn(v2)) |
                              ((uint32_t)__half_as_ushort(__float2half_rn(v3)) << 16);
                *(uint32_t*)(C16 + zC + (size_t)r0 * ldc + c) = u0;
                *(uint32_t*)(C16 + zC + (size_t)r1 * ldc + c) = u1;
            }
        }
    }
}

// ---------------- fp32 -> fp16 convert --------------------------------------------
__global__ void wcvt_kernel(const float* __restrict__ in,
                            fp16* __restrict__ out, int n4)
{
    int i = blockIdx.x * blockDim.x + threadIdx.x;
    if (i >= n4) return;
    float4 v = ((const float4*)in)[i];
    uint2 u;
    u.x = (uint32_t)__half_as_ushort(__float2half_rn(v.x)) |
          ((uint32_t)__half_as_ushort(__float2half_rn(v.y)) << 16);
    u.y = (uint32_t)__half_as_ushort(__float2half_rn(v.z)) |
          ((uint32_t)__half_as_ushort(__float2half_rn(v.w)) << 16);
    *(uint2*)(out + (size_t)i * 4) = u;
}

// ---------------- xdbl GEMM: fp16 A, [2][ML][96], B/C interleaved ---------------
__global__ __launch_bounds__(128)
void xdbl_gemm(const fp16* __restrict__ xcA,
               const float* __restrict__ xw0,
               const float* __restrict__ xw1,
               float* __restrict__ out)
{
    __shared__ float As[16][36];
    __shared__ float Bs[16][100];
    const int dir = blockIdx.z;
    const fp16* A = xcA + (size_t)dir * ML * DIN + (size_t)blockIdx.x * 32 * DIN;
    const float* B = dir ? xw1 : xw0;
    float* C = out + (size_t)dir * ML * 96 + (size_t)blockIdx.x * 32 * 96;

    const int tid = threadIdx.x;
    const int tx = tid & 15, ty = tid >> 4;
    float acc[4][6];
    #pragma unroll
    for (int i = 0; i < 4; i++)
        #pragma unroll
        for (int j = 0; j < 6; j++) acc[i][j] = 0.f;

    const int ar = tid >> 2, akc = (tid & 3) * 4;

    for (int k0 = 0; k0 < DIN; k0 += 16) {
        {
            uint2 raw = *(const uint2*)(A + (size_t)ar * DIN + k0 + akc);
            float2 f0 = __half22float2(*(__half2*)&raw.x);
            float2 f1 = __half22float2(*(__half2*)&raw.y);
            As[akc+0][ar] = f0.x; As[akc+1][ar] = f0.y;
            As[akc+2][ar] = f1.x; As[akc+3][ar] = f1.y;
        }
        #pragma unroll
        for (int j = 0; j < 3; j++) {
            int i = tid + j * 128;
            int n = i >> 2, kc = (i & 3) * 4;
            float4 v = *(const float4*)(B + (size_t)n * DIN + k0 + kc);
            Bs[kc+0][n] = v.x; Bs[kc+1][n] = v.y;
            Bs[kc+2][n] = v.z; Bs[kc+3][n] = v.w;
        }
        __syncthreads();
        #pragma unroll
        for (int kk = 0; kk < 16; kk++) {
            float4 a4 = *(const float4*)&As[kk][ty*4];
            float ar4[4] = {a4.x, a4.y, a4.z, a4.w};
            float2 b0 = *(const float2*)&Bs[kk][tx*6];
            float2 b1 = *(const float2*)&Bs[kk][tx*6+2];
            float2 b2 = *(const float2*)&Bs[kk][tx*6+4];
            float br[6] = {b0.x, b0.y, b1.x, b1.y, b2.x, b2.y};
            #pragma unroll
            for (int i = 0; i < 4; i++)
                #pragma unroll
                for (int j = 0; j < 6; j++)
                    acc[i][j] = fmaf(ar4[i], br[j], acc[i][j]);
        }
        __syncthreads();
    }
    #pragma unroll
    for (int i = 0; i < 4; i++)
        #pragma unroll
        for (int j = 0; j < 6; j++) {
            int c = tx*6 + j;
            int cw = (c < 64) ? c : ((c < 80) ? (64 + 2*(c - 64)) : (65 + 2*(c - 80)));
            C[(size_t)(ty*4+i) * 96 + cw] = acc[i][j];
        }
}

// ---------------- dt GEMM -> (dt,u) fp32 pairs + silu(z) fp16 --------------------
__global__ __launch_bounds__(256)
void dt_gemm(const float* __restrict__ xdblA,
             const fp16* __restrict__ xcA,
             const fp16* __restrict__ xz16,
             const float* __restrict__ w0, const float* __restrict__ w1,
             const float* __restrict__ b0, const float* __restrict__ b1,
             float* __restrict__ dtu,          // [2][ML][DIN][2]
             fp16* __restrict__ sz16)          // [2][ML][DIN]
{
    __shared__ float As[16][132];
    __shared__ float Bs[16][132];

    const int dir = blockIdx.z;
    const float* A = xdblA + (size_t)dir * ML * 96;
    const fp16* xcD = xcA + (size_t)dir * ML * DIN;
    const float* Bw = dir ? w1 : w0;
    const float* bias = dir ? b1 : b0;
    float* C = dtu + (size_t)dir * ML * DIN * 2;
    fp16* S = sz16 + (size_t)dir * ML * DIN;

    const int tid = threadIdx.x;
    const int tx = tid & 15;
    const int ty = tid >> 4;
    const int rowBase = blockIdx.y * 128;
    const int colBase = blockIdx.x * 128;

    const int lm = tid >> 1;
    const int lk = (tid & 1) * 8;

    const float* aPtr = A + (size_t)(rowBase + lm) * 96 + lk;
    const float* bPtr = Bw + (size_t)(colBase + lm) * RDT + lk;

    float acc[8][8];
    #pragma unroll
    for (int i = 0; i < 8; i++)
        #pragma unroll
        for (int j = 0; j < 8; j++) acc[i][j] = 0.f;

    for (int k0 = 0; k0 < RDT; k0 += 16) {
        float4 a0 = *(const float4*)(aPtr + k0);
        float4 a1 = *(const float4*)(aPtr + k0 + 4);
        float4 b0v = *(const float4*)(bPtr + k0);
        float4 b1v = *(const float4*)(bPtr + k0 + 4);

        As[lk+0][lm] = a0.x; As[lk+1][lm] = a0.y; As[lk+2][lm] = a0.z; As[lk+3][lm] = a0.w;
        As[lk+4][lm] = a1.x; As[lk+5][lm] = a1.y; As[lk+6][lm] = a1.z; As[lk+7][lm] = a1.w;
        Bs[lk+0][lm] = b0v.x; Bs[lk+1][lm] = b0v.y; Bs[lk+2][lm] = b0v.z; Bs[lk+3][lm] = b0v.w;
        Bs[lk+4][lm] = b1v.x; Bs[lk+5][lm] = b1v.y; Bs[lk+6][lm] = b1v.z; Bs[lk+7][lm] = b1v.w;
        __syncthreads();

        #pragma unroll
        for (int kk = 0; kk < 16; kk++) {
            float4 ra0 = *(const float4*)&As[kk][ty * 4];
            float4 ra1 = *(const float4*)&As[kk][64 + ty * 4];
            float4 rb0 = *(const float4*)&Bs[kk][tx * 4];
            float4 rb1 = *(const float4*)&Bs[kk][64 + tx * 4];
            float ar[8] = {ra0.x, ra0.y, ra0.z, ra0.w, ra1.x, ra1.y, ra1.z, ra1.w};
            float br[8] = {rb0.x, rb0.y, rb0.z, rb0.w, rb1.x, rb1.y, rb1.z, rb1.w};
            #pragma unroll
            for (int i = 0; i < 8; i++)
                #pragma unroll
                for (int j = 0; j < 8; j++)
                    acc[i][j] = fmaf(ar[i], br[j], acc[i][j]);
        }
        __syncthreads();
    }

    #pragma unroll
    for (int i = 0; i < 8; i++) {
        int r = rowBase + ((i < 4) ? (ty * 4 + i) : (64 + ty * 4 + i - 4));
        #pragma unroll
        for (int j = 0; j < 8; j += 2) {
            int c = colBase + ((j < 4) ? (tx * 4 + j) : (64 + tx * 4 + j - 4));
            float dt0 = softplusf(acc[i][j]   + bias[c]);
            float dt1 = softplusf(acc[i][j+1] + bias[c+1]);
            float2 uv = __half22float2(*(const __half2*)&xcD[(size_t)r * DIN + c]);
            *(float4*)&C[((size_t)r * DIN + c) * 2] = make_float4(dt0, uv.x, dt1, uv.y);

            __half2 zh = *(const __half2*)&xz16[(size_t)r * 8192 + dir * 4096 + 2048 + c];
            float sz0 = siluf(__low2float(zh));
            float sz1 = siluf(__high2float(zh));
            *(__half2*)&S[(size_t)r * DIN + c] = __floats2half2_rn(sz0, sz1);
        }
    }
}

// ---------------- depthwise causal conv, fp16 in/out, float4 over channels ------
__global__ void conv_kernel(const fp16* __restrict__ xz,
                            const float* __restrict__ cw0, const float* __restrict__ cw1,
                            const float* __restrict__ cb0, const float* __restrict__ cb1,
                            fp16* __restrict__ xc)
{
    int idx = blockIdx.x * blockDim.x + threadIdx.x;
    if (idx >= 2 * ML * DIN / 4) return;
    int dir = idx >= ML * DIN / 4;
    int li = dir ? (idx - ML * DIN / 4) : idx;
    int c4 = li & (DIN / 4 - 1);
    int r  = li / (DIN / 4);
    int l  = r & (LS - 1);
    int b  = r >> 11;
    int c  = c4 * 4;
    const float* cw = dir ? cw1 : cw0;
    const float* cb = dir ? cb1 : cb0;
    float4 w[4];
    #pragma unroll
    for (int q = 0; q < 4; q++) w[q] = *(const float4*)&cw[(c + q) * 4];
    float4 acc = *(const float4*)&cb[c];
    float* accp = &acc.x;

    const size_t colOff = (size_t)dir * 4096 + c;
    #pragma unroll
    for (int k = 0; k < 4; k++) {
        int lp = dir ? (l + 3 - k) : (l - 3 + k);
        bool ok = dir ? (lp < LS) : (lp >= 0);
        if (ok) {
            const __half2* hp = (const __half2*)&xz[(size_t)(b * LS + lp) * 8192 + colOff];
            float2 f0 = __half22float2(hp[0]);
            float2 f1 = __half22float2(hp[1]);
            float xp[4] = {f0.x, f0.y, f1.x, f1.y};
            #pragma unroll
            for (int q = 0; q < 4; q++) {
                float wt = (&w[q].x)[k];
                accp[q] = fmaf(xp[q], wt, accp[q]);
            }
        }
    }
    uint2 o;
    __half2 h0 = __floats2half2_rn(siluf(acc.x), siluf(acc.y));
    __half2 h1 = __floats2half2_rn(siluf(acc.z), siluf(acc.w));
    o.x = *(uint32_t*)&h0;
    o.y = *(uint32_t*)&h1;
    *(uint2*)&xc[(size_t)dir * ML * DIN + (size_t)r * DIN + c] = o;
}

// ---------------- selective scan: float2 dtu + fp16 sz broadcast ----------------
__global__ __launch_bounds__(256)
void scan_kernel(const float* __restrict__ dtu,   // [2][ML][DIN][2]
                 const fp16* __restrict__ sz16,   // [2][ML][DIN]
                 const float* __restrict__ xdbl,  // [2][ML][96] (B/C paired)
                 const float* __restrict__ A0, const float* __restrict__ A1,
                 const float* __restrict__ D0, const float* __restrict__ D1,
                 fp16* __restrict__ yout)
{
    __shared__ unsigned short sy[32][16];

    const int tid  = threadIdx.x;
    const int wid  = tid >> 5;
    const int lane = tid & 31;
    const int half = lane >> 4;
    const int s    = lane & 15;

    const int dg  = blockIdx.x & 127;
    const int b   = (blockIdx.x >> 7) & 1;
    const int dir = blockIdx.x >> 8;
    const int dloc = wid * 2 + half;
    const int d    = dg * 16 + dloc;

    const float* Alog = dir ? A1 : A0;
    const float Av = -__expf(Alog[d * DST + s]);
    const float Dd = (dir ? D1 : D0)[d];
    float h = 0.f;
    const bool w0lane = (s == 0);

    const size_t base = (size_t)b * LS;
    const int l0 = dir ? (LS - 1) : 0;
    const int step = dir ? -1 : 1;

    const float* pDtu = dtu + ((size_t)dir * ML * DIN + (base + l0) * DIN + d) * 2;
    const fp16*  pSz  = sz16 + (size_t)dir * ML * DIN + (base + l0) * DIN + d;
    const float* pBC  = xdbl + (size_t)dir * ML * 96 + (base + l0) * 96 + RDT + 2 * s;
    const ptrdiff_t sDtu = (ptrdiff_t)step * DIN * 2;
    const ptrdiff_t sSz  = (ptrdiff_t)step * DIN;
    const ptrdiff_t sBC  = (ptrdiff_t)step * 96;
    const size_t yBase = (size_t)dir * ML * DIN + base * DIN;

    float2 du = *(const float2*)pDtu;
    float2 bc = *(const float2*)pBC;
    float zv  = __half2float(*pSz);

    for (int it = 0; it < LS; it++) {
        const bool more = (it + 1 < LS);
        float2 dun = more ? *(const float2*)(pDtu + sDtu) : du;
        float2 bcn = more ? *(const float2*)(pBC + sBC)   : bc;
        float zn   = more ? __half2float(*(pSz + sSz)) : zv;

        h = h * __expf(du.x * Av) + du.x * du.y * bc.x;
        float y = h * bc.y;
        y += __shfl_xor_sync(0xffffffffu, y, 8);
        y += __shfl_xor_sync(0xffffffffu, y, 4);
        y += __shfl_xor_sync(0xffffffffu, y, 2);
        y += __shfl_xor_sync(0xffffffffu, y, 1);
        if (w0lane) {
            float yv = (y + du.y * Dd) * zv;
            sy[it & 31][dloc] = __half_as_ushort(__float2half_rn(yv));
        }
        if ((it & 31) == 31) {
            __syncthreads();
            const int row = tid >> 3;
            const int cp  = tid & 7;
            const int itr = (it - 31) + row;
            const int gl  = l0 + step * itr;
            const size_t go = yBase + (size_t)gl * DIN + dg * 16 + 2 * cp;
            *(uint32_t*)(yout + go) = *(const uint32_t*)&sy[row][2 * cp];
            __syncthreads();
        }
        pDtu += sDtu; pSz += sSz; pBC += sBC;
        du = dun; bc = bcn; zv = zn;
    }
}

// ---------------- fused residual + layernorm -> xsum + fp16 ln -------------------
__global__ void resln_kernel(const float* __restrict__ x,
                             const float* __restrict__ y0,
                             const float* __restrict__ y1,
                             const float* __restrict__ g,
                             const float* __restrict__ bta,
                             float* __restrict__ xsum,
                             fp16* __restrict__ lnout)
{
    int row = blockIdx.x;
    size_t off4 = (size_t)row * (DM / 4) + threadIdx.x;
    float4 xv = ((const float4*)x)[off4];
    float4 a = ((const float4*)y0)[off4];
    float4 b = ((const float4*)y1)[off4];
    float4 v;
    v.x = xv.x + 0.5f * (a.x + b.x);
    v.y = xv.y + 0.5f * (a.y + b.y);
    v.z = xv.z + 0.5f * (a.z + b.z);
    v.w = xv.w + 0.5f * (a.w + b.w);
    ((float4*)xsum)[off4] = v;

    float s  = v.x + v.y + v.z + v.w;
    float sq = v.x*v.x + v.y*v.y + v.z*v.z + v.w*v.w;
    #pragma unroll
    for (int o = 16; o >= 1; o >>= 1) {
        s  += __shfl_xor_sync(0xffffffffu, s, o);
        sq += __shfl_xor_sync(0xffffffffu, sq, o);
    }
    __shared__ float ss[8], ssq[8];
    int warp = threadIdx.x >> 5, lane = threadIdx.x & 31;
    if (lane == 0) { ss[warp] = s; ssq[warp] = sq; }
    __syncthreads();
    __shared__ float sh_mean, sh_inv;
    if (threadIdx.x == 0) {
        float ts = 0.f, tq = 0.f;
        #pragma unroll
        for (int w = 0; w < 8; w++) { ts += ss[w]; tq += ssq[w]; }
        float mean = ts / DM;
        float var = tq / DM - mean * mean;
        sh_mean = mean;
        sh_inv = rsqrtf(var + 1e-5f);
    }
    __syncthreads();
    float mean = sh_mean, inv = sh_inv;
    float4 gv = ((const float4*)g)[threadIdx.x];
    float4 bv = ((const float4*)bta)[threadIdx.x];
    float o0 = (v.x - mean) * inv * gv.x + bv.x;
    float o1 = (v.y - mean) * inv * gv.y + bv.y;
    float o2 = (v.z - mean) * inv * gv.z + bv.z;
    float o3 = (v.w - mean) * inv * gv.w + bv.w;
    uint2 u;
    u.x = (uint32_t)__half_as_ushort(__float2half_rn(o0)) |
          ((uint32_t)__half_as_ushort(__float2half_rn(o1)) << 16);
    u.y = (uint32_t)__half_as_ushort(__float2half_rn(o2)) |
          ((uint32_t)__half_as_ushort(__float2half_rn(o3)) << 16);
    size_t off = (size_t)row * DM + threadIdx.x * 4;
    *(uint2*)(lnout + off) = u;
}

// ---------------- host orchestration ----------------------------------------------
extern "C" void kernel_launch(void* const* d_in, const int* in_sizes, int n_in,
                              void* d_out, int out_size)
{
    (void)in_sizes; (void)n_in; (void)out_size;

    const float* x = (const float*)d_in[0];
    const float* in_w[2]   = { (const float*)d_in[1],  (const float*)d_in[10] };
    const float* conv_w[2] = { (const float*)d_in[2],  (const float*)d_in[11] };
    const float* conv_b[2] = { (const float*)d_in[3],  (const float*)d_in[12] };
    const float* x_w[2]    = { (const float*)d_in[4],  (const float*)d_in[13] };
    const float* dt_w[2]   = { (const float*)d_in[5],  (const float*)d_in[14] };
    const float* dt_b[2]   = { (const float*)d_in[6],  (const float*)d_in[15] };
    const float* A_log[2]  = { (const float*)d_in[7],  (const float*)d_in[16] };
    const float* Dp[2]     = { (const float*)d_in[8],  (const float*)d_in[17] };
    const float* out_w[2]  = { (const float*)d_in[9],  (const float*)d_in[18] };
    const float* ff_ln_g = (const float*)d_in[19];
    const float* ff_ln_b = (const float*)d_in[20];
    const float* ff_w1   = (const float*)d_in[21];
    const float* ff_b1   = (const float*)d_in[22];
    const float* ff_w2   = (const float*)d_in[23];
    const float* ff_b2   = (const float*)d_in[24];

    float *xdbl, *dtu, *ydir, *xsum;
    fp16 *xz16, *xc16, *sz16, *x16, *y16, *ln16, *f116;
    fp16 *inw16, *outw16, *w116, *w216;
    cudaGetSymbolAddress((void**)&xz16, g_xz16);
    cudaGetSymbolAddress((void**)&xc16, g_xc16);
    cudaGetSymbolAddress((void**)&xdbl, g_xdbl);
    cudaGetSymbolAddress((void**)&dtu,  g_dtu);
    cudaGetSymbolAddress((void**)&sz16, g_sz16);
    cudaGetSymbolAddress((void**)&ydir, g_ydir);
    cudaGetSymbolAddress((void**)&xsum, g_xsum);
    cudaGetSymbolAddress((void**)&x16,  g_x16);
    cudaGetSymbolAddress((void**)&y16,  g_y16);
    cudaGetSymbolAddress((void**)&ln16, g_ln16);
    cudaGetSymbolAddress((void**)&f116, g_f116);
    cudaGetSymbolAddress((void**)&inw16,  g_inw16);
    cudaGetSymbolAddress((void**)&outw16, g_outw16);
    cudaGetSymbolAddress((void**)&w116, g_w116);
    cudaGetSymbolAddress((void**)&w216, g_w216);

    cudaFuncSetAttribute(mma_gemm2, cudaFuncAttributeMaxDynamicSharedMemorySize, DSMEM2);

    const size_t szXC   = (size_t)ML * DIN;
    const size_t szYDIR = (size_t)ML * DM;
    const size_t szINW  = (size_t)2 * DIN * DM;
    const size_t szOUTW = (size_t)DM * DIN;

    dim3 blk(256);

    // idx 0-2: converts needed for in-proj
    wcvt_kernel<<<(ML*DM/4 + 255)/256, blk>>>(x, x16, ML*DM/4);
    wcvt_kernel<<<((int)szINW/4 + 255)/256, blk>>>(in_w[0], inw16,         (int)szINW/4);
    wcvt_kernel<<<((int)szINW/4 + 255)/256, blk>>>(in_w[1], inw16 + szINW, (int)szINW/4);

    // idx 3 (profiled): merged in-proj -> fp16 xz, M=4096, N=8192, K=1024
    mma_gemm2<<<dim3(64, 32, 1), blk, DSMEM2>>>(
        x16, DM, inw16, DM,
        nullptr, nullptr, nullptr, xz16,
        8192, DM, 0, 0, 0, 0);

    // remaining weight converts
    wcvt_kernel<<<(DFF*DM/4 + 255)/256, blk>>>(ff_w1, w116, DFF*DM/4);
    wcvt_kernel<<<((int)szOUTW/4 + 255)/256, blk>>>(out_w[0], outw16,          (int)szOUTW/4);
    wcvt_kernel<<<((int)szOUTW/4 + 255)/256, blk>>>(out_w[1], outw16 + szOUTW, (int)szOUTW/4);
    wcvt_kernel<<<(DM*DFF/4 + 255)/256, blk>>>(ff_w2, w216, DM*DFF/4);

    // conv (both dirs), fp16 in/out
    conv_kernel<<<(2*ML*DIN/4 + 255)/256, blk>>>(xz16, conv_w[0], conv_w[1],
                                                 conv_b[0], conv_b[1], xc16);

    // xdbl (both dirs), fp16 A, B/C interleaved
    xdbl_gemm<<<dim3(ML/32, 1, 2), dim3(128)>>>(xc16, x_w[0], x_w[1], xdbl);

    // dt (both dirs) -> (dt,u) pairs + silu(z) fp16
    dt_gemm<<<dim3(DIN/128, ML/128, 2), blk>>>(xdbl, xc16, xz16, dt_w[0], dt_w[1],
                                               dt_b[0], dt_b[1], dtu, sz16);

    // scan (both dirs): 512 blocks = 2 dir x 2 b x 128 d-groups
    scan_kernel<<<512, blk>>>(dtu, sz16, xdbl, A_log[0], A_log[1],
                              Dp[0], Dp[1], y16);

    // out-proj (both dirs via z)
    mma_gemm2<<<dim3(8, 32, 2), blk, DSMEM2>>>(
        y16, DIN, outw16, DIN,
        nullptr, nullptr, ydir, nullptr,
        DM, DIN, 0, szXC, szOUTW, szYDIR);

    // fused residual + LN
    resln_kernel<<<ML, blk>>>(x, ydir, ydir + szYDIR, ff_ln_g, ff_ln_b,
                              xsum, ln16);

    // ff1 = silu(ln @ ff_w1^T + b1) -> fp16
    mma_gemm2<<<dim3(32, 32, 1), blk, DSMEM2>>>(
        ln16, DM, w116, DM,
        ff_b1, nullptr, nullptr, f116,
        DFF, DM, 1, 0, 0, 0);

    // out = xsum + (ff1 @ ff_w2^T + b2)
    mma_gemm2<<<dim3(8, 32, 1), blk, DSMEM2>>>(
        f116, DFF, w216, DFF,
        ff_b2, xsum, (float*)d_out, nullptr,
        DM, DFF, 0, 0, 0, 0);
}